// round 6
// baseline (speedup 1.0000x reference)
#include <cuda_runtime.h>
#include <cuda_fp16.h>
#include <math.h>
#include <stdint.h>

#define BB   16
#define SS   512
#define WW   8
#define DQ   256
#define DIN  512
#define DOUT 512

// ---------------- device scratch: hi/lo fp16 plane pairs ----------------
static __device__ __align__(1024) __half g_qh[(size_t)BB*SS*WW*DQ],  g_ql[(size_t)BB*SS*WW*DQ];
static __device__ __align__(1024) __half g_dh[(size_t)BB*SS*DIN],    g_dl[(size_t)BB*SS*DIN];
static __device__ __align__(1024) __half g_wqh[DIN*DQ],   g_wql[DIN*DQ];
static __device__ __align__(1024) __half g_wkh[DIN*DIN],  g_wkl[DIN*DIN];
static __device__ __align__(1024) __half g_wvh[DOUT*DIN], g_wvl[DOUT*DIN];
static __device__ __align__(1024) __half g_wzh[DOUT*DOUT],g_wzl[DOUT*DOUT];
static __device__ __align__(1024) __half g_Qh[(size_t)BB*SS*WW*DIN], g_Ql[(size_t)BB*SS*WW*DIN];
static __device__ __align__(1024) __half g_Kh[(size_t)BB*SS*DIN],    g_Kl[(size_t)BB*SS*DIN];
static __device__ __align__(1024) __half g_Vh[(size_t)BB*DIN*SS],    g_Vl[(size_t)BB*DIN*SS]; // V^T
static __device__ __align__(1024) __half g_Ph[(size_t)BB*SS*WW*SS],  g_Pl[(size_t)BB*SS*WW*SS];
static __device__ __align__(1024) __half g_Zh[(size_t)BB*SS*WW*DOUT],g_Zl[(size_t)BB*SS*WW*DOUT];
static __device__ __align__(1024) float  g_S[(size_t)BB*SS*WW*SS];   // fp32 scores
static __device__ unsigned char g_cmask[BB*SS*WW];
static __device__ unsigned char g_words[BB*SS];
static __device__ int g_mask_mode;

// ---------------- low-level helpers ----------------
__device__ __forceinline__ uint32_t smem_u32(const void* p) {
    uint32_t a;
    asm("{ .reg .u64 t; cvta.to.shared.u64 t, %1; cvt.u32.u64 %0, t; }" : "=r"(a) : "l"(p));
    return a;
}
__device__ __forceinline__ void ldsm4(uint32_t* r, uint32_t addr) {
    asm volatile("ldmatrix.sync.aligned.m8n8.x4.shared.b16 {%0,%1,%2,%3}, [%4];\n"
        : "=r"(r[0]), "=r"(r[1]), "=r"(r[2]), "=r"(r[3]) : "r"(addr));
}
__device__ __forceinline__ void mma16816(float* c, const uint32_t* a, const uint32_t* b) {
    asm volatile(
        "mma.sync.aligned.m16n8k16.row.col.f32.f16.f16.f32 "
        "{%0,%1,%2,%3}, {%4,%5,%6,%7}, {%8,%9}, {%0,%1,%2,%3};\n"
        : "+f"(c[0]), "+f"(c[1]), "+f"(c[2]), "+f"(c[3])
        : "r"(a[0]), "r"(a[1]), "r"(a[2]), "r"(a[3]), "r"(b[0]), "r"(b[1]));
}
#define CPASYNC16(dst, src) \
    asm volatile("cp.async.cg.shared.global [%0], [%1], 16;\n" :: "r"(dst), "l"(src) : "memory")
#define CPCOMMIT() asm volatile("cp.async.commit_group;\n" ::: "memory")
#define CPWAIT2()  asm volatile("cp.async.wait_group 2;\n" ::: "memory")

__device__ __forceinline__ uint32_t pack2(__half a, __half b) {
    __half2 h = __halves2half2(a, b);
    return *(uint32_t*)&h;
}
__device__ __forceinline__ void split1(float v, __half& h, __half& l) {
    h = __float2half_rn(v);
    l = __float2half_rn(v - __half2float(h));
}

// ---------------- plane-streaming HMMA GEMM: C[M,N] = A[M,K] @ B[N,K]^T ----------------
// BM=128, BN=256, BK=32, 256 threads, 8 warps (2x4), 64x64 warp tile, 3-stage cp.async.
#define ROWB   80
#define A_PL   10240
#define B_PL   20480
#define STAGEB 61440
#define NSTAGE 3

__device__ __forceinline__ void issue_chunk(uint32_t sb,
    const __half* Ah, const __half* Al, const __half* Bh, const __half* Bl,
    long long lda, long long ldb, int k0, int tid)
{
    #pragma unroll
    for (int it = 0; it < 2; it++) {              // A: 128 rows x 4 seg16
        int s = tid + it * 256, r = s >> 2, sg = s & 3;
        long long go = (long long)r * lda + k0 + sg * 8;
        CPASYNC16(sb + r * ROWB + sg * 16, Ah + go);
        CPASYNC16(sb + A_PL + r * ROWB + sg * 16, Al + go);
    }
    uint32_t bb = sb + 2 * A_PL;
    #pragma unroll
    for (int it = 0; it < 4; it++) {              // B: 256 rows x 4 seg16
        int s = tid + it * 256, r = s >> 2, sg = s & 3;
        long long go = (long long)r * ldb + k0 + sg * 8;
        CPASYNC16(bb + r * ROWB + sg * 16, Bh + go);
        CPASYNC16(bb + B_PL + r * ROWB + sg * 16, Bl + go);
    }
}

__device__ __forceinline__ void gemm_compute(uint32_t sb, int wm, int wn, int lane, float* acc) {
    const uint32_t Ah = sb, Al = sb + A_PL, Bh = sb + 2 * A_PL, Bl = sb + 2 * A_PL + B_PL;
    const int mrow = (lane & 7) + ((lane >> 3) & 1) * 8, akcol = ((lane >> 4) & 1) * 8;
    const int nrow = (lane & 7) + ((lane >> 4) & 1) * 8, bkcol = ((lane >> 3) & 1) * 8;
    #pragma unroll
    for (int ks = 0; ks < 2; ks++) {
        const int k0 = ks * 16;
        uint32_t bfh[16], bfl[16];
        #pragma unroll
        for (int np = 0; np < 4; np++) {
            uint32_t off = (uint32_t)((wn * 64 + np * 16 + nrow) * ROWB + (k0 + bkcol) * 2);
            ldsm4(&bfh[np * 4], Bh + off);   // [N][K] k-contig == mma "col" B, non-trans
            ldsm4(&bfl[np * 4], Bl + off);
        }
        #pragma unroll
        for (int mi = 0; mi < 4; mi++) {
            uint32_t off = (uint32_t)((wm * 64 + mi * 16 + mrow) * ROWB + (k0 + akcol) * 2);
            uint32_t ah[4], al[4];
            ldsm4(ah, Ah + off);
            ldsm4(al, Al + off);
            #pragma unroll
            for (int ni = 0; ni < 8; ni++) {
                float* c = acc + (mi * 8 + ni) * 4;
                mma16816(c, ah, &bfh[ni * 2]);   // hi*hi
                mma16816(c, al, &bfh[ni * 2]);   // lo*hi
                mma16816(c, ah, &bfl[ni * 2]);   // hi*lo
            }
        }
    }
}

// OUT: 0 = fp32 C, 1 = hi/lo plane pair (Ch, Cl)
template<int OUT>
__global__ __launch_bounds__(256, 1)
void hgemm(const __half* __restrict__ Ah, const __half* __restrict__ Al,
           const __half* __restrict__ Bh, const __half* __restrict__ Bl,
           const float* __restrict__ colbias, const float* __restrict__ rowbias, float oscale,
           float* __restrict__ C, __half* __restrict__ Ch, __half* __restrict__ Cl,
           int K, long long lda, long long ldb, long long ldc,
           long long sAb, long long sBb, long long sCb)
{
    extern __shared__ char dsm[];
    const int tid = threadIdx.x, wid = tid >> 5, lane = tid & 31;
    const int wm = wid & 1, wn = wid >> 1;

    long long aoff = (long long)blockIdx.z * sAb + (long long)blockIdx.y * 128 * lda;
    long long boff = (long long)blockIdx.z * sBb + (long long)blockIdx.x * 256 * ldb;
    Ah += aoff; Al += aoff;
    Bh += boff; Bl += boff;

    float acc[128];
    #pragma unroll
    for (int i = 0; i < 128; i++) acc[i] = 0.0f;

    const uint32_t sbase = smem_u32(dsm);
    const int NC = K >> 5;

    issue_chunk(sbase, Ah, Al, Bh, Bl, lda, ldb, 0, tid);  CPCOMMIT();
    issue_chunk(sbase + STAGEB, Ah, Al, Bh, Bl, lda, ldb, 32, tid); CPCOMMIT();

    for (int i = 0; i < NC; i++) {
        if (i + 2 < NC)
            issue_chunk(sbase + ((i + 2) % NSTAGE) * STAGEB, Ah, Al, Bh, Bl,
                        lda, ldb, (i + 2) * 32, tid);
        CPCOMMIT();
        CPWAIT2();               // group i complete
        __syncthreads();
        gemm_compute(sbase + (i % NSTAGE) * STAGEB, wm, wn, lane, acc);
        __syncthreads();         // stage i%3 free for reuse at iter i+1's issue
    }

    // epilogue: frag c0:(r,c) c1:(r,c+1) c2:(r+8,c) c3:(r+8,c+1)
    const long long wr = (long long)blockIdx.y * 128 + wm * 64;
    const long long wc = (long long)blockIdx.x * 256 + wn * 64;
    #pragma unroll
    for (int mi = 0; mi < 4; mi++) {
        long long r0 = wr + mi * 16 + (lane >> 2);
        float rb0 = rowbias ? rowbias[r0]     : 0.0f;
        float rb1 = rowbias ? rowbias[r0 + 8] : 0.0f;
        #pragma unroll
        for (int ni = 0; ni < 8; ni++) {
            long long c0 = wc + ni * 8 + (lane & 3) * 2;
            float cb0 = 0.0f, cb1 = 0.0f;
            if (colbias) { float2 cb = *(const float2*)(colbias + c0); cb0 = cb.x; cb1 = cb.y; }
            const float* a = acc + (mi * 8 + ni) * 4;
            float v00 = (a[0] + cb0 + rb0) * oscale, v01 = (a[1] + cb1 + rb0) * oscale;
            float v10 = (a[2] + cb0 + rb1) * oscale, v11 = (a[3] + cb1 + rb1) * oscale;
            if (OUT == 0) {
                long long o0 = ((long long)blockIdx.z * sCb) + r0 * ldc + c0;
                *(float2*)(C + o0)            = make_float2(v00, v01);
                *(float2*)(C + o0 + 8 * ldc)  = make_float2(v10, v11);
            } else {
                long long o0 = ((long long)blockIdx.z * sCb) + r0 * ldc + c0;
                __half h00, l00, h01, l01, h10, l10, h11, l11;
                split1(v00, h00, l00); split1(v01, h01, l01);
                split1(v10, h10, l10); split1(v11, h11, l11);
                *(uint32_t*)(Ch + o0)           = pack2(h00, h01);
                *(uint32_t*)(Cl + o0)           = pack2(l00, l01);
                *(uint32_t*)(Ch + o0 + 8 * ldc) = pack2(h10, h11);
                *(uint32_t*)(Cl + o0 + 8 * ldc) = pack2(l10, l11);
            }
        }
    }
}

// ---------------- fused mask+softmax: S -> P planes + att (transposed) ----------------
__global__ __launch_bounds__(256)
void smx_att(const float* __restrict__ S, const unsigned char* __restrict__ cmask,
             const unsigned char* __restrict__ words,
             __half* __restrict__ Ph, __half* __restrict__ Pl, float* __restrict__ att)
{
    __shared__ float tile[8][521];
    __shared__ unsigned char words_s[512];
    const int b = blockIdx.y, q = blockIdx.x;
    const int tid = threadIdx.x, w = tid >> 5, lane = tid & 31;
    for (int i = tid; i < 512; i += 256) words_s[i] = words[b * 512 + i];
    __syncthreads();

    const long long base8 = ((long long)b * 512 + q) * 8;
    const float* row = S + (base8 + w) * 512;
    const bool cmb = cmask[base8 + w] != 0;

    float v[16];
    float mx = -3.0e38f;
    #pragma unroll
    for (int i = 0; i < 4; i++) {
        float4 x = *(const float4*)(row + i * 128 + lane * 4);
        float t[4] = {x.x, x.y, x.z, x.w};
        #pragma unroll
        for (int j = 0; j < 4; j++) {
            int k = i * 128 + lane * 4 + j;
            float s = t[j];                       // scale pre-folded into Qp
            s = (cmb && words_s[k]) ? s : -1e9f;
            v[i * 4 + j] = s;
            mx = fmaxf(mx, s);
        }
    }
    #pragma unroll
    for (int o = 16; o > 0; o >>= 1) mx = fmaxf(mx, __shfl_xor_sync(0xffffffffu, mx, o));
    float sum = 0.0f;
    #pragma unroll
    for (int i = 0; i < 16; i++) { float e = __expf(v[i] - mx); v[i] = e; sum += e; }
    #pragma unroll
    for (int o = 16; o > 0; o >>= 1) sum += __shfl_xor_sync(0xffffffffu, sum, o);
    const float inv = 1.0f / sum;

    #pragma unroll
    for (int i = 0; i < 4; i++) {
        float p0 = v[i*4]*inv, p1 = v[i*4+1]*inv, p2 = v[i*4+2]*inv, p3 = v[i*4+3]*inv;
        long long off = (base8 + w) * 512 + i * 128 + lane * 4;
        __half h0,l0,h1,l1,h2,l2,h3,l3;
        split1(p0,h0,l0); split1(p1,h1,l1); split1(p2,h2,l2); split1(p3,h3,l3);
        *(uint2*)(Ph + off) = make_uint2(pack2(h0,h1), pack2(h2,h3));
        *(uint2*)(Pl + off) = make_uint2(pack2(l0,l1), pack2(l2,l3));
        int k = i * 128 + lane * 4;
        tile[w][k] = p0; tile[w][k+1] = p1; tile[w][k+2] = p2; tile[w][k+3] = p3;
    }
    if (att) {
        __syncthreads();
        float* obase = att + base8 * 512;
        #pragma unroll
        for (int it = 0; it < 16; it++) {
            int idx = tid + it * 256;
            obase[idx] = tile[idx & 7][idx >> 3];
        }
    }
}

// ---------------- input conversion ----------------
__global__ void split4_kernel(const float* __restrict__ in, __half* __restrict__ h,
                              __half* __restrict__ l, long long n4) {
    long long i = (long long)blockIdx.x * blockDim.x + threadIdx.x;
    if (i >= n4) return;
    float4 v = ((const float4*)in)[i];
    __half h0,l0,h1,l1,h2,l2,h3,l3;
    split1(v.x,h0,l0); split1(v.y,h1,l1); split1(v.z,h2,l2); split1(v.w,h3,l3);
    ((uint2*)h)[i] = make_uint2(pack2(h0,h1), pack2(h2,h3));
    ((uint2*)l)[i] = make_uint2(pack2(l0,l1), pack2(l2,l3));
}

// transpose [R][C] fp32 -> [C][R] hi/lo planes
__global__ void transpose_split(const float* __restrict__ in, __half* __restrict__ oh,
                                __half* __restrict__ ol, int R, int C) {
    __shared__ float t[32][33];
    int c0 = blockIdx.x * 32, r0 = blockIdx.y * 32;
    int x = threadIdx.x, y = threadIdx.y;
    #pragma unroll
    for (int j = 0; j < 32; j += 8)
        t[y + j][x] = in[(long long)(r0 + y + j) * C + c0 + x];
    __syncthreads();
    #pragma unroll
    for (int j = 0; j < 32; j += 8) {
        float v = t[x][y + j];
        __half h, l; split1(v, h, l);
        long long o = (long long)(c0 + y + j) * R + r0 + x;
        oh[o] = h; ol[o] = l;
    }
}

// ---------------- mask handling ----------------
__global__ void detect_mask_kernel(const unsigned int* __restrict__ m) {
    if (blockIdx.x == 0 && threadIdx.x == 0) {
        bool all01 = true, allf = true;
        for (int i = 0; i < 1024; i++) {
            unsigned int v = m[i];
            if (!(v == 0u || v == 1u)) all01 = false;
            if (!(v == 0u || v == 0x3F800000u)) allf = false;
        }
        g_mask_mode = all01 ? 1 : (allf ? 0 : 2);
    }
}
__global__ void normalize_mask_kernel(const void* __restrict__ m,
                                      unsigned char* __restrict__ cmask,
                                      unsigned char* __restrict__ words) {
    int idx = blockIdx.x * blockDim.x + threadIdx.x;
    if (idx >= BB * SS) return;
    int mode = g_mask_mode;
    unsigned char any = 0;
    #pragma unroll
    for (int w = 0; w < WW; w++) {
        int e = idx * WW + w;
        unsigned char v;
        if (mode == 1)      v = (((const int*)m)[e] != 0);
        else if (mode == 0) v = (((const float*)m)[e] != 0.0f);
        else                v = (((const unsigned char*)m)[e] != 0);
        cmask[e] = v;
        any |= v;
    }
    words[idx] = any;
}

// ---------------- launch ----------------
extern "C" void kernel_launch(void* const* d_in, const int* in_sizes, int n_in,
                              void* d_out, int out_size) {
    const float* query = (const float*)d_in[0];
    const float* data  = (const float*)d_in[1];
    const void*  maskr = d_in[2];
    const float* Wq = (const float*)d_in[3];
    const float* bq = (const float*)d_in[4];
    const float* Wk = (const float*)d_in[5];
    const float* bk = (const float*)d_in[6];
    const float* Wv = (const float*)d_in[7];
    const float* bv = (const float*)d_in[8];
    const float* Wz = (const float*)d_in[9];
    const float* bz = (const float*)d_in[10];

    float* out = (float*)d_out;
    const long long zs_elems  = (long long)BB * SS * WW * DOUT;
    const long long att_elems = (long long)BB * SS * SS * WW;
    float* att = ((long long)out_size >= zs_elems + att_elems) ? out + zs_elems : nullptr;

    __half *qh,*ql,*dh,*dl,*wqh,*wql,*wkh,*wkl,*wvh,*wvl,*wzh,*wzl;
    __half *Qh,*Ql,*Kh,*Kl,*Vh,*Vl,*Ph,*Pl,*Zh,*Zl;
    float *Sp;
    unsigned char *cm, *wm;
    cudaGetSymbolAddress((void**)&qh, g_qh);  cudaGetSymbolAddress((void**)&ql, g_ql);
    cudaGetSymbolAddress((void**)&dh, g_dh);  cudaGetSymbolAddress((void**)&dl, g_dl);
    cudaGetSymbolAddress((void**)&wqh, g_wqh); cudaGetSymbolAddress((void**)&wql, g_wql);
    cudaGetSymbolAddress((void**)&wkh, g_wkh); cudaGetSymbolAddress((void**)&wkl, g_wkl);
    cudaGetSymbolAddress((void**)&wvh, g_wvh); cudaGetSymbolAddress((void**)&wvl, g_wvl);
    cudaGetSymbolAddress((void**)&wzh, g_wzh); cudaGetSymbolAddress((void**)&wzl, g_wzl);
    cudaGetSymbolAddress((void**)&Qh, g_Qh);  cudaGetSymbolAddress((void**)&Ql, g_Ql);
    cudaGetSymbolAddress((void**)&Kh, g_Kh);  cudaGetSymbolAddress((void**)&Kl, g_Kl);
    cudaGetSymbolAddress((void**)&Vh, g_Vh);  cudaGetSymbolAddress((void**)&Vl, g_Vl);
    cudaGetSymbolAddress((void**)&Ph, g_Ph);  cudaGetSymbolAddress((void**)&Pl, g_Pl);
    cudaGetSymbolAddress((void**)&Zh, g_Zh);  cudaGetSymbolAddress((void**)&Zl, g_Zl);
    cudaGetSymbolAddress((void**)&Sp, g_S);
    cudaGetSymbolAddress((void**)&cm, g_cmask);
    cudaGetSymbolAddress((void**)&wm, g_words);

    const int SMEM = NSTAGE * STAGEB;   // 184320
    cudaFuncSetAttribute(hgemm<0>, cudaFuncAttributeMaxDynamicSharedMemorySize, SMEM);
    cudaFuncSetAttribute(hgemm<1>, cudaFuncAttributeMaxDynamicSharedMemorySize, SMEM);

    detect_mask_kernel<<<1, 1>>>((const unsigned int*)maskr);
    normalize_mask_kernel<<<(BB * SS + 255) / 256, 256>>>(maskr, cm, wm);

    // input splits
    {
        long long nq4 = (long long)BB * SS * WW * DQ / 4;
        split4_kernel<<<(unsigned)((nq4 + 255) / 256), 256>>>(query, qh, ql, nq4);
        long long nd4 = (long long)BB * SS * DIN / 4;
        split4_kernel<<<(unsigned)((nd4 + 255) / 256), 256>>>(data, dh, dl, nd4);
    }
    transpose_split<<<dim3(DIN/32, DQ/32),   dim3(32,8)>>>(Wq, wqh, wql, DQ,  DIN);
    transpose_split<<<dim3(DIN/32, DIN/32),  dim3(32,8)>>>(Wk, wkh, wkl, DIN, DIN);
    transpose_split<<<dim3(DOUT/32, DIN/32), dim3(32,8)>>>(Wv, wvh, wvl, DIN, DOUT);
    transpose_split<<<dim3(DOUT/32, DOUT/32),dim3(32,8)>>>(Wz, wzh, wzl, DOUT, DOUT);

    const float SCALE = 0.04419417382415922f;  // 1/sqrt(512), folded into Qp

    // Qproj -> Qp planes (scaled): [65536,512]
    hgemm<1><<<dim3(2, 512, 1), 256, SMEM>>>(qh, ql, wqh, wql, bq, nullptr, SCALE,
        nullptr, Qh, Ql, DQ, DQ, DQ, DIN, 0, 0, 0);
    // Kproj -> Kp planes: [8192,512]
    hgemm<1><<<dim3(2, 64, 1), 256, SMEM>>>(dh, dl, wkh, wkl, bk, nullptr, 1.0f,
        nullptr, Kh, Kl, DIN, DIN, DIN, DIN, 0, 0, 0);
    // VT[b] planes: [512z,512s] = wv[z,:] . data_b[s,:] + bv[z]
    hgemm<1><<<dim3(2, 4, BB), 256, SMEM>>>(wvh, wvl, dh, dl, nullptr, bv, 1.0f,
        nullptr, Vh, Vl, DIN, DIN, DIN, SS, 0, (long long)SS * DIN, (long long)DIN * SS);
    // scores[b] fp32: [4096,512] = Qp_b @ Kp_b^T
    hgemm<0><<<dim3(2, 32, BB), 256, SMEM>>>(Qh, Ql, Kh, Kl, nullptr, nullptr, 1.0f,
        Sp, nullptr, nullptr, DIN, DIN, DIN, SS,
        (long long)SS * WW * DIN, (long long)SS * DIN, (long long)SS * WW * SS);
    // softmax + P planes + att
    smx_att<<<dim3(SS, BB), 256>>>(Sp, cm, wm, Ph, Pl, att);
    // Z1[b] planes = P_b @ VT_b^T
    hgemm<1><<<dim3(2, 32, BB), 256, SMEM>>>(Ph, Pl, Vh, Vl, nullptr, nullptr, 1.0f,
        nullptr, Zh, Zl, SS, SS, SS, DOUT,
        (long long)SS * WW * SS, (long long)DIN * SS, (long long)SS * WW * DOUT);
    // zs = Z1 @ Wz^T + bz -> d_out fp32
    hgemm<0><<<dim3(2, 512, 1), 256, SMEM>>>(Zh, Zl, wzh, wzl, bz, nullptr, 1.0f,
        out, nullptr, nullptr, DOUT, DOUT, DOUT, DOUT, 0, 0, 0);
}

// round 7
// speedup vs baseline: 1.0587x; 1.0587x over previous
#include <cuda_runtime.h>
#include <cuda_fp16.h>
#include <math.h>
#include <stdint.h>

#define BB   16
#define SS   512
#define WW   8
#define DQ   256
#define DIN  512
#define DOUT 512

// ---------------- device scratch: hi/lo fp16 plane pairs ----------------
static __device__ __align__(1024) __half g_qh[(size_t)BB*SS*WW*DQ],  g_ql[(size_t)BB*SS*WW*DQ];
static __device__ __align__(1024) __half g_dh[(size_t)BB*SS*DIN],    g_dl[(size_t)BB*SS*DIN];
static __device__ __align__(1024) __half g_wqh[DIN*DQ],   g_wql[DIN*DQ];
static __device__ __align__(1024) __half g_wkh[DIN*DIN],  g_wkl[DIN*DIN];
static __device__ __align__(1024) __half g_wvh[DOUT*DIN], g_wvl[DOUT*DIN];
static __device__ __align__(1024) __half g_wzh[DOUT*DOUT],g_wzl[DOUT*DOUT];
static __device__ __align__(1024) __half g_Qh[(size_t)BB*SS*WW*DIN], g_Ql[(size_t)BB*SS*WW*DIN];
static __device__ __align__(1024) __half g_Kh[(size_t)BB*SS*DIN],    g_Kl[(size_t)BB*SS*DIN];
static __device__ __align__(1024) __half g_Vh[(size_t)BB*DIN*SS],    g_Vl[(size_t)BB*DIN*SS]; // V^T
static __device__ __align__(1024) __half g_Ph[(size_t)BB*SS*WW*SS],  g_Pl[(size_t)BB*SS*WW*SS];
static __device__ __align__(1024) __half g_Zh[(size_t)BB*SS*WW*DOUT],g_Zl[(size_t)BB*SS*WW*DOUT];
static __device__ __align__(1024) float  g_S[(size_t)BB*SS*WW*SS];   // fp32 scores
static __device__ unsigned char g_cmask[BB*SS*WW];
static __device__ unsigned char g_words[BB*SS];
static __device__ int g_mask_mode;

// ---------------- low-level helpers ----------------
__device__ __forceinline__ uint32_t smem_u32(const void* p) {
    uint32_t a;
    asm("{ .reg .u64 t; cvta.to.shared.u64 t, %1; cvt.u32.u64 %0, t; }" : "=r"(a) : "l"(p));
    return a;
}
__device__ __forceinline__ void ldsm4(uint32_t* r, uint32_t addr) {
    asm volatile("ldmatrix.sync.aligned.m8n8.x4.shared.b16 {%0,%1,%2,%3}, [%4];\n"
        : "=r"(r[0]), "=r"(r[1]), "=r"(r[2]), "=r"(r[3]) : "r"(addr));
}
__device__ __forceinline__ void mma16816(float* c, const uint32_t* a, const uint32_t* b) {
    asm volatile(
        "mma.sync.aligned.m16n8k16.row.col.f32.f16.f16.f32 "
        "{%0,%1,%2,%3}, {%4,%5,%6,%7}, {%8,%9}, {%0,%1,%2,%3};\n"
        : "+f"(c[0]), "+f"(c[1]), "+f"(c[2]), "+f"(c[3])
        : "r"(a[0]), "r"(a[1]), "r"(a[2]), "r"(a[3]), "r"(b[0]), "r"(b[1]));
}
#define CPASYNC16(dst, src) \
    asm volatile("cp.async.cg.shared.global [%0], [%1], 16;\n" :: "r"(dst), "l"(src) : "memory")
#define CPCOMMIT() asm volatile("cp.async.commit_group;\n" ::: "memory")
#define CPWAIT1()  asm volatile("cp.async.wait_group 1;\n" ::: "memory")

__device__ __forceinline__ uint32_t pack2(__half a, __half b) {
    __half2 h = __halves2half2(a, b);
    return *(uint32_t*)&h;
}
__device__ __forceinline__ void split1(float v, __half& h, __half& l) {
    h = __float2half_rn(v);
    l = __float2half_rn(v - __half2float(h));
}

// ---------------- plane-streaming HMMA GEMM: C[M,N] = A[M,K] @ B[N,K]^T ----------------
// BM=128, BN=128, BK=32, 256 threads, 8 warps (4x2), warp tile 32x64, 2-stage, 2 CTAs/SM.
#define ROWB   80
#define PLANE  10240           /* 128 rows x 80B */
#define STAGEB 40960           /* Ah, Al, Bh, Bl planes */
#define NSTAGE 2

__device__ __forceinline__ void issue_chunk(uint32_t sb,
    const __half* Ah, const __half* Al, const __half* Bh, const __half* Bl,
    long long lda, long long ldb, int k0, int tid)
{
    #pragma unroll
    for (int it = 0; it < 2; it++) {              // 128 rows x 4 lines per plane
        int s = tid + it * 256, r = s >> 2, sg = s & 3;
        long long ga = (long long)r * lda + k0 + sg * 8;
        CPASYNC16(sb + r * ROWB + sg * 16,          Ah + ga);
        CPASYNC16(sb + PLANE + r * ROWB + sg * 16,  Al + ga);
        long long gb = (long long)r * ldb + k0 + sg * 8;
        CPASYNC16(sb + 2*PLANE + r * ROWB + sg * 16, Bh + gb);
        CPASYNC16(sb + 3*PLANE + r * ROWB + sg * 16, Bl + gb);
    }
}

__device__ __forceinline__ void gemm_compute(uint32_t sb, int wm, int wn, int lane, float* acc) {
    const uint32_t Ah = sb, Al = sb + PLANE, Bh = sb + 2*PLANE, Bl = sb + 3*PLANE;
    const int mrow = (lane & 7) + ((lane >> 3) & 1) * 8, akcol = ((lane >> 4) & 1) * 8;
    const int nrow = (lane & 7) + ((lane >> 4) & 1) * 8, bkcol = ((lane >> 3) & 1) * 8;
    #pragma unroll
    for (int ks = 0; ks < 2; ks++) {
        const int k0 = ks * 16;
        uint32_t bfh[16], bfl[16];
        #pragma unroll
        for (int np = 0; np < 4; np++) {
            uint32_t off = (uint32_t)((wn * 64 + np * 16 + nrow) * ROWB + (k0 + bkcol) * 2);
            ldsm4(&bfh[np * 4], Bh + off);   // [N][K] k-contig == mma "col" B, non-trans
            ldsm4(&bfl[np * 4], Bl + off);
        }
        #pragma unroll
        for (int mi = 0; mi < 2; mi++) {
            uint32_t off = (uint32_t)((wm * 32 + mi * 16 + mrow) * ROWB + (k0 + akcol) * 2);
            uint32_t ah[4], al[4];
            ldsm4(ah, Ah + off);
            ldsm4(al, Al + off);
            #pragma unroll
            for (int ni = 0; ni < 8; ni++) {
                float* c = acc + (mi * 8 + ni) * 4;
                mma16816(c, ah, &bfh[ni * 2]);   // hi*hi
                mma16816(c, al, &bfh[ni * 2]);   // lo*hi
                mma16816(c, ah, &bfl[ni * 2]);   // hi*lo
            }
        }
    }
}

// OUT: 0 = fp32 C, 1 = hi/lo plane pair (Ch, Cl)
template<int OUT>
__global__ __launch_bounds__(256, 2)
void hgemm(const __half* __restrict__ Ah, const __half* __restrict__ Al,
           const __half* __restrict__ Bh, const __half* __restrict__ Bl,
           const float* __restrict__ colbias, const float* __restrict__ rowbias, float oscale,
           float* __restrict__ C, __half* __restrict__ Ch, __half* __restrict__ Cl,
           int K, long long lda, long long ldb, long long ldc,
           long long sAb, long long sBb, long long sCb)
{
    extern __shared__ char dsm[];
    const int tid = threadIdx.x, wid = tid >> 5, lane = tid & 31;
    const int wm = wid & 3, wn = wid >> 2;   // 4x2 warp grid, tile 32x64

    long long aoff = (long long)blockIdx.z * sAb + (long long)blockIdx.y * 128 * lda;
    long long boff = (long long)blockIdx.z * sBb + (long long)blockIdx.x * 128 * ldb;
    Ah += aoff; Al += aoff;
    Bh += boff; Bl += boff;

    float acc[64];
    #pragma unroll
    for (int i = 0; i < 64; i++) acc[i] = 0.0f;

    const uint32_t sbase = smem_u32(dsm);
    const int NC = K >> 5;

    issue_chunk(sbase, Ah, Al, Bh, Bl, lda, ldb, 0, tid);
    CPCOMMIT();

    for (int i = 0; i < NC; i++) {
        if (i + 1 < NC)
            issue_chunk(sbase + ((i + 1) & 1) * STAGEB, Ah, Al, Bh, Bl, lda, ldb, (i + 1) * 32, tid);
        CPCOMMIT();
        CPWAIT1();               // chunk i resident
        __syncthreads();
        gemm_compute(sbase + (i & 1) * STAGEB, wm, wn, lane, acc);
        __syncthreads();         // stage (i&1) free before iter i+1 issues into it
    }

    // epilogue: frag c0:(r,c) c1:(r,c+1) c2:(r+8,c) c3:(r+8,c+1)
    const long long wr = (long long)blockIdx.y * 128 + wm * 32;
    const long long wc = (long long)blockIdx.x * 128 + wn * 64;
    #pragma unroll
    for (int mi = 0; mi < 2; mi++) {
        long long r0 = wr + mi * 16 + (lane >> 2);
        float rb0 = rowbias ? rowbias[r0]     : 0.0f;
        float rb1 = rowbias ? rowbias[r0 + 8] : 0.0f;
        #pragma unroll
        for (int ni = 0; ni < 8; ni++) {
            long long c0 = wc + ni * 8 + (lane & 3) * 2;
            float cb0 = 0.0f, cb1 = 0.0f;
            if (colbias) { float2 cb = *(const float2*)(colbias + c0); cb0 = cb.x; cb1 = cb.y; }
            const float* a = acc + (mi * 8 + ni) * 4;
            float v00 = (a[0] + cb0 + rb0) * oscale, v01 = (a[1] + cb1 + rb0) * oscale;
            float v10 = (a[2] + cb0 + rb1) * oscale, v11 = (a[3] + cb1 + rb1) * oscale;
            long long o0 = ((long long)blockIdx.z * sCb) + r0 * ldc + c0;
            if (OUT == 0) {
                *(float2*)(C + o0)           = make_float2(v00, v01);
                *(float2*)(C + o0 + 8 * ldc) = make_float2(v10, v11);
            } else {
                __half h00, l00, h01, l01, h10, l10, h11, l11;
                split1(v00, h00, l00); split1(v01, h01, l01);
                split1(v10, h10, l10); split1(v11, h11, l11);
                *(uint32_t*)(Ch + o0)           = pack2(h00, h01);
                *(uint32_t*)(Cl + o0)           = pack2(l00, l01);
                *(uint32_t*)(Ch + o0 + 8 * ldc) = pack2(h10, h11);
                *(uint32_t*)(Cl + o0 + 8 * ldc) = pack2(l10, l11);
            }
        }
    }
}

// ---------------- fused mask+softmax: S -> P planes + att (transposed) ----------------
__global__ __launch_bounds__(256)
void smx_att(const float* __restrict__ S, const unsigned char* __restrict__ cmask,
             const unsigned char* __restrict__ words,
             __half* __restrict__ Ph, __half* __restrict__ Pl, float* __restrict__ att)
{
    __shared__ float tile[8][521];
    __shared__ unsigned char words_s[512];
    const int b = blockIdx.y, q = blockIdx.x;
    const int tid = threadIdx.x, w = tid >> 5, lane = tid & 31;
    for (int i = tid; i < 512; i += 256) words_s[i] = words[b * 512 + i];
    __syncthreads();

    const long long base8 = ((long long)b * 512 + q) * 8;
    const float* row = S + (base8 + w) * 512;
    const bool cmb = cmask[base8 + w] != 0;

    float v[16];
    float mx = -3.0e38f;
    #pragma unroll
    for (int i = 0; i < 4; i++) {
        float4 x = *(const float4*)(row + i * 128 + lane * 4);
        float t[4] = {x.x, x.y, x.z, x.w};
        #pragma unroll
        for (int j = 0; j < 4; j++) {
            int k = i * 128 + lane * 4 + j;
            float s = t[j];                       // 1/sqrt(512) pre-folded into Qp
            s = (cmb && words_s[k]) ? s : -1e9f;
            v[i * 4 + j] = s;
            mx = fmaxf(mx, s);
        }
    }
    #pragma unroll
    for (int o = 16; o > 0; o >>= 1) mx = fmaxf(mx, __shfl_xor_sync(0xffffffffu, mx, o));
    float sum = 0.0f;
    #pragma unroll
    for (int i = 0; i < 16; i++) { float e = __expf(v[i] - mx); v[i] = e; sum += e; }
    #pragma unroll
    for (int o = 16; o > 0; o >>= 1) sum += __shfl_xor_sync(0xffffffffu, sum, o);
    const float inv = 1.0f / sum;

    #pragma unroll
    for (int i = 0; i < 4; i++) {
        float p0 = v[i*4]*inv, p1 = v[i*4+1]*inv, p2 = v[i*4+2]*inv, p3 = v[i*4+3]*inv;
        long long off = (base8 + w) * 512 + i * 128 + lane * 4;
        __half h0,l0,h1,l1,h2,l2,h3,l3;
        split1(p0,h0,l0); split1(p1,h1,l1); split1(p2,h2,l2); split1(p3,h3,l3);
        *(uint2*)(Ph + off) = make_uint2(pack2(h0,h1), pack2(h2,h3));
        *(uint2*)(Pl + off) = make_uint2(pack2(l0,l1), pack2(l2,l3));
        int k = i * 128 + lane * 4;
        tile[w][k] = p0; tile[w][k+1] = p1; tile[w][k+2] = p2; tile[w][k+3] = p3;
    }
    if (att) {
        __syncthreads();
        float* obase = att + base8 * 512;
        #pragma unroll
        for (int it = 0; it < 16; it++) {
            int idx = tid + it * 256;
            obase[idx] = tile[idx & 7][idx >> 3];
        }
    }
}

// ---------------- input conversion ----------------
__global__ void split4_kernel(const float* __restrict__ in, __half* __restrict__ h,
                              __half* __restrict__ l, long long n4) {
    long long i = (long long)blockIdx.x * blockDim.x + threadIdx.x;
    if (i >= n4) return;
    float4 v = ((const float4*)in)[i];
    __half h0,l0,h1,l1,h2,l2,h3,l3;
    split1(v.x,h0,l0); split1(v.y,h1,l1); split1(v.z,h2,l2); split1(v.w,h3,l3);
    ((uint2*)h)[i] = make_uint2(pack2(h0,h1), pack2(h2,h3));
    ((uint2*)l)[i] = make_uint2(pack2(l0,l1), pack2(l2,l3));
}

// transpose [R][C] fp32 -> [C][R] hi/lo planes
__global__ void transpose_split(const float* __restrict__ in, __half* __restrict__ oh,
                                __half* __restrict__ ol, int R, int C) {
    __shared__ float t[32][33];
    int c0 = blockIdx.x * 32, r0 = blockIdx.y * 32;
    int x = threadIdx.x, y = threadIdx.y;
    #pragma unroll
    for (int j = 0; j < 32; j += 8)
        t[y + j][x] = in[(long long)(r0 + y + j) * C + c0 + x];
    __syncthreads();
    #pragma unroll
    for (int j = 0; j < 32; j += 8) {
        float v = t[x][y + j];
        __half h, l; split1(v, h, l);
        long long o = (long long)(c0 + y + j) * R + r0 + x;
        oh[o] = h; ol[o] = l;
    }
}

// ---------------- mask handling ----------------
__global__ void detect_mask_kernel(const unsigned int* __restrict__ m) {
    if (blockIdx.x == 0 && threadIdx.x == 0) {
        bool all01 = true, allf = true;
        for (int i = 0; i < 1024; i++) {
            unsigned int v = m[i];
            if (!(v == 0u || v == 1u)) all01 = false;
            if (!(v == 0u || v == 0x3F800000u)) allf = false;
        }
        g_mask_mode = all01 ? 1 : (allf ? 0 : 2);
    }
}
__global__ void normalize_mask_kernel(const void* __restrict__ m,
                                      unsigned char* __restrict__ cmask,
                                      unsigned char* __restrict__ words) {
    int idx = blockIdx.x * blockDim.x + threadIdx.x;
    if (idx >= BB * SS) return;
    int mode = g_mask_mode;
    unsigned char any = 0;
    #pragma unroll
    for (int w = 0; w < WW; w++) {
        int e = idx * WW + w;
        unsigned char v;
        if (mode == 1)      v = (((const int*)m)[e] != 0);
        else if (mode == 0) v = (((const float*)m)[e] != 0.0f);
        else                v = (((const unsigned char*)m)[e] != 0);
        cmask[e] = v;
        any |= v;
    }
    words[idx] = any;
}

// ---------------- launch ----------------
extern "C" void kernel_launch(void* const* d_in, const int* in_sizes, int n_in,
                              void* d_out, int out_size) {
    const float* query = (const float*)d_in[0];
    const float* data  = (const float*)d_in[1];
    const void*  maskr = d_in[2];
    const float* Wq = (const float*)d_in[3];
    const float* bq = (const float*)d_in[4];
    const float* Wk = (const float*)d_in[5];
    const float* bk = (const float*)d_in[6];
    const float* Wv = (const float*)d_in[7];
    const float* bv = (const float*)d_in[8];
    const float* Wz = (const float*)d_in[9];
    const float* bz = (const float*)d_in[10];

    float* out = (float*)d_out;
    const long long zs_elems  = (long long)BB * SS * WW * DOUT;
    const long long att_elems = (long long)BB * SS * SS * WW;
    float* att = ((long long)out_size >= zs_elems + att_elems) ? out + zs_elems : nullptr;

    __half *qh,*ql,*dh,*dl,*wqh,*wql,*wkh,*wkl,*wvh,*wvl,*wzh,*wzl;
    __half *Qh,*Ql,*Kh,*Kl,*Vh,*Vl,*Ph,*Pl,*Zh,*Zl;
    float *Sp;
    unsigned char *cm, *wm;
    cudaGetSymbolAddress((void**)&qh, g_qh);  cudaGetSymbolAddress((void**)&ql, g_ql);
    cudaGetSymbolAddress((void**)&dh, g_dh);  cudaGetSymbolAddress((void**)&dl, g_dl);
    cudaGetSymbolAddress((void**)&wqh, g_wqh); cudaGetSymbolAddress((void**)&wql, g_wql);
    cudaGetSymbolAddress((void**)&wkh, g_wkh); cudaGetSymbolAddress((void**)&wkl, g_wkl);
    cudaGetSymbolAddress((void**)&wvh, g_wvh); cudaGetSymbolAddress((void**)&wvl, g_wvl);
    cudaGetSymbolAddress((void**)&wzh, g_wzh); cudaGetSymbolAddress((void**)&wzl, g_wzl);
    cudaGetSymbolAddress((void**)&Qh, g_Qh);  cudaGetSymbolAddress((void**)&Ql, g_Ql);
    cudaGetSymbolAddress((void**)&Kh, g_Kh);  cudaGetSymbolAddress((void**)&Kl, g_Kl);
    cudaGetSymbolAddress((void**)&Vh, g_Vh);  cudaGetSymbolAddress((void**)&Vl, g_Vl);
    cudaGetSymbolAddress((void**)&Ph, g_Ph);  cudaGetSymbolAddress((void**)&Pl, g_Pl);
    cudaGetSymbolAddress((void**)&Zh, g_Zh);  cudaGetSymbolAddress((void**)&Zl, g_Zl);
    cudaGetSymbolAddress((void**)&Sp, g_S);
    cudaGetSymbolAddress((void**)&cm, g_cmask);
    cudaGetSymbolAddress((void**)&wm, g_words);

    const int SMEM = NSTAGE * STAGEB;   // 81920 -> 2 CTAs/SM
    cudaFuncSetAttribute(hgemm<0>, cudaFuncAttributeMaxDynamicSharedMemorySize, SMEM);
    cudaFuncSetAttribute(hgemm<1>, cudaFuncAttributeMaxDynamicSharedMemorySize, SMEM);

    detect_mask_kernel<<<1, 1>>>((const unsigned int*)maskr);
    normalize_mask_kernel<<<(BB * SS + 255) / 256, 256>>>(maskr, cm, wm);

    {
        long long nq4 = (long long)BB * SS * WW * DQ / 4;
        split4_kernel<<<(unsigned)((nq4 + 255) / 256), 256>>>(query, qh, ql, nq4);
        long long nd4 = (long long)BB * SS * DIN / 4;
        split4_kernel<<<(unsigned)((nd4 + 255) / 256), 256>>>(data, dh, dl, nd4);
    }
    transpose_split<<<dim3(DIN/32, DQ/32),   dim3(32,8)>>>(Wq, wqh, wql, DQ,  DIN);
    transpose_split<<<dim3(DIN/32, DIN/32),  dim3(32,8)>>>(Wk, wkh, wkl, DIN, DIN);
    transpose_split<<<dim3(DOUT/32, DIN/32), dim3(32,8)>>>(Wv, wvh, wvl, DIN, DOUT);
    transpose_split<<<dim3(DOUT/32, DOUT/32),dim3(32,8)>>>(Wz, wzh, wzl, DOUT, DOUT);

    const float SCALE = 0.04419417382415922f;  // 1/sqrt(512), folded into Qp

    // Qproj -> Qp planes (scaled): [65536,512]
    hgemm<1><<<dim3(4, 512, 1), 256, SMEM>>>(qh, ql, wqh, wql, bq, nullptr, SCALE,
        nullptr, Qh, Ql, DQ, DQ, DQ, DIN, 0, 0, 0);
    // Kproj -> Kp planes: [8192,512]
    hgemm<1><<<dim3(4, 64, 1), 256, SMEM>>>(dh, dl, wkh, wkl, bk, nullptr, 1.0f,
        nullptr, Kh, Kl, DIN, DIN, DIN, DIN, 0, 0, 0);
    // VT[b] planes: [512z,512s] = wv[z,:] . data_b[s,:] + bv[z]
    hgemm<1><<<dim3(4, 4, BB), 256, SMEM>>>(wvh, wvl, dh, dl, nullptr, bv, 1.0f,
        nullptr, Vh, Vl, DIN, DIN, DIN, SS, 0, (long long)SS * DIN, (long long)DIN * SS);
    // scores[b] fp32: [4096,512] = Qp_b @ Kp_b^T
    hgemm<0><<<dim3(4, 32, BB), 256, SMEM>>>(Qh, Ql, Kh, Kl, nullptr, nullptr, 1.0f,
        Sp, nullptr, nullptr, DIN, DIN, DIN, SS,
        (long long)SS * WW * DIN, (long long)SS * DIN, (long long)SS * WW * SS);
    // softmax + P planes + att
    smx_att<<<dim3(SS, BB), 256>>>(Sp, cm, wm, Ph, Pl, att);
    // Z1[b] planes = P_b @ VT_b^T
    hgemm<1><<<dim3(4, 32, BB), 256, SMEM>>>(Ph, Pl, Vh, Vl, nullptr, nullptr, 1.0f,
        nullptr, Zh, Zl, SS, SS, SS, DOUT,
        (long long)SS * WW * SS, (long long)DIN * SS, (long long)SS * WW * DOUT);
    // zs = Z1 @ Wz^T + bz -> d_out fp32
    hgemm<0><<<dim3(4, 512, 1), 256, SMEM>>>(Zh, Zl, wzh, wzl, bz, nullptr, 1.0f,
        out, nullptr, nullptr, DOUT, DOUT, DOUT, DOUT, 0, 0, 0);
}

// round 8
// speedup vs baseline: 1.0689x; 1.0096x over previous
#include <cuda_runtime.h>
#include <cuda_fp16.h>
#include <math.h>
#include <stdint.h>

#define BB   16
#define SS   512
#define WW   8
#define DQ   256
#define DIN  512
#define DOUT 512

// ---------------- device scratch: hi/lo fp16 plane pairs ----------------
static __device__ __align__(1024) __half g_qh[(size_t)BB*SS*WW*DQ],  g_ql[(size_t)BB*SS*WW*DQ];
static __device__ __align__(1024) __half g_dh[(size_t)BB*SS*DIN],    g_dl[(size_t)BB*SS*DIN];
static __device__ __align__(1024) __half g_wqh[DIN*DQ],   g_wql[DIN*DQ];
static __device__ __align__(1024) __half g_wkh[DIN*DIN],  g_wkl[DIN*DIN];
static __device__ __align__(1024) __half g_wvh[DOUT*DIN], g_wvl[DOUT*DIN];
static __device__ __align__(1024) __half g_wzh[DOUT*DOUT],g_wzl[DOUT*DOUT];
static __device__ __align__(1024) __half g_Qh[(size_t)BB*SS*WW*DIN], g_Ql[(size_t)BB*SS*WW*DIN];
static __device__ __align__(1024) __half g_Kh[(size_t)BB*SS*DIN],    g_Kl[(size_t)BB*SS*DIN];
static __device__ __align__(1024) __half g_Vh[(size_t)BB*DIN*SS],    g_Vl[(size_t)BB*DIN*SS]; // V^T
static __device__ __align__(1024) __half g_Ph[(size_t)BB*SS*WW*SS],  g_Pl[(size_t)BB*SS*WW*SS];
static __device__ __align__(1024) __half g_Zh[(size_t)BB*SS*WW*DOUT],g_Zl[(size_t)BB*SS*WW*DOUT];
static __device__ __align__(1024) float  g_S[(size_t)BB*SS*WW*SS];   // fp32 scores
static __device__ unsigned char g_cmask[BB*SS*WW];
static __device__ unsigned char g_words[BB*SS];
static __device__ int g_mask_mode;

// ---------------- low-level helpers ----------------
__device__ __forceinline__ uint32_t smem_u32(const void* p) {
    uint32_t a;
    asm("{ .reg .u64 t; cvta.to.shared.u64 t, %1; cvt.u32.u64 %0, t; }" : "=r"(a) : "l"(p));
    return a;
}
__device__ __forceinline__ void ldsm4(uint32_t* r, uint32_t addr) {
    asm volatile("ldmatrix.sync.aligned.m8n8.x4.shared.b16 {%0,%1,%2,%3}, [%4];\n"
        : "=r"(r[0]), "=r"(r[1]), "=r"(r[2]), "=r"(r[3]) : "r"(addr));
}
__device__ __forceinline__ void mma16816(float* c, const uint32_t* a, const uint32_t* b) {
    asm volatile(
        "mma.sync.aligned.m16n8k16.row.col.f32.f16.f16.f32 "
        "{%0,%1,%2,%3}, {%4,%5,%6,%7}, {%8,%9}, {%0,%1,%2,%3};\n"
        : "+f"(c[0]), "+f"(c[1]), "+f"(c[2]), "+f"(c[3])
        : "r"(a[0]), "r"(a[1]), "r"(a[2]), "r"(a[3]), "r"(b[0]), "r"(b[1]));
}
#define CPASYNC16(dst, src) \
    asm volatile("cp.async.cg.shared.global [%0], [%1], 16;\n" :: "r"(dst), "l"(src) : "memory")
#define CPCOMMIT() asm volatile("cp.async.commit_group;\n" ::: "memory")
#define CPWAIT0()  asm volatile("cp.async.wait_group 0;\n" ::: "memory")

__device__ __forceinline__ uint32_t pack2(__half a, __half b) {
    __half2 h = __halves2half2(a, b);
    return *(uint32_t*)&h;
}
__device__ __forceinline__ void split1(float v, __half& h, __half& l) {
    h = __float2half_rn(v);
    l = __float2half_rn(v - __half2float(h));
}

// ---------------- plane-streaming HMMA GEMM: C[M,N] = A[M,K] @ B[N,K]^T ----------------
// BM=128, BN=128, BK=32, 256 threads, 8 warps (4x2), warp tile 32x64, 2-stage, 2 CTAs/SM.
// Single __syncthreads per chunk: wait(i) -> sync -> issue(i+1) -> compute(i).
#define ROWB   80
#define PLANE  10240           /* 128 rows x 80B */
#define STAGEB 40960           /* Ah, Al, Bh, Bl planes */
#define NSTAGE 2

__device__ __forceinline__ void issue_chunk(uint32_t sb,
    const __half* Ah, const __half* Al, const __half* Bh, const __half* Bl,
    long long lda, long long ldb, int k0, int tid)
{
    #pragma unroll
    for (int it = 0; it < 2; it++) {              // 128 rows x 4 lines per plane
        int s = tid + it * 256, r = s >> 2, sg = s & 3;
        long long ga = (long long)r * lda + k0 + sg * 8;
        CPASYNC16(sb + r * ROWB + sg * 16,          Ah + ga);
        CPASYNC16(sb + PLANE + r * ROWB + sg * 16,  Al + ga);
        long long gb = (long long)r * ldb + k0 + sg * 8;
        CPASYNC16(sb + 2*PLANE + r * ROWB + sg * 16, Bh + gb);
        CPASYNC16(sb + 3*PLANE + r * ROWB + sg * 16, Bl + gb);
    }
}

__device__ __forceinline__ void gemm_compute(uint32_t sb, int wm, int wn, int lane, float* acc) {
    const uint32_t Ah = sb, Al = sb + PLANE, Bh = sb + 2*PLANE, Bl = sb + 3*PLANE;
    const int mrow = (lane & 7) + ((lane >> 3) & 1) * 8, akcol = ((lane >> 4) & 1) * 8;
    const int nrow = (lane & 7) + ((lane >> 4) & 1) * 8, bkcol = ((lane >> 3) & 1) * 8;
    #pragma unroll
    for (int ks = 0; ks < 2; ks++) {
        const int k0 = ks * 16;
        uint32_t bfh[16], bfl[16];
        #pragma unroll
        for (int np = 0; np < 4; np++) {
            uint32_t off = (uint32_t)((wn * 64 + np * 16 + nrow) * ROWB + (k0 + bkcol) * 2);
            ldsm4(&bfh[np * 4], Bh + off);   // [N][K] k-contig == mma "col" B, non-trans
            ldsm4(&bfl[np * 4], Bl + off);
        }
        #pragma unroll
        for (int mi = 0; mi < 2; mi++) {
            uint32_t off = (uint32_t)((wm * 32 + mi * 16 + mrow) * ROWB + (k0 + akcol) * 2);
            uint32_t ah[4], al[4];
            ldsm4(ah, Ah + off);
            ldsm4(al, Al + off);
            #pragma unroll
            for (int ni = 0; ni < 8; ni++) {
                float* c = acc + (mi * 8 + ni) * 4;
                mma16816(c, ah, &bfh[ni * 2]);   // hi*hi
                mma16816(c, al, &bfh[ni * 2]);   // lo*hi
                mma16816(c, ah, &bfl[ni * 2]);   // hi*lo
            }
        }
    }
}

// OUT: 0 = fp32 C, 1 = hi/lo plane pair (Ch, Cl)
template<int OUT>
__global__ __launch_bounds__(256, 2)
void hgemm(const __half* __restrict__ Ah, const __half* __restrict__ Al,
           const __half* __restrict__ Bh, const __half* __restrict__ Bl,
           const float* __restrict__ colbias, const float* __restrict__ rowbias, float oscale,
           float* __restrict__ C, __half* __restrict__ Ch, __half* __restrict__ Cl,
           int K, long long lda, long long ldb, long long ldc,
           long long sAb, long long sBb, long long sCb)
{
    extern __shared__ char dsm[];
    const int tid = threadIdx.x, wid = tid >> 5, lane = tid & 31;
    const int wm = wid & 3, wn = wid >> 2;   // 4x2 warp grid, tile 32x64

    long long aoff = (long long)blockIdx.z * sAb + (long long)blockIdx.y * 128 * lda;
    long long boff = (long long)blockIdx.z * sBb + (long long)blockIdx.x * 128 * ldb;
    Ah += aoff; Al += aoff;
    Bh += boff; Bl += boff;

    float acc[64];
    #pragma unroll
    for (int i = 0; i < 64; i++) acc[i] = 0.0f;

    const uint32_t sbase = smem_u32(dsm);
    const int NC = K >> 5;

    issue_chunk(sbase, Ah, Al, Bh, Bl, lda, ldb, 0, tid);
    CPCOMMIT();

    for (int i = 0; i < NC; i++) {
        CPWAIT0();               // chunk i resident
        __syncthreads();         // all warps past compute(i-1); buffer visible
        if (i + 1 < NC) {
            issue_chunk(sbase + ((i + 1) & 1) * STAGEB, Ah, Al, Bh, Bl,
                        lda, ldb, (i + 1) * 32, tid);
            CPCOMMIT();
        }
        gemm_compute(sbase + (i & 1) * STAGEB, wm, wn, lane, acc);
    }

    // epilogue: frag c0:(r,c) c1:(r,c+1) c2:(r+8,c) c3:(r+8,c+1)
    const long long wr = (long long)blockIdx.y * 128 + wm * 32;
    const long long wc = (long long)blockIdx.x * 128 + wn * 64;
    #pragma unroll
    for (int mi = 0; mi < 2; mi++) {
        long long r0 = wr + mi * 16 + (lane >> 2);
        float rb0 = rowbias ? rowbias[r0]     : 0.0f;
        float rb1 = rowbias ? rowbias[r0 + 8] : 0.0f;
        #pragma unroll
        for (int ni = 0; ni < 8; ni++) {
            long long c0 = wc + ni * 8 + (lane & 3) * 2;
            float cb0 = 0.0f, cb1 = 0.0f;
            if (colbias) { float2 cb = *(const float2*)(colbias + c0); cb0 = cb.x; cb1 = cb.y; }
            const float* a = acc + (mi * 8 + ni) * 4;
            float v00 = (a[0] + cb0 + rb0) * oscale, v01 = (a[1] + cb1 + rb0) * oscale;
            float v10 = (a[2] + cb0 + rb1) * oscale, v11 = (a[3] + cb1 + rb1) * oscale;
            long long o0 = ((long long)blockIdx.z * sCb) + r0 * ldc + c0;
            if (OUT == 0) {
                *(float2*)(C + o0)           = make_float2(v00, v01);
                *(float2*)(C + o0 + 8 * ldc) = make_float2(v10, v11);
            } else {
                __half h00, l00, h01, l01, h10, l10, h11, l11;
                split1(v00, h00, l00); split1(v01, h01, l01);
                split1(v10, h10, l10); split1(v11, h11, l11);
                *(uint32_t*)(Ch + o0)           = pack2(h00, h01);
                *(uint32_t*)(Cl + o0)           = pack2(l00, l01);
                *(uint32_t*)(Ch + o0 + 8 * ldc) = pack2(h10, h11);
                *(uint32_t*)(Cl + o0 + 8 * ldc) = pack2(l10, l11);
            }
        }
    }
}

// ---------------- fused mask+softmax: S -> P planes + att (transposed) ----------------
__global__ __launch_bounds__(256)
void smx_att(const float* __restrict__ S, const unsigned char* __restrict__ cmask,
             const unsigned char* __restrict__ words,
             __half* __restrict__ Ph, __half* __restrict__ Pl, float* __restrict__ att)
{
    __shared__ float tile[8][521];
    __shared__ unsigned char words_s[512];
    const int b = blockIdx.y, q = blockIdx.x;
    const int tid = threadIdx.x, w = tid >> 5, lane = tid & 31;
    for (int i = tid; i < 512; i += 256) words_s[i] = words[b * 512 + i];
    __syncthreads();

    const long long base8 = ((long long)b * 512 + q) * 8;
    const float* row = S + (base8 + w) * 512;
    const bool cmb = cmask[base8 + w] != 0;

    float v[16];
    float mx = -3.0e38f;
    #pragma unroll
    for (int i = 0; i < 4; i++) {
        float4 x = *(const float4*)(row + i * 128 + lane * 4);
        float t[4] = {x.x, x.y, x.z, x.w};
        #pragma unroll
        for (int j = 0; j < 4; j++) {
            int k = i * 128 + lane * 4 + j;
            float s = t[j];                       // 1/sqrt(512) pre-folded into Qp
            s = (cmb && words_s[k]) ? s : -1e9f;
            v[i * 4 + j] = s;
            mx = fmaxf(mx, s);
        }
    }
    #pragma unroll
    for (int o = 16; o > 0; o >>= 1) mx = fmaxf(mx, __shfl_xor_sync(0xffffffffu, mx, o));
    float sum = 0.0f;
    #pragma unroll
    for (int i = 0; i < 16; i++) { float e = __expf(v[i] - mx); v[i] = e; sum += e; }
    #pragma unroll
    for (int o = 16; o > 0; o >>= 1) sum += __shfl_xor_sync(0xffffffffu, sum, o);
    const float inv = 1.0f / sum;

    #pragma unroll
    for (int i = 0; i < 4; i++) {
        float p0 = v[i*4]*inv, p1 = v[i*4+1]*inv, p2 = v[i*4+2]*inv, p3 = v[i*4+3]*inv;
        long long off = (base8 + w) * 512 + i * 128 + lane * 4;
        __half h0,l0,h1,l1,h2,l2,h3,l3;
        split1(p0,h0,l0); split1(p1,h1,l1); split1(p2,h2,l2); split1(p3,h3,l3);
        *(uint2*)(Ph + off) = make_uint2(pack2(h0,h1), pack2(h2,h3));
        *(uint2*)(Pl + off) = make_uint2(pack2(l0,l1), pack2(l2,l3));
        int k = i * 128 + lane * 4;
        tile[w][k] = p0; tile[w][k+1] = p1; tile[w][k+2] = p2; tile[w][k+3] = p3;
    }
    if (att) {
        __syncthreads();
        float* obase = att + base8 * 512;
        #pragma unroll
        for (int it = 0; it < 16; it++) {
            int idx = tid + it * 256;
            obase[idx] = tile[idx & 7][idx >> 3];
        }
    }
}

// ---------------- input conversion ----------------
__global__ void split4_kernel(const float* __restrict__ in, __half* __restrict__ h,
                              __half* __restrict__ l, long long n4) {
    long long i = (long long)blockIdx.x * blockDim.x + threadIdx.x;
    if (i >= n4) return;
    float4 v = ((const float4*)in)[i];
    __half h0,l0,h1,l1,h2,l2,h3,l3;
    split1(v.x,h0,l0); split1(v.y,h1,l1); split1(v.z,h2,l2); split1(v.w,h3,l3);
    ((uint2*)h)[i] = make_uint2(pack2(h0,h1), pack2(h2,h3));
    ((uint2*)l)[i] = make_uint2(pack2(l0,l1), pack2(l2,l3));
}

// all 4 weight transposes in ONE launch: [R][C] fp32 -> [C][R] hi/lo planes
__global__ void transpose_split_all(
    const float* __restrict__ Wq, const float* __restrict__ Wk,
    const float* __restrict__ Wv, const float* __restrict__ Wz,
    __half* __restrict__ wqh, __half* __restrict__ wql,
    __half* __restrict__ wkh, __half* __restrict__ wkl,
    __half* __restrict__ wvh, __half* __restrict__ wvl,
    __half* __restrict__ wzh, __half* __restrict__ wzl)
{
    __shared__ float t[32][33];
    const int z = blockIdx.z;
    const float* in; __half *oh, *ol; int R;
    if (z == 0)      { in = Wq; oh = wqh; ol = wql; R = DQ; }
    else if (z == 1) { in = Wk; oh = wkh; ol = wkl; R = DIN; }
    else if (z == 2) { in = Wv; oh = wvh; ol = wvl; R = DIN; }
    else             { in = Wz; oh = wzh; ol = wzl; R = DOUT; }
    const int C = 512;
    int c0 = blockIdx.x * 32, r0 = blockIdx.y * 32;
    if (r0 >= R) return;   // uniform per block
    int x = threadIdx.x, y = threadIdx.y;
    #pragma unroll
    for (int j = 0; j < 32; j += 8)
        t[y + j][x] = in[(long long)(r0 + y + j) * C + c0 + x];
    __syncthreads();
    #pragma unroll
    for (int j = 0; j < 32; j += 8) {
        float v = t[x][y + j];
        __half h, l; split1(v, h, l);
        long long o = (long long)(c0 + y + j) * R + r0 + x;
        oh[o] = h; ol[o] = l;
    }
}

// ---------------- mask handling ----------------
__global__ void detect_mask_kernel(const unsigned int* __restrict__ m) {
    if (blockIdx.x == 0 && threadIdx.x == 0) {
        bool all01 = true, allf = true;
        for (int i = 0; i < 1024; i++) {
            unsigned int v = m[i];
            if (!(v == 0u || v == 1u)) all01 = false;
            if (!(v == 0u || v == 0x3F800000u)) allf = false;
        }
        g_mask_mode = all01 ? 1 : (allf ? 0 : 2);
    }
}
__global__ void normalize_mask_kernel(const void* __restrict__ m,
                                      unsigned char* __restrict__ cmask,
                                      unsigned char* __restrict__ words) {
    int idx = blockIdx.x * blockDim.x + threadIdx.x;
    if (idx >= BB * SS) return;
    int mode = g_mask_mode;
    unsigned char any = 0;
    #pragma unroll
    for (int w = 0; w < WW; w++) {
        int e = idx * WW + w;
        unsigned char v;
        if (mode == 1)      v = (((const int*)m)[e] != 0);
        else if (mode == 0) v = (((const float*)m)[e] != 0.0f);
        else                v = (((const unsigned char*)m)[e] != 0);
        cmask[e] = v;
        any |= v;
    }
    words[idx] = any;
}

// ---------------- launch ----------------
extern "C" void kernel_launch(void* const* d_in, const int* in_sizes, int n_in,
                              void* d_out, int out_size) {
    const float* query = (const float*)d_in[0];
    const float* data  = (const float*)d_in[1];
    const void*  maskr = d_in[2];
    const float* Wq = (const float*)d_in[3];
    const float* bq = (const float*)d_in[4];
    const float* Wk = (const float*)d_in[5];
    const float* bk = (const float*)d_in[6];
    const float* Wv = (const float*)d_in[7];
    const float* bv = (const float*)d_in[8];
    const float* Wz = (const float*)d_in[9];
    const float* bz = (const float*)d_in[10];

    float* out = (float*)d_out;
    const long long zs_elems  = (long long)BB * SS * WW * DOUT;
    const long long att_elems = (long long)BB * SS * SS * WW;
    float* att = ((long long)out_size >= zs_elems + att_elems) ? out + zs_elems : nullptr;

    __half *qh,*ql,*dh,*dl,*wqh,*wql,*wkh,*wkl,*wvh,*wvl,*wzh,*wzl;
    __half *Qh,*Ql,*Kh,*Kl,*Vh,*Vl,*Ph,*Pl,*Zh,*Zl;
    float *Sp;
    unsigned char *cm, *wm;
    cudaGetSymbolAddress((void**)&qh, g_qh);  cudaGetSymbolAddress((void**)&ql, g_ql);
    cudaGetSymbolAddress((void**)&dh, g_dh);  cudaGetSymbolAddress((void**)&dl, g_dl);
    cudaGetSymbolAddress((void**)&wqh, g_wqh); cudaGetSymbolAddress((void**)&wql, g_wql);
    cudaGetSymbolAddress((void**)&wkh, g_wkh); cudaGetSymbolAddress((void**)&wkl, g_wkl);
    cudaGetSymbolAddress((void**)&wvh, g_wvh); cudaGetSymbolAddress((void**)&wvl, g_wvl);
    cudaGetSymbolAddress((void**)&wzh, g_wzh); cudaGetSymbolAddress((void**)&wzl, g_wzl);
    cudaGetSymbolAddress((void**)&Qh, g_Qh);  cudaGetSymbolAddress((void**)&Ql, g_Ql);
    cudaGetSymbolAddress((void**)&Kh, g_Kh);  cudaGetSymbolAddress((void**)&Kl, g_Kl);
    cudaGetSymbolAddress((void**)&Vh, g_Vh);  cudaGetSymbolAddress((void**)&Vl, g_Vl);
    cudaGetSymbolAddress((void**)&Ph, g_Ph);  cudaGetSymbolAddress((void**)&Pl, g_Pl);
    cudaGetSymbolAddress((void**)&Zh, g_Zh);  cudaGetSymbolAddress((void**)&Zl, g_Zl);
    cudaGetSymbolAddress((void**)&Sp, g_S);
    cudaGetSymbolAddress((void**)&cm, g_cmask);
    cudaGetSymbolAddress((void**)&wm, g_words);

    const int SMEM = NSTAGE * STAGEB;   // 81920 -> 2 CTAs/SM
    cudaFuncSetAttribute(hgemm<0>, cudaFuncAttributeMaxDynamicSharedMemorySize, SMEM);
    cudaFuncSetAttribute(hgemm<1>, cudaFuncAttributeMaxDynamicSharedMemorySize, SMEM);

    // launches 1-5 (keeps hgemm Qproj as launch #6 for the ncu -s 5 -c 1 window)
    detect_mask_kernel<<<1, 1>>>((const unsigned int*)maskr);
    normalize_mask_kernel<<<(BB * SS + 255) / 256, 256>>>(maskr, cm, wm);
    {
        long long nq4 = (long long)BB * SS * WW * DQ / 4;
        split4_kernel<<<(unsigned)((nq4 + 255) / 256), 256>>>(query, qh, ql, nq4);
        long long nd4 = (long long)BB * SS * DIN / 4;
        split4_kernel<<<(unsigned)((nd4 + 255) / 256), 256>>>(data, dh, dl, nd4);
    }
    transpose_split_all<<<dim3(16, 16, 4), dim3(32, 8)>>>(
        Wq, Wk, Wv, Wz, wqh, wql, wkh, wkl, wvh, wvl, wzh, wzl);

    const float SCALE = 0.04419417382415922f;  // 1/sqrt(512), folded into Qp

    // #6: Qproj -> Qp planes (scaled): [65536,512]
    hgemm<1><<<dim3(4, 512, 1), 256, SMEM>>>(qh, ql, wqh, wql, bq, nullptr, SCALE,
        nullptr, Qh, Ql, DQ, DQ, DQ, DIN, 0, 0, 0);
    // Kproj -> Kp planes: [8192,512]
    hgemm<1><<<dim3(4, 64, 1), 256, SMEM>>>(dh, dl, wkh, wkl, bk, nullptr, 1.0f,
        nullptr, Kh, Kl, DIN, DIN, DIN, DIN, 0, 0, 0);
    // VT[b] planes: [512z,512s] = wv[z,:] . data_b[s,:] + bv[z]
    hgemm<1><<<dim3(4, 4, BB), 256, SMEM>>>(wvh, wvl, dh, dl, nullptr, bv, 1.0f,
        nullptr, Vh, Vl, DIN, DIN, DIN, SS, 0, (long long)SS * DIN, (long long)DIN * SS);
    // scores[b] fp32: [4096,512] = Qp_b @ Kp_b^T
    hgemm<0><<<dim3(4, 32, BB), 256, SMEM>>>(Qh, Ql, Kh, Kl, nullptr, nullptr, 1.0f,
        Sp, nullptr, nullptr, DIN, DIN, DIN, SS,
        (long long)SS * WW * DIN, (long long)SS * DIN, (long long)SS * WW * SS);
    // softmax + P planes + att
    smx_att<<<dim3(SS, BB), 256>>>(Sp, cm, wm, Ph, Pl, att);
    // Z1[b] planes = P_b @ VT_b^T
    hgemm<1><<<dim3(4, 32, BB), 256, SMEM>>>(Ph, Pl, Vh, Vl, nullptr, nullptr, 1.0f,
        nullptr, Zh, Zl, SS, SS, SS, DOUT,
        (long long)SS * WW * SS, (long long)DIN * SS, (long long)SS * WW * DOUT);
    // zs = Z1 @ Wz^T + bz -> d_out fp32
    hgemm<0><<<dim3(4, 512, 1), 256, SMEM>>>(Zh, Zl, wzh, wzl, bz, nullptr, 1.0f,
        out, nullptr, nullptr, DOUT, DOUT, DOUT, DOUT, 0, 0, 0);
}

// round 9
// speedup vs baseline: 1.4579x; 1.3640x over previous
#include <cuda_runtime.h>
#include <cuda_fp16.h>
#include <math.h>
#include <stdint.h>

#define BB   16
#define SS   512
#define WW   8
#define DQ   256
#define DIN  512
#define DOUT 512

// ---------------- device scratch: hi/lo fp16 plane pairs ----------------
// lo planes only kept where the tensor is consumed as the A (lo-corrected) operand.
static __device__ __align__(1024) __half g_qh[(size_t)BB*SS*WW*DQ],  g_ql[(size_t)BB*SS*WW*DQ];
static __device__ __align__(1024) __half g_dh[(size_t)BB*SS*DIN],    g_dl[(size_t)BB*SS*DIN];
static __device__ __align__(1024) __half g_wqh[DIN*DQ];
static __device__ __align__(1024) __half g_wkh[DIN*DIN];
static __device__ __align__(1024) __half g_wvh[DOUT*DIN], g_wvl[DOUT*DIN];
static __device__ __align__(1024) __half g_wzh[DOUT*DOUT];
static __device__ __align__(1024) __half g_Qh[(size_t)BB*SS*WW*DIN], g_Ql[(size_t)BB*SS*WW*DIN];
static __device__ __align__(1024) __half g_Kh[(size_t)BB*SS*DIN];                     // B-only
static __device__ __align__(1024) __half g_Vh[(size_t)BB*DIN*SS];                     // V^T, B-only
static __device__ __align__(1024) __half g_Ph[(size_t)BB*SS*WW*SS],  g_Pl[(size_t)BB*SS*WW*SS];
static __device__ __align__(1024) __half g_Zh[(size_t)BB*SS*WW*DOUT],g_Zl[(size_t)BB*SS*WW*DOUT];
static __device__ __align__(1024) float  g_S[(size_t)BB*SS*WW*SS];   // fp32 scores
static __device__ unsigned char g_cmask[BB*SS*WW];
static __device__ unsigned char g_words[BB*SS];
static __device__ int g_mask_mode;

// ---------------- low-level helpers ----------------
__device__ __forceinline__ uint32_t smem_u32(const void* p) {
    uint32_t a;
    asm("{ .reg .u64 t; cvta.to.shared.u64 t, %1; cvt.u32.u64 %0, t; }" : "=r"(a) : "l"(p));
    return a;
}
__device__ __forceinline__ void ldsm4(uint32_t* r, uint32_t addr) {
    asm volatile("ldmatrix.sync.aligned.m8n8.x4.shared.b16 {%0,%1,%2,%3}, [%4];\n"
        : "=r"(r[0]), "=r"(r[1]), "=r"(r[2]), "=r"(r[3]) : "r"(addr));
}
__device__ __forceinline__ void mma16816(float* c, const uint32_t* a, const uint32_t* b) {
    asm volatile(
        "mma.sync.aligned.m16n8k16.row.col.f32.f16.f16.f32 "
        "{%0,%1,%2,%3}, {%4,%5,%6,%7}, {%8,%9}, {%0,%1,%2,%3};\n"
        : "+f"(c[0]), "+f"(c[1]), "+f"(c[2]), "+f"(c[3])
        : "r"(a[0]), "r"(a[1]), "r"(a[2]), "r"(a[3]), "r"(b[0]), "r"(b[1]));
}
#define CPASYNC16(dst, src) \
    asm volatile("cp.async.cg.shared.global [%0], [%1], 16;\n" :: "r"(dst), "l"(src) : "memory")
#define CPCOMMIT() asm volatile("cp.async.commit_group;\n" ::: "memory")
#define CPWAIT0()  asm volatile("cp.async.wait_group 0;\n" ::: "memory")

__device__ __forceinline__ uint32_t pack2(__half a, __half b) {
    __half2 h = __halves2half2(a, b);
    return *(uint32_t*)&h;
}
__device__ __forceinline__ void split1(float v, __half& h, __half& l) {
    h = __float2half_rn(v);
    l = __float2half_rn(v - __half2float(h));
}

// ---------------- 2-MMA split-fp16 GEMM: C[M,N] = A[M,K] @ B[N,K]^T ----------------
// acc = ah*bh + al*bh (B low plane dropped; error ~1e-4 per GEMM).
// BM=128, BN=128, BK=32, 256 threads, 8 warps (4x2), warp tile 32x64, 2-stage, 2 CTAs/SM.
#define ROWB   80
#define PLANE  10240           /* 128 rows x 80B */
#define STAGEB 30720           /* Ah, Al, Bh planes */
#define NSTAGE 2

__device__ __forceinline__ void issue_chunk(uint32_t sb,
    const __half* Ah, const __half* Al, const __half* Bh,
    long long lda, long long ldb, int k0, int tid)
{
    #pragma unroll
    for (int it = 0; it < 2; it++) {              // 128 rows x 4 lines per plane
        int s = tid + it * 256, r = s >> 2, sg = s & 3;
        long long ga = (long long)r * lda + k0 + sg * 8;
        CPASYNC16(sb + r * ROWB + sg * 16,           Ah + ga);
        CPASYNC16(sb + PLANE + r * ROWB + sg * 16,   Al + ga);
        long long gb = (long long)r * ldb + k0 + sg * 8;
        CPASYNC16(sb + 2*PLANE + r * ROWB + sg * 16, Bh + gb);
    }
}

__device__ __forceinline__ void gemm_compute(uint32_t sb, int wm, int wn, int lane, float* acc) {
    const uint32_t Ah = sb, Al = sb + PLANE, Bh = sb + 2*PLANE;
    const int mrow = (lane & 7) + ((lane >> 3) & 1) * 8, akcol = ((lane >> 4) & 1) * 8;
    const int nrow = (lane & 7) + ((lane >> 4) & 1) * 8, bkcol = ((lane >> 3) & 1) * 8;
    #pragma unroll
    for (int ks = 0; ks < 2; ks++) {
        const int k0 = ks * 16;
        uint32_t bfh[16];
        #pragma unroll
        for (int np = 0; np < 4; np++) {
            uint32_t off = (uint32_t)((wn * 64 + np * 16 + nrow) * ROWB + (k0 + bkcol) * 2);
            ldsm4(&bfh[np * 4], Bh + off);   // [N][K] k-contig == mma "col" B, non-trans
        }
        #pragma unroll
        for (int mi = 0; mi < 2; mi++) {
            uint32_t off = (uint32_t)((wm * 32 + mi * 16 + mrow) * ROWB + (k0 + akcol) * 2);
            uint32_t ah[4], al[4];
            ldsm4(ah, Ah + off);
            ldsm4(al, Al + off);
            #pragma unroll
            for (int ni = 0; ni < 8; ni++) {
                float* c = acc + (mi * 8 + ni) * 4;
                mma16816(c, ah, &bfh[ni * 2]);   // hi*hi
                mma16816(c, al, &bfh[ni * 2]);   // lo*hi
            }
        }
    }
}

// OUT: 0 = fp32 C, 1 = fp16 planes (Ch always, Cl if non-null)
template<int OUT>
__global__ __launch_bounds__(256, 2)
void hgemm(const __half* __restrict__ Ah, const __half* __restrict__ Al,
           const __half* __restrict__ Bh,
           const float* __restrict__ colbias, const float* __restrict__ rowbias, float oscale,
           float* __restrict__ C, __half* __restrict__ Ch, __half* __restrict__ Cl,
           int K, long long lda, long long ldb, long long ldc,
           long long sAb, long long sBb, long long sCb)
{
    extern __shared__ char dsm[];
    const int tid = threadIdx.x, wid = tid >> 5, lane = tid & 31;
    const int wm = wid & 3, wn = wid >> 2;   // 4x2 warp grid, tile 32x64

    long long aoff = (long long)blockIdx.z * sAb + (long long)blockIdx.y * 128 * lda;
    long long boff = (long long)blockIdx.z * sBb + (long long)blockIdx.x * 128 * ldb;
    Ah += aoff; Al += aoff;
    Bh += boff;

    float acc[64];
    #pragma unroll
    for (int i = 0; i < 64; i++) acc[i] = 0.0f;

    const uint32_t sbase = smem_u32(dsm);
    const int NC = K >> 5;

    issue_chunk(sbase, Ah, Al, Bh, lda, ldb, 0, tid);
    CPCOMMIT();

    for (int i = 0; i < NC; i++) {
        CPWAIT0();               // chunk i resident
        __syncthreads();         // all warps past compute(i-1)
        if (i + 1 < NC) {
            issue_chunk(sbase + ((i + 1) & 1) * STAGEB, Ah, Al, Bh,
                        lda, ldb, (i + 1) * 32, tid);
            CPCOMMIT();
        }
        gemm_compute(sbase + (i & 1) * STAGEB, wm, wn, lane, acc);
    }

    // epilogue: frag c0:(r,c) c1:(r,c+1) c2:(r+8,c) c3:(r+8,c+1)
    const long long wr = (long long)blockIdx.y * 128 + wm * 32;
    const long long wc = (long long)blockIdx.x * 128 + wn * 64;
    #pragma unroll
    for (int mi = 0; mi < 2; mi++) {
        long long r0 = wr + mi * 16 + (lane >> 2);
        float rb0 = rowbias ? rowbias[r0]     : 0.0f;
        float rb1 = rowbias ? rowbias[r0 + 8] : 0.0f;
        #pragma unroll
        for (int ni = 0; ni < 8; ni++) {
            long long c0 = wc + ni * 8 + (lane & 3) * 2;
            float cb0 = 0.0f, cb1 = 0.0f;
            if (colbias) { float2 cb = *(const float2*)(colbias + c0); cb0 = cb.x; cb1 = cb.y; }
            const float* a = acc + (mi * 8 + ni) * 4;
            float v00 = (a[0] + cb0 + rb0) * oscale, v01 = (a[1] + cb1 + rb0) * oscale;
            float v10 = (a[2] + cb0 + rb1) * oscale, v11 = (a[3] + cb1 + rb1) * oscale;
            long long o0 = ((long long)blockIdx.z * sCb) + r0 * ldc + c0;
            if (OUT == 0) {
                *(float2*)(C + o0)           = make_float2(v00, v01);
                *(float2*)(C + o0 + 8 * ldc) = make_float2(v10, v11);
            } else {
                __half h00, l00, h01, l01, h10, l10, h11, l11;
                split1(v00, h00, l00); split1(v01, h01, l01);
                split1(v10, h10, l10); split1(v11, h11, l11);
                *(uint32_t*)(Ch + o0)           = pack2(h00, h01);
                *(uint32_t*)(Ch + o0 + 8 * ldc) = pack2(h10, h11);
                if (Cl) {
                    *(uint32_t*)(Cl + o0)           = pack2(l00, l01);
                    *(uint32_t*)(Cl + o0 + 8 * ldc) = pack2(l10, l11);
                }
            }
        }
    }
}

// ---------------- fused mask+softmax: S -> P planes + att (transposed) ----------------
__global__ __launch_bounds__(256)
void smx_att(const float* __restrict__ S, const unsigned char* __restrict__ cmask,
             const unsigned char* __restrict__ words,
             __half* __restrict__ Ph, __half* __restrict__ Pl, float* __restrict__ att)
{
    __shared__ float tile[8][521];
    __shared__ unsigned char words_s[512];
    const int b = blockIdx.y, q = blockIdx.x;
    const int tid = threadIdx.x, w = tid >> 5, lane = tid & 31;
    for (int i = tid; i < 512; i += 256) words_s[i] = words[b * 512 + i];
    __syncthreads();

    const long long base8 = ((long long)b * 512 + q) * 8;
    const float* row = S + (base8 + w) * 512;
    const bool cmb = cmask[base8 + w] != 0;

    float v[16];
    float mx = -3.0e38f;
    #pragma unroll
    for (int i = 0; i < 4; i++) {
        float4 x = *(const float4*)(row + i * 128 + lane * 4);
        float t[4] = {x.x, x.y, x.z, x.w};
        #pragma unroll
        for (int j = 0; j < 4; j++) {
            int k = i * 128 + lane * 4 + j;
            float s = t[j];                       // 1/sqrt(512) pre-folded into Qp
            s = (cmb && words_s[k]) ? s : -1e9f;
            v[i * 4 + j] = s;
            mx = fmaxf(mx, s);
        }
    }
    #pragma unroll
    for (int o = 16; o > 0; o >>= 1) mx = fmaxf(mx, __shfl_xor_sync(0xffffffffu, mx, o));
    float sum = 0.0f;
    #pragma unroll
    for (int i = 0; i < 16; i++) { float e = __expf(v[i] - mx); v[i] = e; sum += e; }
    #pragma unroll
    for (int o = 16; o > 0; o >>= 1) sum += __shfl_xor_sync(0xffffffffu, sum, o);
    const float inv = 1.0f / sum;

    #pragma unroll
    for (int i = 0; i < 4; i++) {
        float p0 = v[i*4]*inv, p1 = v[i*4+1]*inv, p2 = v[i*4+2]*inv, p3 = v[i*4+3]*inv;
        long long off = (base8 + w) * 512 + i * 128 + lane * 4;
        __half h0,l0,h1,l1,h2,l2,h3,l3;
        split1(p0,h0,l0); split1(p1,h1,l1); split1(p2,h2,l2); split1(p3,h3,l3);
        *(uint2*)(Ph + off) = make_uint2(pack2(h0,h1), pack2(h2,h3));
        *(uint2*)(Pl + off) = make_uint2(pack2(l0,l1), pack2(l2,l3));
        int k = i * 128 + lane * 4;
        tile[w][k] = p0; tile[w][k+1] = p1; tile[w][k+2] = p2; tile[w][k+3] = p3;
    }
    if (att) {
        __syncthreads();
        float* obase = att + base8 * 512;
        #pragma unroll
        for (int it = 0; it < 16; it++) {
            int idx = tid + it * 256;
            obase[idx] = tile[idx & 7][idx >> 3];
        }
    }
}

// ---------------- input conversion ----------------
__global__ void split4_kernel(const float* __restrict__ in, __half* __restrict__ h,
                              __half* __restrict__ l, long long n4) {
    long long i = (long long)blockIdx.x * blockDim.x + threadIdx.x;
    if (i >= n4) return;
    float4 v = ((const float4*)in)[i];
    __half h0,l0,h1,l1,h2,l2,h3,l3;
    split1(v.x,h0,l0); split1(v.y,h1,l1); split1(v.z,h2,l2); split1(v.w,h3,l3);
    ((uint2*)h)[i] = make_uint2(pack2(h0,h1), pack2(h2,h3));
    ((uint2*)l)[i] = make_uint2(pack2(l0,l1), pack2(l2,l3));
}

// all 4 weight transposes in ONE launch: [R][C] fp32 -> [C][R] planes
// (lo plane written only for Wv — the only weight consumed as an A operand)
__global__ void transpose_split_all(
    const float* __restrict__ Wq, const float* __restrict__ Wk,
    const float* __restrict__ Wv, const float* __restrict__ Wz,
    __half* __restrict__ wqh, __half* __restrict__ wkh,
    __half* __restrict__ wvh, __half* __restrict__ wvl,
    __half* __restrict__ wzh)
{
    __shared__ float t[32][33];
    const int z = blockIdx.z;
    const float* in; __half *oh, *ol; int R;
    if (z == 0)      { in = Wq; oh = wqh; ol = nullptr; R = DQ; }
    else if (z == 1) { in = Wk; oh = wkh; ol = nullptr; R = DIN; }
    else if (z == 2) { in = Wv; oh = wvh; ol = wvl;     R = DIN; }
    else             { in = Wz; oh = wzh; ol = nullptr; R = DOUT; }
    const int C = 512;
    int c0 = blockIdx.x * 32, r0 = blockIdx.y * 32;
    if (r0 >= R) return;   // uniform per block
    int x = threadIdx.x, y = threadIdx.y;
    #pragma unroll
    for (int j = 0; j < 32; j += 8)
        t[y + j][x] = in[(long long)(r0 + y + j) * C + c0 + x];
    __syncthreads();
    #pragma unroll
    for (int j = 0; j < 32; j += 8) {
        float v = t[x][y + j];
        __half h, l; split1(v, h, l);
        long long o = (long long)(c0 + y + j) * R + r0 + x;
        oh[o] = h;
        if (ol) ol[o] = l;
    }
}

// ---------------- mask handling ----------------
__global__ void detect_mask_kernel(const unsigned int* __restrict__ m) {
    if (blockIdx.x == 0 && threadIdx.x == 0) {
        bool all01 = true, allf = true;
        for (int i = 0; i < 1024; i++) {
            unsigned int v = m[i];
            if (!(v == 0u || v == 1u)) all01 = false;
            if (!(v == 0u || v == 0x3F800000u)) allf = false;
        }
        g_mask_mode = all01 ? 1 : (allf ? 0 : 2);
    }
}
__global__ void normalize_mask_kernel(const void* __restrict__ m,
                                      unsigned char* __restrict__ cmask,
                                      unsigned char* __restrict__ words) {
    int idx = blockIdx.x * blockDim.x + threadIdx.x;
    if (idx >= BB * SS) return;
    int mode = g_mask_mode;
    unsigned char any = 0;
    #pragma unroll
    for (int w = 0; w < WW; w++) {
        int e = idx * WW + w;
        unsigned char v;
        if (mode == 1)      v = (((const int*)m)[e] != 0);
        else if (mode == 0) v = (((const float*)m)[e] != 0.0f);
        else                v = (((const unsigned char*)m)[e] != 0);
        cmask[e] = v;
        any |= v;
    }
    words[idx] = any;
}

// ---------------- launch ----------------
extern "C" void kernel_launch(void* const* d_in, const int* in_sizes, int n_in,
                              void* d_out, int out_size) {
    const float* query = (const float*)d_in[0];
    const float* data  = (const float*)d_in[1];
    const void*  maskr = d_in[2];
    const float* Wq = (const float*)d_in[3];
    const float* bq = (const float*)d_in[4];
    const float* Wk = (const float*)d_in[5];
    const float* bk = (const float*)d_in[6];
    const float* Wv = (const float*)d_in[7];
    const float* bv = (const float*)d_in[8];
    const float* Wz = (const float*)d_in[9];
    const float* bz = (const float*)d_in[10];

    float* out = (float*)d_out;
    const long long zs_elems  = (long long)BB * SS * WW * DOUT;
    const long long att_elems = (long long)BB * SS * SS * WW;
    float* att = ((long long)out_size >= zs_elems + att_elems) ? out + zs_elems : nullptr;

    __half *qh,*ql,*dh,*dl,*wqh,*wkh,*wvh,*wvl,*wzh;
    __half *Qh,*Ql,*Kh,*Vh,*Ph,*Pl,*Zh,*Zl;
    float *Sp;
    unsigned char *cm, *wm;
    cudaGetSymbolAddress((void**)&qh, g_qh);  cudaGetSymbolAddress((void**)&ql, g_ql);
    cudaGetSymbolAddress((void**)&dh, g_dh);  cudaGetSymbolAddress((void**)&dl, g_dl);
    cudaGetSymbolAddress((void**)&wqh, g_wqh);
    cudaGetSymbolAddress((void**)&wkh, g_wkh);
    cudaGetSymbolAddress((void**)&wvh, g_wvh); cudaGetSymbolAddress((void**)&wvl, g_wvl);
    cudaGetSymbolAddress((void**)&wzh, g_wzh);
    cudaGetSymbolAddress((void**)&Qh, g_Qh);  cudaGetSymbolAddress((void**)&Ql, g_Ql);
    cudaGetSymbolAddress((void**)&Kh, g_Kh);
    cudaGetSymbolAddress((void**)&Vh, g_Vh);
    cudaGetSymbolAddress((void**)&Ph, g_Ph);  cudaGetSymbolAddress((void**)&Pl, g_Pl);
    cudaGetSymbolAddress((void**)&Zh, g_Zh);  cudaGetSymbolAddress((void**)&Zl, g_Zl);
    cudaGetSymbolAddress((void**)&Sp, g_S);
    cudaGetSymbolAddress((void**)&cm, g_cmask);
    cudaGetSymbolAddress((void**)&wm, g_words);

    const int SMEM = NSTAGE * STAGEB;   // 61440 -> 2 CTAs/SM
    cudaFuncSetAttribute(hgemm<0>, cudaFuncAttributeMaxDynamicSharedMemorySize, SMEM);
    cudaFuncSetAttribute(hgemm<1>, cudaFuncAttributeMaxDynamicSharedMemorySize, SMEM);

    detect_mask_kernel<<<1, 1>>>((const unsigned int*)maskr);
    normalize_mask_kernel<<<(BB * SS + 255) / 256, 256>>>(maskr, cm, wm);
    {
        long long nq4 = (long long)BB * SS * WW * DQ / 4;
        split4_kernel<<<(unsigned)((nq4 + 255) / 256), 256>>>(query, qh, ql, nq4);
        long long nd4 = (long long)BB * SS * DIN / 4;
        split4_kernel<<<(unsigned)((nd4 + 255) / 256), 256>>>(data, dh, dl, nd4);
    }
    transpose_split_all<<<dim3(16, 16, 4), dim3(32, 8)>>>(
        Wq, Wk, Wv, Wz, wqh, wkh, wvh, wvl, wzh);

    const float SCALE = 0.04419417382415922f;  // 1/sqrt(512), folded into Qp

    // Qproj -> Qp planes (scaled): [65536,512]
    hgemm<1><<<dim3(4, 512, 1), 256, SMEM>>>(qh, ql, wqh, bq, nullptr, SCALE,
        nullptr, Qh, Ql, DQ, DQ, DQ, DIN, 0, 0, 0);
    // Kproj -> Kp hi only: [8192,512]
    hgemm<1><<<dim3(4, 64, 1), 256, SMEM>>>(dh, dl, wkh, bk, nullptr, 1.0f,
        nullptr, Kh, nullptr, DIN, DIN, DIN, DIN, 0, 0, 0);
    // VT[b] hi only: [512z,512s] = wv[z,:] . data_b[s,:] + bv[z]
    hgemm<1><<<dim3(4, 4, BB), 256, SMEM>>>(wvh, wvl, dh, nullptr, bv, 1.0f,
        nullptr, Vh, nullptr, DIN, DIN, DIN, SS, 0, (long long)SS * DIN, (long long)DIN * SS);
    // scores[b] fp32: [4096,512] = Qp_b @ Kp_b^T
    hgemm<0><<<dim3(4, 32, BB), 256, SMEM>>>(Qh, Ql, Kh, nullptr, nullptr, 1.0f,
        Sp, nullptr, nullptr, DIN, DIN, DIN, SS,
        (long long)SS * WW * DIN, (long long)SS * DIN, (long long)SS * WW * SS);
    // softmax + P planes + att
    smx_att<<<dim3(SS, BB), 256>>>(Sp, cm, wm, Ph, Pl, att);
    // Z1[b] planes = P_b @ VT_b^T
    hgemm<1><<<dim3(4, 32, BB), 256, SMEM>>>(Ph, Pl, Vh, nullptr, nullptr, 1.0f,
        nullptr, Zh, Zl, SS, SS, SS, DOUT,
        (long long)SS * WW * SS, (long long)DIN * SS, (long long)SS * WW * DOUT);
    // zs = Z1 @ Wz^T + bz -> d_out fp32
    hgemm<0><<<dim3(4, 512, 1), 256, SMEM>>>(Zh, Zl, wzh, bz, nullptr, 1.0f,
        out, nullptr, nullptr, DOUT, DOUT, DOUT, DOUT, 0, 0, 0);
}

// round 10
// speedup vs baseline: 1.8253x; 1.2520x over previous
#include <cuda_runtime.h>
#include <cuda_fp16.h>
#include <math.h>
#include <stdint.h>

#define BB   16
#define SS   512
#define WW   8
#define DQ   256
#define DIN  512
#define DOUT 512

// ---------------- device scratch: fp16 planes (lo only where consumed as corrected-A) ----------------
static __device__ __align__(1024) __half g_qh[(size_t)BB*SS*WW*DQ],  g_ql[(size_t)BB*SS*WW*DQ];
static __device__ __align__(1024) __half g_dh[(size_t)BB*SS*DIN],    g_dl[(size_t)BB*SS*DIN];
static __device__ __align__(1024) __half g_wqh[DIN*DQ];
static __device__ __align__(1024) __half g_wkh[DIN*DIN];
static __device__ __align__(1024) __half g_wvh[DOUT*DIN], g_wvl[DOUT*DIN];
static __device__ __align__(1024) __half g_wzh[DOUT*DOUT];
static __device__ __align__(1024) __half g_Qh[(size_t)BB*SS*WW*DIN], g_Ql[(size_t)BB*SS*WW*DIN];
static __device__ __align__(1024) __half g_Kh[(size_t)BB*SS*DIN];                    // B-only
static __device__ __align__(1024) __half g_Vh[(size_t)BB*DIN*SS];                    // V^T, B-only
static __device__ __align__(1024) __half g_Ph[(size_t)BB*SS*WW*SS];                  // A, hi-only
static __device__ __align__(1024) __half g_Zh[(size_t)BB*SS*WW*DOUT];                // A, hi-only
static __device__ __align__(1024) float  g_S[(size_t)BB*SS*WW*SS];   // fp32 scores
static __device__ unsigned char g_cmask[BB*SS*WW];
static __device__ unsigned char g_words[BB*SS];
static __device__ int g_mask_mode;

// ---------------- low-level helpers ----------------
__device__ __forceinline__ uint32_t smem_u32(const void* p) {
    uint32_t a;
    asm("{ .reg .u64 t; cvta.to.shared.u64 t, %1; cvt.u32.u64 %0, t; }" : "=r"(a) : "l"(p));
    return a;
}
__device__ __forceinline__ void ldsm4(uint32_t* r, uint32_t addr) {
    asm volatile("ldmatrix.sync.aligned.m8n8.x4.shared.b16 {%0,%1,%2,%3}, [%4];\n"
        : "=r"(r[0]), "=r"(r[1]), "=r"(r[2]), "=r"(r[3]) : "r"(addr));
}
__device__ __forceinline__ void mma16816(float* c, const uint32_t* a, const uint32_t* b) {
    asm volatile(
        "mma.sync.aligned.m16n8k16.row.col.f32.f16.f16.f32 "
        "{%0,%1,%2,%3}, {%4,%5,%6,%7}, {%8,%9}, {%0,%1,%2,%3};\n"
        : "+f"(c[0]), "+f"(c[1]), "+f"(c[2]), "+f"(c[3])
        : "r"(a[0]), "r"(a[1]), "r"(a[2]), "r"(a[3]), "r"(b[0]), "r"(b[1]));
}
#define CPASYNC16(dst, src) \
    asm volatile("cp.async.cg.shared.global [%0], [%1], 16;\n" :: "r"(dst), "l"(src) : "memory")
#define CPCOMMIT() asm volatile("cp.async.commit_group;\n" ::: "memory")
#define CPWAIT1()  asm volatile("cp.async.wait_group 1;\n" ::: "memory")

__device__ __forceinline__ uint32_t pack2(__half a, __half b) {
    __half2 h = __halves2half2(a, b);
    return *(uint32_t*)&h;
}
__device__ __forceinline__ void split1(float v, __half& h, __half& l) {
    h = __float2half_rn(v);
    l = __float2half_rn(v - __half2float(h));
}

// ---------------- split-fp16 GEMM: C[M,N] = A[M,K] @ B[N,K]^T ----------------
// APL=2: acc = ah*bh + al*bh ; APL=1: acc = ah*bh (plain fp16 A).
// BM=128, BN=128, BK=32, 256 thr, 8 warps (4x2), warp tile 32x64, 3-stage, 2 CTAs/SM.
#define ROWB   80
#define PLANE  10240           /* 128 rows x 80B */
#define STAGEB 30720           /* Ah, (Al), Bh plane slots */
#define NSTAGE 3

template<int APL>
__device__ __forceinline__ void issue_chunk(uint32_t sb,
    const __half* Ah, const __half* Al, const __half* Bh,
    long long lda, long long ldb, int k0, int tid)
{
    #pragma unroll
    for (int it = 0; it < 2; it++) {              // 128 rows x 4 lines per plane
        int s = tid + it * 256, r = s >> 2, sg = s & 3;
        long long ga = (long long)r * lda + k0 + sg * 8;
        CPASYNC16(sb + r * ROWB + sg * 16, Ah + ga);
        if (APL == 2) CPASYNC16(sb + PLANE + r * ROWB + sg * 16, Al + ga);
        long long gb = (long long)r * ldb + k0 + sg * 8;
        CPASYNC16(sb + 2*PLANE + r * ROWB + sg * 16, Bh + gb);
    }
}

template<int APL>
__device__ __forceinline__ void gemm_compute(uint32_t sb, int wm, int wn, int lane, float* acc) {
    const uint32_t Ah = sb, Al = sb + PLANE, Bh = sb + 2*PLANE;
    const int mrow = (lane & 7) + ((lane >> 3) & 1) * 8, akcol = ((lane >> 4) & 1) * 8;
    const int nrow = (lane & 7) + ((lane >> 4) & 1) * 8, bkcol = ((lane >> 3) & 1) * 8;
    #pragma unroll
    for (int ks = 0; ks < 2; ks++) {
        const int k0 = ks * 16;
        uint32_t bfh[16];
        #pragma unroll
        for (int np = 0; np < 4; np++) {
            uint32_t off = (uint32_t)((wn * 64 + np * 16 + nrow) * ROWB + (k0 + bkcol) * 2);
            ldsm4(&bfh[np * 4], Bh + off);   // [N][K] k-contig == mma "col" B, non-trans
        }
        #pragma unroll
        for (int mi = 0; mi < 2; mi++) {
            uint32_t off = (uint32_t)((wm * 32 + mi * 16 + mrow) * ROWB + (k0 + akcol) * 2);
            uint32_t ah[4], al[4];
            ldsm4(ah, Ah + off);
            if (APL == 2) ldsm4(al, Al + off);
            #pragma unroll
            for (int ni = 0; ni < 8; ni++) {
                float* c = acc + (mi * 8 + ni) * 4;
                mma16816(c, ah, &bfh[ni * 2]);                 // hi*hi
                if (APL == 2) mma16816(c, al, &bfh[ni * 2]);   // lo*hi
            }
        }
    }
}

// OUT: 0 = fp32 C, 1 = fp16 planes (Ch always, Cl if non-null)
template<int OUT, int APL>
__global__ __launch_bounds__(256, 2)
void hgemm(const __half* __restrict__ Ah, const __half* __restrict__ Al,
           const __half* __restrict__ Bh,
           const float* __restrict__ colbias, const float* __restrict__ rowbias, float oscale,
           float* __restrict__ C, __half* __restrict__ Ch, __half* __restrict__ Cl,
           int K, long long lda, long long ldb, long long ldc,
           long long sAb, long long sBb, long long sCb)
{
    extern __shared__ char dsm[];
    const int tid = threadIdx.x, wid = tid >> 5, lane = tid & 31;
    const int wm = wid & 3, wn = wid >> 2;   // 4x2 warp grid, tile 32x64

    long long aoff = (long long)blockIdx.z * sAb + (long long)blockIdx.y * 128 * lda;
    long long boff = (long long)blockIdx.z * sBb + (long long)blockIdx.x * 128 * ldb;
    Ah += aoff; if (APL == 2) Al += aoff;
    Bh += boff;

    float acc[64];
    #pragma unroll
    for (int i = 0; i < 64; i++) acc[i] = 0.0f;

    const uint32_t sbase = smem_u32(dsm);
    const int NC = K >> 5;

    issue_chunk<APL>(sbase,          Ah, Al, Bh, lda, ldb, 0,  tid); CPCOMMIT();
    issue_chunk<APL>(sbase + STAGEB, Ah, Al, Bh, lda, ldb, 32, tid); CPCOMMIT();

    for (int i = 0; i < NC; i++) {
        CPWAIT1();               // >= chunk i complete (i+1 may still be in flight)
        __syncthreads();         // all warps past compute(i-1); stage (i+2)%3 free
        if (i + 2 < NC)
            issue_chunk<APL>(sbase + ((i + 2) % NSTAGE) * STAGEB, Ah, Al, Bh,
                             lda, ldb, (i + 2) * 32, tid);
        CPCOMMIT();              // unconditional: keeps pending-group invariant at tail
        gemm_compute<APL>(sbase + (i % NSTAGE) * STAGEB, wm, wn, lane, acc);
    }

    // epilogue: frag c0:(r,c) c1:(r,c+1) c2:(r+8,c) c3:(r+8,c+1)
    const long long wr = (long long)blockIdx.y * 128 + wm * 32;
    const long long wc = (long long)blockIdx.x * 128 + wn * 64;
    #pragma unroll
    for (int mi = 0; mi < 2; mi++) {
        long long r0 = wr + mi * 16 + (lane >> 2);
        float rb0 = rowbias ? rowbias[r0]     : 0.0f;
        float rb1 = rowbias ? rowbias[r0 + 8] : 0.0f;
        #pragma unroll
        for (int ni = 0; ni < 8; ni++) {
            long long c0 = wc + ni * 8 + (lane & 3) * 2;
            float cb0 = 0.0f, cb1 = 0.0f;
            if (colbias) { float2 cb = *(const float2*)(colbias + c0); cb0 = cb.x; cb1 = cb.y; }
            const float* a = acc + (mi * 8 + ni) * 4;
            float v00 = (a[0] + cb0 + rb0) * oscale, v01 = (a[1] + cb1 + rb0) * oscale;
            float v10 = (a[2] + cb0 + rb1) * oscale, v11 = (a[3] + cb1 + rb1) * oscale;
            long long o0 = ((long long)blockIdx.z * sCb) + r0 * ldc + c0;
            if (OUT == 0) {
                *(float2*)(C + o0)           = make_float2(v00, v01);
                *(float2*)(C + o0 + 8 * ldc) = make_float2(v10, v11);
            } else {
                __half h00, l00, h01, l01, h10, l10, h11, l11;
                split1(v00, h00, l00); split1(v01, h01, l01);
                split1(v10, h10, l10); split1(v11, h11, l11);
                *(uint32_t*)(Ch + o0)           = pack2(h00, h01);
                *(uint32_t*)(Ch + o0 + 8 * ldc) = pack2(h10, h11);
                if (Cl) {
                    *(uint32_t*)(Cl + o0)           = pack2(l00, l01);
                    *(uint32_t*)(Cl + o0 + 8 * ldc) = pack2(l10, l11);
                }
            }
        }
    }
}

// ---------------- fused mask+softmax: S -> P hi plane + att (transposed) ----------------
__global__ __launch_bounds__(256)
void smx_att(const float* __restrict__ S, const unsigned char* __restrict__ cmask,
             const unsigned char* __restrict__ words,
             __half* __restrict__ Ph, float* __restrict__ att)
{
    __shared__ float tile[8][521];
    __shared__ unsigned char words_s[512];
    const int b = blockIdx.y, q = blockIdx.x;
    const int tid = threadIdx.x, w = tid >> 5, lane = tid & 31;
    for (int i = tid; i < 512; i += 256) words_s[i] = words[b * 512 + i];
    __syncthreads();

    const long long base8 = ((long long)b * 512 + q) * 8;
    const float* row = S + (base8 + w) * 512;
    const bool cmb = cmask[base8 + w] != 0;

    float v[16];
    float mx = -3.0e38f;
    #pragma unroll
    for (int i = 0; i < 4; i++) {
        float4 x = *(const float4*)(row + i * 128 + lane * 4);
        float t[4] = {x.x, x.y, x.z, x.w};
        #pragma unroll
        for (int j = 0; j < 4; j++) {
            int k = i * 128 + lane * 4 + j;
            float s = t[j];                       // 1/sqrt(512) pre-folded into Qp
            s = (cmb && words_s[k]) ? s : -1e9f;
            v[i * 4 + j] = s;
            mx = fmaxf(mx, s);
        }
    }
    #pragma unroll
    for (int o = 16; o > 0; o >>= 1) mx = fmaxf(mx, __shfl_xor_sync(0xffffffffu, mx, o));
    float sum = 0.0f;
    #pragma unroll
    for (int i = 0; i < 16; i++) { float e = __expf(v[i] - mx); v[i] = e; sum += e; }
    #pragma unroll
    for (int o = 16; o > 0; o >>= 1) sum += __shfl_xor_sync(0xffffffffu, sum, o);
    const float inv = 1.0f / sum;

    #pragma unroll
    for (int i = 0; i < 4; i++) {
        float p0 = v[i*4]*inv, p1 = v[i*4+1]*inv, p2 = v[i*4+2]*inv, p3 = v[i*4+3]*inv;
        long long off = (base8 + w) * 512 + i * 128 + lane * 4;
        *(uint2*)(Ph + off) = make_uint2(
            pack2(__float2half_rn(p0), __float2half_rn(p1)),
            pack2(__float2half_rn(p2), __float2half_rn(p3)));
        int k = i * 128 + lane * 4;
        tile[w][k] = p0; tile[w][k+1] = p1; tile[w][k+2] = p2; tile[w][k+3] = p3;
    }
    if (att) {
        __syncthreads();
        float* obase = att + base8 * 512;
        #pragma unroll
        for (int it = 0; it < 16; it++) {
            int idx = tid + it * 256;
            obase[idx] = tile[idx & 7][idx >> 3];
        }
    }
}

// ---------------- input conversion ----------------
__global__ void split4_kernel(const float* __restrict__ in, __half* __restrict__ h,
                              __half* __restrict__ l, long long n4) {
    long long i = (long long)blockIdx.x * blockDim.x + threadIdx.x;
    if (i >= n4) return;
    float4 v = ((const float4*)in)[i];
    __half h0,l0,h1,l1,h2,l2,h3,l3;
    split1(v.x,h0,l0); split1(v.y,h1,l1); split1(v.z,h2,l2); split1(v.w,h3,l3);
    ((uint2*)h)[i] = make_uint2(pack2(h0,h1), pack2(h2,h3));
    ((uint2*)l)[i] = make_uint2(pack2(l0,l1), pack2(l2,l3));
}

// all 4 weight transposes in ONE launch: [R][C] fp32 -> [C][R] planes
// (lo plane written only for Wv — the only weight consumed as an A operand)
__global__ void transpose_split_all(
    const float* __restrict__ Wq, const float* __restrict__ Wk,
    const float* __restrict__ Wv, const float* __restrict__ Wz,
    __half* __restrict__ wqh, __half* __restrict__ wkh,
    __half* __restrict__ wvh, __half* __restrict__ wvl,
    __half* __restrict__ wzh)
{
    __shared__ float t[32][33];
    const int z = blockIdx.z;
    const float* in; __half *oh, *ol; int R;
    if (z == 0)      { in = Wq; oh = wqh; ol = nullptr; R = DQ; }
    else if (z == 1) { in = Wk; oh = wkh; ol = nullptr; R = DIN; }
    else if (z == 2) { in = Wv; oh = wvh; ol = wvl;     R = DIN; }
    else             { in = Wz; oh = wzh; ol = nullptr; R = DOUT; }
    const int C = 512;
    int c0 = blockIdx.x * 32, r0 = blockIdx.y * 32;
    if (r0 >= R) return;   // uniform per block
    int x = threadIdx.x, y = threadIdx.y;
    #pragma unroll
    for (int j = 0; j < 32; j += 8)
        t[y + j][x] = in[(long long)(r0 + y + j) * C + c0 + x];
    __syncthreads();
    #pragma unroll
    for (int j = 0; j < 32; j += 8) {
        float v = t[x][y + j];
        __half h, l; split1(v, h, l);
        long long o = (long long)(c0 + y + j) * R + r0 + x;
        oh[o] = h;
        if (ol) ol[o] = l;
    }
}

// ---------------- mask handling ----------------
__global__ void detect_mask_kernel(const unsigned int* __restrict__ m) {
    if (blockIdx.x == 0 && threadIdx.x == 0) {
        bool all01 = true, allf = true;
        for (int i = 0; i < 1024; i++) {
            unsigned int v = m[i];
            if (!(v == 0u || v == 1u)) all01 = false;
            if (!(v == 0u || v == 0x3F800000u)) allf = false;
        }
        g_mask_mode = all01 ? 1 : (allf ? 0 : 2);
    }
}
__global__ void normalize_mask_kernel(const void* __restrict__ m,
                                      unsigned char* __restrict__ cmask,
                                      unsigned char* __restrict__ words) {
    int idx = blockIdx.x * blockDim.x + threadIdx.x;
    if (idx >= BB * SS) return;
    int mode = g_mask_mode;
    unsigned char any = 0;
    #pragma unroll
    for (int w = 0; w < WW; w++) {
        int e = idx * WW + w;
        unsigned char v;
        if (mode == 1)      v = (((const int*)m)[e] != 0);
        else if (mode == 0) v = (((const float*)m)[e] != 0.0f);
        else                v = (((const unsigned char*)m)[e] != 0);
        cmask[e] = v;
        any |= v;
    }
    words[idx] = any;
}

// ---------------- launch ----------------
extern "C" void kernel_launch(void* const* d_in, const int* in_sizes, int n_in,
                              void* d_out, int out_size) {
    const float* query = (const float*)d_in[0];
    const float* data  = (const float*)d_in[1];
    const void*  maskr = d_in[2];
    const float* Wq = (const float*)d_in[3];
    const float* bq = (const float*)d_in[4];
    const float* Wk = (const float*)d_in[5];
    const float* bk = (const float*)d_in[6];
    const float* Wv = (const float*)d_in[7];
    const float* bv = (const float*)d_in[8];
    const float* Wz = (const float*)d_in[9];
    const float* bz = (const float*)d_in[10];

    float* out = (float*)d_out;
    const long long zs_elems  = (long long)BB * SS * WW * DOUT;
    const long long att_elems = (long long)BB * SS * SS * WW;
    float* att = ((long long)out_size >= zs_elems + att_elems) ? out + zs_elems : nullptr;

    __half *qh,*ql,*dh,*dl,*wqh,*wkh,*wvh,*wvl,*wzh;
    __half *Qh,*Ql,*Kh,*Vh,*Ph,*Zh;
    float *Sp;
    unsigned char *cm, *wm;
    cudaGetSymbolAddress((void**)&qh, g_qh);  cudaGetSymbolAddress((void**)&ql, g_ql);
    cudaGetSymbolAddress((void**)&dh, g_dh);  cudaGetSymbolAddress((void**)&dl, g_dl);
    cudaGetSymbolAddress((void**)&wqh, g_wqh);
    cudaGetSymbolAddress((void**)&wkh, g_wkh);
    cudaGetSymbolAddress((void**)&wvh, g_wvh); cudaGetSymbolAddress((void**)&wvl, g_wvl);
    cudaGetSymbolAddress((void**)&wzh, g_wzh);
    cudaGetSymbolAddress((void**)&Qh, g_Qh);  cudaGetSymbolAddress((void**)&Ql, g_Ql);
    cudaGetSymbolAddress((void**)&Kh, g_Kh);
    cudaGetSymbolAddress((void**)&Vh, g_Vh);
    cudaGetSymbolAddress((void**)&Ph, g_Ph);
    cudaGetSymbolAddress((void**)&Zh, g_Zh);
    cudaGetSymbolAddress((void**)&Sp, g_S);
    cudaGetSymbolAddress((void**)&cm, g_cmask);
    cudaGetSymbolAddress((void**)&wm, g_words);

    const int SMEM = NSTAGE * STAGEB;   // 92160 -> 2 CTAs/SM (184 KB < 228 KB)
    cudaFuncSetAttribute(hgemm<0,1>, cudaFuncAttributeMaxDynamicSharedMemorySize, SMEM);
    cudaFuncSetAttribute(hgemm<0,2>, cudaFuncAttributeMaxDynamicSharedMemorySize, SMEM);
    cudaFuncSetAttribute(hgemm<1,1>, cudaFuncAttributeMaxDynamicSharedMemorySize, SMEM);
    cudaFuncSetAttribute(hgemm<1,2>, cudaFuncAttributeMaxDynamicSharedMemorySize, SMEM);

    detect_mask_kernel<<<1, 1>>>((const unsigned int*)maskr);
    normalize_mask_kernel<<<(BB * SS + 255) / 256, 256>>>(maskr, cm, wm);
    {
        long long nq4 = (long long)BB * SS * WW * DQ / 4;
        split4_kernel<<<(unsigned)((nq4 + 255) / 256), 256>>>(query, qh, ql, nq4);
        long long nd4 = (long long)BB * SS * DIN / 4;
        split4_kernel<<<(unsigned)((nd4 + 255) / 256), 256>>>(data, dh, dl, nd4);
    }
    transpose_split_all<<<dim3(16, 16, 4), dim3(32, 8)>>>(
        Wq, Wk, Wv, Wz, wqh, wkh, wvh, wvl, wzh);

    const float SCALE = 0.04419417382415922f;  // 1/sqrt(512), folded into Qp

    // Qproj -> Qp planes (scaled): [65536,512]
    hgemm<1,2><<<dim3(4, 512, 1), 256, SMEM>>>(qh, ql, wqh, bq, nullptr, SCALE,
        nullptr, Qh, Ql, DQ, DQ, DQ, DIN, 0, 0, 0);
    // Kproj -> Kp hi only: [8192,512]
    hgemm<1,2><<<dim3(4, 64, 1), 256, SMEM>>>(dh, dl, wkh, bk, nullptr, 1.0f,
        nullptr, Kh, nullptr, DIN, DIN, DIN, DIN, 0, 0, 0);
    // VT[b] hi only: [512z,512s] = wv[z,:] . data_b[s,:] + bv[z]
    hgemm<1,2><<<dim3(4, 4, BB), 256, SMEM>>>(wvh, wvl, dh, nullptr, bv, 1.0f,
        nullptr, Vh, nullptr, DIN, DIN, DIN, SS, 0, (long long)SS * DIN, (long long)DIN * SS);
    // scores[b] fp32: [4096,512] = Qp_b @ Kp_b^T
    hgemm<0,2><<<dim3(4, 32, BB), 256, SMEM>>>(Qh, Ql, Kh, nullptr, nullptr, 1.0f,
        Sp, nullptr, nullptr, DIN, DIN, DIN, SS,
        (long long)SS * WW * DIN, (long long)SS * DIN, (long long)SS * WW * SS);
    // softmax + P hi plane + att
    smx_att<<<dim3(SS, BB), 256>>>(Sp, cm, wm, Ph, att);
    // Z1[b] hi only = P_b @ VT_b^T   (single-plane A)
    hgemm<1,1><<<dim3(4, 32, BB), 256, SMEM>>>(Ph, nullptr, Vh, nullptr, nullptr, 1.0f,
        nullptr, Zh, nullptr, SS, SS, SS, DOUT,
        (long long)SS * WW * SS, (long long)DIN * SS, (long long)SS * WW * DOUT);
    // zs = Z1 @ Wz^T + bz -> d_out fp32   (single-plane A)
    hgemm<0,1><<<dim3(4, 512, 1), 256, SMEM>>>(Zh, nullptr, wzh, bz, nullptr, 1.0f,
        out, nullptr, nullptr, DOUT, DOUT, DOUT, DOUT, 0, 0, 0);
}

// round 11
// speedup vs baseline: 2.0889x; 1.1444x over previous
#include <cuda_runtime.h>
#include <cuda_fp16.h>
#include <math.h>
#include <stdint.h>

#define BB   16
#define SS   512
#define WW   8
#define DQ   256
#define DIN  512
#define DOUT 512

// ---------------- device scratch: fp16 planes (lo only where consumed as corrected-A) ----------------
static __device__ __align__(1024) __half g_qh[(size_t)BB*SS*WW*DQ],  g_ql[(size_t)BB*SS*WW*DQ];
static __device__ __align__(1024) __half g_dh[(size_t)BB*SS*DIN],    g_dl[(size_t)BB*SS*DIN];
static __device__ __align__(1024) __half g_wqh[DIN*DQ];
static __device__ __align__(1024) __half g_wkh[DIN*DIN];
static __device__ __align__(1024) __half g_wvh[DOUT*DIN], g_wvl[DOUT*DIN];
static __device__ __align__(1024) __half g_wzh[DOUT*DOUT];
static __device__ __align__(1024) __half g_Qh[(size_t)BB*SS*WW*DIN];                 // hi-only now
static __device__ __align__(1024) __half g_Kh[(size_t)BB*SS*DIN];                    // B-only
static __device__ __align__(1024) __half g_Vh[(size_t)BB*DIN*SS];                    // V^T, B-only
static __device__ __align__(1024) __half g_Ph[(size_t)BB*SS*WW*SS];                  // A, hi-only
static __device__ __align__(1024) __half g_Zh[(size_t)BB*SS*WW*DOUT];                // A, hi-only
static __device__ __align__(1024) float  g_S[(size_t)BB*SS*WW*SS];   // fp32 scores
static __device__ unsigned char g_cmask[BB*SS*WW];
static __device__ unsigned char g_words[BB*SS];
static __device__ int g_mask_mode;

// ---------------- low-level helpers ----------------
__device__ __forceinline__ uint32_t smem_u32(const void* p) {
    uint32_t a;
    asm("{ .reg .u64 t; cvta.to.shared.u64 t, %1; cvt.u32.u64 %0, t; }" : "=r"(a) : "l"(p));
    return a;
}
__device__ __forceinline__ void ldsm4(uint32_t* r, uint32_t addr) {
    asm volatile("ldmatrix.sync.aligned.m8n8.x4.shared.b16 {%0,%1,%2,%3}, [%4];\n"
        : "=r"(r[0]), "=r"(r[1]), "=r"(r[2]), "=r"(r[3]) : "r"(addr));
}
__device__ __forceinline__ void mma16816(float* c, const uint32_t* a, const uint32_t* b) {
    asm volatile(
        "mma.sync.aligned.m16n8k16.row.col.f32.f16.f16.f32 "
        "{%0,%1,%2,%3}, {%4,%5,%6,%7}, {%8,%9}, {%0,%1,%2,%3};\n"
        : "+f"(c[0]), "+f"(c[1]), "+f"(c[2]), "+f"(c[3])
        : "r"(a[0]), "r"(a[1]), "r"(a[2]), "r"(a[3]), "r"(b[0]), "r"(b[1]));
}
#define CPASYNC16(dst, src) \
    asm volatile("cp.async.cg.shared.global [%0], [%1], 16;\n" :: "r"(dst), "l"(src) : "memory")
#define CPCOMMIT() asm volatile("cp.async.commit_group;\n" ::: "memory")
#define CPWAIT1()  asm volatile("cp.async.wait_group 1;\n" ::: "memory")

__device__ __forceinline__ uint32_t pack2(__half a, __half b) {
    __half2 h = __halves2half2(a, b);
    return *(uint32_t*)&h;
}
__device__ __forceinline__ void split1(float v, __half& h, __half& l) {
    h = __float2half_rn(v);
    l = __float2half_rn(v - __half2float(h));
}

// ---------------- split-fp16 GEMM: C[M,N] = A[M,K] @ B[N,K]^T ----------------
// APL=2: acc = ah*bh + al*bh ; APL=1: acc = ah*bh (plain fp16 A).
// BM=128, BN=128, BK=32, 256 thr, 8 warps (4x2), warp tile 32x64, 3-stage, 2 CTAs/SM.
#define ROWB   80
#define PLANE  10240           /* 128 rows x 80B */
#define STAGEB 30720           /* Ah, (Al), Bh plane slots */
#define NSTAGE 3

template<int APL>
__device__ __forceinline__ void issue_chunk(uint32_t sb,
    const __half* Ah, const __half* Al, const __half* Bh,
    long long lda, long long ldb, int k0, int tid)
{
    #pragma unroll
    for (int it = 0; it < 2; it++) {              // 128 rows x 4 lines per plane
        int s = tid + it * 256, r = s >> 2, sg = s & 3;
        long long ga = (long long)r * lda + k0 + sg * 8;
        CPASYNC16(sb + r * ROWB + sg * 16, Ah + ga);
        if (APL == 2) CPASYNC16(sb + PLANE + r * ROWB + sg * 16, Al + ga);
        long long gb = (long long)r * ldb + k0 + sg * 8;
        CPASYNC16(sb + 2*PLANE + r * ROWB + sg * 16, Bh + gb);
    }
}

template<int APL>
__device__ __forceinline__ void gemm_compute(uint32_t sb, int wm, int wn, int lane, float* acc) {
    const uint32_t Ah = sb, Al = sb + PLANE, Bh = sb + 2*PLANE;
    const int mrow = (lane & 7) + ((lane >> 3) & 1) * 8, akcol = ((lane >> 4) & 1) * 8;
    const int nrow = (lane & 7) + ((lane >> 4) & 1) * 8, bkcol = ((lane >> 3) & 1) * 8;
    #pragma unroll
    for (int ks = 0; ks < 2; ks++) {
        const int k0 = ks * 16;
        uint32_t bfh[16];
        #pragma unroll
        for (int np = 0; np < 4; np++) {
            uint32_t off = (uint32_t)((wn * 64 + np * 16 + nrow) * ROWB + (k0 + bkcol) * 2);
            ldsm4(&bfh[np * 4], Bh + off);   // [N][K] k-contig == mma "col" B, non-trans
        }
        #pragma unroll
        for (int mi = 0; mi < 2; mi++) {
            uint32_t off = (uint32_t)((wm * 32 + mi * 16 + mrow) * ROWB + (k0 + akcol) * 2);
            uint32_t ah[4], al[4];
            ldsm4(ah, Ah + off);
            if (APL == 2) ldsm4(al, Al + off);
            #pragma unroll
            for (int ni = 0; ni < 8; ni++) {
                float* c = acc + (mi * 8 + ni) * 4;
                mma16816(c, ah, &bfh[ni * 2]);                 // hi*hi
                if (APL == 2) mma16816(c, al, &bfh[ni * 2]);   // lo*hi
            }
        }
    }
}

// OUT: 0 = fp32 C, 1 = fp16 planes (Ch always, Cl if non-null)
template<int OUT, int APL>
__global__ __launch_bounds__(256, 2)
void hgemm(const __half* __restrict__ Ah, const __half* __restrict__ Al,
           const __half* __restrict__ Bh,
           const float* __restrict__ colbias, const float* __restrict__ rowbias, float oscale,
           float* __restrict__ C, __half* __restrict__ Ch, __half* __restrict__ Cl,
           int K, long long lda, long long ldb, long long ldc,
           long long sAb, long long sBb, long long sCb)
{
    extern __shared__ char dsm[];
    const int tid = threadIdx.x, wid = tid >> 5, lane = tid & 31;
    const int wm = wid & 3, wn = wid >> 2;   // 4x2 warp grid, tile 32x64

    long long aoff = (long long)blockIdx.z * sAb + (long long)blockIdx.y * 128 * lda;
    long long boff = (long long)blockIdx.z * sBb + (long long)blockIdx.x * 128 * ldb;
    Ah += aoff; if (APL == 2) Al += aoff;
    Bh += boff;

    float acc[64];
    #pragma unroll
    for (int i = 0; i < 64; i++) acc[i] = 0.0f;

    const uint32_t sbase = smem_u32(dsm);
    const int NC = K >> 5;

    issue_chunk<APL>(sbase,          Ah, Al, Bh, lda, ldb, 0,  tid); CPCOMMIT();
    issue_chunk<APL>(sbase + STAGEB, Ah, Al, Bh, lda, ldb, 32, tid); CPCOMMIT();

    for (int i = 0; i < NC; i++) {
        CPWAIT1();               // >= chunk i complete (i+1 may still be in flight)
        __syncthreads();         // all warps past compute(i-1); stage (i+2)%3 free
        if (i + 2 < NC)
            issue_chunk<APL>(sbase + ((i + 2) % NSTAGE) * STAGEB, Ah, Al, Bh,
                             lda, ldb, (i + 2) * 32, tid);
        CPCOMMIT();              // unconditional: keeps pending-group invariant at tail
        gemm_compute<APL>(sbase + (i % NSTAGE) * STAGEB, wm, wn, lane, acc);
    }

    // epilogue: frag c0:(r,c) c1:(r,c+1) c2:(r+8,c) c3:(r+8,c+1)
    const long long wr = (long long)blockIdx.y * 128 + wm * 32;
    const long long wc = (long long)blockIdx.x * 128 + wn * 64;
    #pragma unroll
    for (int mi = 0; mi < 2; mi++) {
        long long r0 = wr + mi * 16 + (lane >> 2);
        float rb0 = rowbias ? rowbias[r0]     : 0.0f;
        float rb1 = rowbias ? rowbias[r0 + 8] : 0.0f;
        #pragma unroll
        for (int ni = 0; ni < 8; ni++) {
            long long c0 = wc + ni * 8 + (lane & 3) * 2;
            float cb0 = 0.0f, cb1 = 0.0f;
            if (colbias) { float2 cb = *(const float2*)(colbias + c0); cb0 = cb.x; cb1 = cb.y; }
            const float* a = acc + (mi * 8 + ni) * 4;
            float v00 = (a[0] + cb0 + rb0) * oscale, v01 = (a[1] + cb1 + rb0) * oscale;
            float v10 = (a[2] + cb0 + rb1) * oscale, v11 = (a[3] + cb1 + rb1) * oscale;
            long long o0 = ((long long)blockIdx.z * sCb) + r0 * ldc + c0;
            if (OUT == 0) {
                *(float2*)(C + o0)           = make_float2(v00, v01);
                *(float2*)(C + o0 + 8 * ldc) = make_float2(v10, v11);
            } else {
                __half h00, l00, h01, l01, h10, l10, h11, l11;
                split1(v00, h00, l00); split1(v01, h01, l01);
                split1(v10, h10, l10); split1(v11, h11, l11);
                *(uint32_t*)(Ch + o0)           = pack2(h00, h01);
                *(uint32_t*)(Ch + o0 + 8 * ldc) = pack2(h10, h11);
                if (Cl) {
                    *(uint32_t*)(Cl + o0)           = pack2(l00, l01);
                    *(uint32_t*)(Cl + o0 + 8 * ldc) = pack2(l10, l11);
                }
            }
        }
    }
}

// ---------------- fused mask+softmax: S -> P hi plane + att (transposed) ----------------
__global__ __launch_bounds__(256)
void smx_att(const float* __restrict__ S, const unsigned char* __restrict__ cmask,
             const unsigned char* __restrict__ words,
             __half* __restrict__ Ph, float* __restrict__ att)
{
    __shared__ float tile[8][521];
    __shared__ unsigned char words_s[512];
    const int b = blockIdx.y, q = blockIdx.x;
    const int tid = threadIdx.x, w = tid >> 5, lane = tid & 31;
    for (int i = tid; i < 512; i += 256) words_s[i] = words[b * 512 + i];
    __syncthreads();

    const long long base8 = ((long long)b * 512 + q) * 8;
    const float* row = S + (base8 + w) * 512;
    const bool cmb = cmask[base8 + w] != 0;

    float v[16];
    float mx = -3.0e38f;
    #pragma unroll
    for (int i = 0; i < 4; i++) {
        float4 x = *(const float4*)(row + i * 128 + lane * 4);
        float t[4] = {x.x, x.y, x.z, x.w};
        #pragma unroll
        for (int j = 0; j < 4; j++) {
            int k = i * 128 + lane * 4 + j;
            float s = t[j];                       // 1/sqrt(512) pre-folded into Qp
            s = (cmb && words_s[k]) ? s : -1e9f;
            v[i * 4 + j] = s;
            mx = fmaxf(mx, s);
        }
    }
    #pragma unroll
    for (int o = 16; o > 0; o >>= 1) mx = fmaxf(mx, __shfl_xor_sync(0xffffffffu, mx, o));
    float sum = 0.0f;
    #pragma unroll
    for (int i = 0; i < 16; i++) { float e = __expf(v[i] - mx); v[i] = e; sum += e; }
    #pragma unroll
    for (int o = 16; o > 0; o >>= 1) sum += __shfl_xor_sync(0xffffffffu, sum, o);
    const float inv = 1.0f / sum;

    #pragma unroll
    for (int i = 0; i < 4; i++) {
        float p0 = v[i*4]*inv, p1 = v[i*4+1]*inv, p2 = v[i*4+2]*inv, p3 = v[i*4+3]*inv;
        long long off = (base8 + w) * 512 + i * 128 + lane * 4;
        *(uint2*)(Ph + off) = make_uint2(
            pack2(__float2half_rn(p0), __float2half_rn(p1)),
            pack2(__float2half_rn(p2), __float2half_rn(p3)));
        int k = i * 128 + lane * 4;
        tile[w][k] = p0; tile[w][k+1] = p1; tile[w][k+2] = p2; tile[w][k+3] = p3;
    }
    if (att) {
        __syncthreads();
        float* obase = att + base8 * 512;
        #pragma unroll
        for (int it = 0; it < 16; it++) {
            int idx = tid + it * 256;
            obase[idx] = tile[idx & 7][idx >> 3];
        }
    }
}

// ---------------- input conversion ----------------
__global__ void split4_kernel(const float* __restrict__ in, __half* __restrict__ h,
                              __half* __restrict__ l, long long n4) {
    long long i = (long long)blockIdx.x * blockDim.x + threadIdx.x;
    if (i >= n4) return;
    float4 v = ((const float4*)in)[i];
    __half h0,l0,h1,l1,h2,l2,h3,l3;
    split1(v.x,h0,l0); split1(v.y,h1,l1); split1(v.z,h2,l2); split1(v.w,h3,l3);
    ((uint2*)h)[i] = make_uint2(pack2(h0,h1), pack2(h2,h3));
    ((uint2*)l)[i] = make_uint2(pack2(l0,l1), pack2(l2,l3));
}

// all 4 weight transposes in ONE launch: [R][C] fp32 -> [C][R] planes
// (lo plane written only for Wv — the only weight consumed as an A operand)
__global__ void transpose_split_all(
    const float* __restrict__ Wq, const float* __restrict__ Wk,
    const float* __restrict__ Wv, const float* __restrict__ Wz,
    __half* __restrict__ wqh, __half* __restrict__ wkh,
    __half* __restrict__ wvh, __half* __restrict__ wvl,
    __half* __restrict__ wzh)
{
    __shared__ float t[32][33];
    const int z = blockIdx.z;
    const float* in; __half *oh, *ol; int R;
    if (z == 0)      { in = Wq; oh = wqh; ol = nullptr; R = DQ; }
    else if (z == 1) { in = Wk; oh = wkh; ol = nullptr; R = DIN; }
    else if (z == 2) { in = Wv; oh = wvh; ol = wvl;     R = DIN; }
    else             { in = Wz; oh = wzh; ol = nullptr; R = DOUT; }
    const int C = 512;
    int c0 = blockIdx.x * 32, r0 = blockIdx.y * 32;
    if (r0 >= R) return;   // uniform per block
    int x = threadIdx.x, y = threadIdx.y;
    #pragma unroll
    for (int j = 0; j < 32; j += 8)
        t[y + j][x] = in[(long long)(r0 + y + j) * C + c0 + x];
    __syncthreads();
    #pragma unroll
    for (int j = 0; j < 32; j += 8) {
        float v = t[x][y + j];
        __half h, l; split1(v, h, l);
        long long o = (long long)(c0 + y + j) * R + r0 + x;
        oh[o] = h;
        if (ol) ol[o] = l;
    }
}

// ---------------- mask handling ----------------
__global__ void detect_mask_kernel(const unsigned int* __restrict__ m) {
    if (blockIdx.x == 0 && threadIdx.x == 0) {
        bool all01 = true, allf = true;
        for (int i = 0; i < 1024; i++) {
            unsigned int v = m[i];
            if (!(v == 0u || v == 1u)) all01 = false;
            if (!(v == 0u || v == 0x3F800000u)) allf = false;
        }
        g_mask_mode = all01 ? 1 : (allf ? 0 : 2);
    }
}
__global__ void normalize_mask_kernel(const void* __restrict__ m,
                                      unsigned char* __restrict__ cmask,
                                      unsigned char* __restrict__ words) {
    int idx = blockIdx.x * blockDim.x + threadIdx.x;
    if (idx >= BB * SS) return;
    int mode = g_mask_mode;
    unsigned char any = 0;
    #pragma unroll
    for (int w = 0; w < WW; w++) {
        int e = idx * WW + w;
        unsigned char v;
        if (mode == 1)      v = (((const int*)m)[e] != 0);
        else if (mode == 0) v = (((const float*)m)[e] != 0.0f);
        else                v = (((const unsigned char*)m)[e] != 0);
        cmask[e] = v;
        any |= v;
    }
    words[idx] = any;
}

// ---------------- launch ----------------
extern "C" void kernel_launch(void* const* d_in, const int* in_sizes, int n_in,
                              void* d_out, int out_size) {
    const float* query = (const float*)d_in[0];
    const float* data  = (const float*)d_in[1];
    const void*  maskr = d_in[2];
    const float* Wq = (const float*)d_in[3];
    const float* bq = (const float*)d_in[4];
    const float* Wk = (const float*)d_in[5];
    const float* bk = (const float*)d_in[6];
    const float* Wv = (const float*)d_in[7];
    const float* bv = (const float*)d_in[8];
    const float* Wz = (const float*)d_in[9];
    const float* bz = (const float*)d_in[10];

    float* out = (float*)d_out;
    const long long zs_elems  = (long long)BB * SS * WW * DOUT;
    const long long att_elems = (long long)BB * SS * SS * WW;
    float* att = ((long long)out_size >= zs_elems + att_elems) ? out + zs_elems : nullptr;

    __half *qh,*ql,*dh,*dl,*wqh,*wkh,*wvh,*wvl,*wzh;
    __half *Qh,*Kh,*Vh,*Ph,*Zh;
    float *Sp;
    unsigned char *cm, *wm;
    cudaGetSymbolAddress((void**)&qh, g_qh);  cudaGetSymbolAddress((void**)&ql, g_ql);
    cudaGetSymbolAddress((void**)&dh, g_dh);  cudaGetSymbolAddress((void**)&dl, g_dl);
    cudaGetSymbolAddress((void**)&wqh, g_wqh);
    cudaGetSymbolAddress((void**)&wkh, g_wkh);
    cudaGetSymbolAddress((void**)&wvh, g_wvh); cudaGetSymbolAddress((void**)&wvl, g_wvl);
    cudaGetSymbolAddress((void**)&wzh, g_wzh);
    cudaGetSymbolAddress((void**)&Qh, g_Qh);
    cudaGetSymbolAddress((void**)&Kh, g_Kh);
    cudaGetSymbolAddress((void**)&Vh, g_Vh);
    cudaGetSymbolAddress((void**)&Ph, g_Ph);
    cudaGetSymbolAddress((void**)&Zh, g_Zh);
    cudaGetSymbolAddress((void**)&Sp, g_S);
    cudaGetSymbolAddress((void**)&cm, g_cmask);
    cudaGetSymbolAddress((void**)&wm, g_words);

    const int SMEM = NSTAGE * STAGEB;   // 92160 -> 2 CTAs/SM (184 KB < 228 KB)
    cudaFuncSetAttribute(hgemm<0,1>, cudaFuncAttributeMaxDynamicSharedMemorySize, SMEM);
    cudaFuncSetAttribute(hgemm<1,1>, cudaFuncAttributeMaxDynamicSharedMemorySize, SMEM);
    cudaFuncSetAttribute(hgemm<1,2>, cudaFuncAttributeMaxDynamicSharedMemorySize, SMEM);

    detect_mask_kernel<<<1, 1>>>((const unsigned int*)maskr);
    normalize_mask_kernel<<<(BB * SS + 255) / 256, 256>>>(maskr, cm, wm);
    {
        long long nq4 = (long long)BB * SS * WW * DQ / 4;
        split4_kernel<<<(unsigned)((nq4 + 255) / 256), 256>>>(query, qh, ql, nq4);
        long long nd4 = (long long)BB * SS * DIN / 4;
        split4_kernel<<<(unsigned)((nd4 + 255) / 256), 256>>>(data, dh, dl, nd4);
    }
    transpose_split_all<<<dim3(16, 16, 4), dim3(32, 8)>>>(
        Wq, Wk, Wv, Wz, wqh, wkh, wvh, wvl, wzh);

    const float SCALE = 0.04419417382415922f;  // 1/sqrt(512), folded into Qp

    // Qproj -> Qh only (scaled): [65536,512]  (accurate 2-plane input, hi-only output)
    hgemm<1,2><<<dim3(4, 512, 1), 256, SMEM>>>(qh, ql, wqh, bq, nullptr, SCALE,
        nullptr, Qh, nullptr, DQ, DQ, DQ, DIN, 0, 0, 0);
    // Kproj -> Kh only: [8192,512]
    hgemm<1,2><<<dim3(4, 64, 1), 256, SMEM>>>(dh, dl, wkh, bk, nullptr, 1.0f,
        nullptr, Kh, nullptr, DIN, DIN, DIN, DIN, 0, 0, 0);
    // VT[b] hi only: [512z,512s] = wv[z,:] . data_b[s,:] + bv[z]
    hgemm<1,2><<<dim3(4, 4, BB), 256, SMEM>>>(wvh, wvl, dh, nullptr, bv, 1.0f,
        nullptr, Vh, nullptr, DIN, DIN, DIN, SS, 0, (long long)SS * DIN, (long long)DIN * SS);
    // scores[b] fp32: [4096,512] = Qh_b @ Kh_b^T  (single-plane A)
    hgemm<0,1><<<dim3(4, 32, BB), 256, SMEM>>>(Qh, nullptr, Kh, nullptr, nullptr, 1.0f,
        Sp, nullptr, nullptr, DIN, DIN, DIN, SS,
        (long long)SS * WW * DIN, (long long)SS * DIN, (long long)SS * WW * SS);
    // softmax + P hi plane + att
    smx_att<<<dim3(SS, BB), 256>>>(Sp, cm, wm, Ph, att);
    // Z1[b] hi only = P_b @ VT_b^T   (single-plane A)
    hgemm<1,1><<<dim3(4, 32, BB), 256, SMEM>>>(Ph, nullptr, Vh, nullptr, nullptr, 1.0f,
        nullptr, Zh, nullptr, SS, SS, SS, DOUT,
        (long long)SS * WW * SS, (long long)DIN * SS, (long long)SS * WW * DOUT);
    // zs = Z1 @ Wz^T + bz -> d_out fp32   (single-plane A)
    hgemm<0,1><<<dim3(4, 512, 1), 256, SMEM>>>(Zh, nullptr, wzh, bz, nullptr, 1.0f,
        out, nullptr, nullptr, DOUT, DOUT, DOUT, DOUT, 0, 0, 0);
}

// round 12
// speedup vs baseline: 2.2894x; 1.0960x over previous
#include <cuda_runtime.h>
#include <cuda_fp16.h>
#include <math.h>
#include <stdint.h>

#define BB   16
#define SS   512
#define WW   8
#define DQ   256
#define DIN  512
#define DOUT 512

// ---------------- device scratch: plain fp16 operands ----------------
static __device__ __align__(1024) __half g_qh[(size_t)BB*SS*WW*DQ];
static __device__ __align__(1024) __half g_dh[(size_t)BB*SS*DIN];
static __device__ __align__(1024) __half g_wqh[DIN*DQ];
static __device__ __align__(1024) __half g_wkh[DIN*DIN];
static __device__ __align__(1024) __half g_wvh[DOUT*DIN];
static __device__ __align__(1024) __half g_wzh[DOUT*DOUT];
static __device__ __align__(1024) __half g_Qh[(size_t)BB*SS*WW*DIN];
static __device__ __align__(1024) __half g_Kh[(size_t)BB*SS*DIN];
static __device__ __align__(1024) __half g_Vh[(size_t)BB*DIN*SS];   // V^T
static __device__ __align__(1024) __half g_Ph[(size_t)BB*SS*WW*SS];
static __device__ __align__(1024) __half g_Zh[(size_t)BB*SS*WW*DOUT];
static __device__ __align__(1024) float  g_S[(size_t)BB*SS*WW*SS];  // fp32 scores
static __device__ unsigned char g_cmask[BB*SS*WW];
static __device__ unsigned char g_words[BB*SS];
static __device__ int g_mask_mode;

// ---------------- low-level helpers ----------------
__device__ __forceinline__ uint32_t smem_u32(const void* p) {
    uint32_t a;
    asm("{ .reg .u64 t; cvta.to.shared.u64 t, %1; cvt.u32.u64 %0, t; }" : "=r"(a) : "l"(p));
    return a;
}
__device__ __forceinline__ void ldsm4(uint32_t* r, uint32_t addr) {
    asm volatile("ldmatrix.sync.aligned.m8n8.x4.shared.b16 {%0,%1,%2,%3}, [%4];\n"
        : "=r"(r[0]), "=r"(r[1]), "=r"(r[2]), "=r"(r[3]) : "r"(addr));
}
__device__ __forceinline__ void mma16816(float* c, const uint32_t* a, const uint32_t* b) {
    asm volatile(
        "mma.sync.aligned.m16n8k16.row.col.f32.f16.f16.f32 "
        "{%0,%1,%2,%3}, {%4,%5,%6,%7}, {%8,%9}, {%0,%1,%2,%3};\n"
        : "+f"(c[0]), "+f"(c[1]), "+f"(c[2]), "+f"(c[3])
        : "r"(a[0]), "r"(a[1]), "r"(a[2]), "r"(a[3]), "r"(b[0]), "r"(b[1]));
}
#define CPASYNC16(dst, src) \
    asm volatile("cp.async.cg.shared.global [%0], [%1], 16;\n" :: "r"(dst), "l"(src) : "memory")
#define CPCOMMIT() asm volatile("cp.async.commit_group;\n" ::: "memory")
#define CPWAIT1()  asm volatile("cp.async.wait_group 1;\n" ::: "memory")

__device__ __forceinline__ uint32_t pack2(__half a, __half b) {
    __half2 h = __halves2half2(a, b);
    return *(uint32_t*)&h;
}

// ---------------- fp16 HMMA GEMM: C[M,N] = A[M,K] @ B[N,K]^T ----------------
// BM=128, BN=128, BK=32, 256 thr, 8 warps (4x2), warp tile 32x64, 3-stage, 2 CTAs/SM.
#define ROWB   80
#define PLANE  10240           /* 128 rows x 80B */
#define STAGEB 20480           /* A, B plane slots */
#define NSTAGE 3

__device__ __forceinline__ void issue_chunk(uint32_t sb,
    const __half* A, const __half* B, long long lda, long long ldb, int k0, int tid)
{
    #pragma unroll
    for (int it = 0; it < 2; it++) {              // 128 rows x 4 lines per plane
        int s = tid + it * 256, r = s >> 2, sg = s & 3;
        CPASYNC16(sb + r * ROWB + sg * 16,         A + (long long)r * lda + k0 + sg * 8);
        CPASYNC16(sb + PLANE + r * ROWB + sg * 16, B + (long long)r * ldb + k0 + sg * 8);
    }
}

__device__ __forceinline__ void gemm_compute(uint32_t sb, int wm, int wn, int lane, float* acc) {
    const uint32_t As = sb, Bs = sb + PLANE;
    const int mrow = (lane & 7) + ((lane >> 3) & 1) * 8, akcol = ((lane >> 4) & 1) * 8;
    const int nrow = (lane & 7) + ((lane >> 4) & 1) * 8, bkcol = ((lane >> 3) & 1) * 8;
    #pragma unroll
    for (int ks = 0; ks < 2; ks++) {
        const int k0 = ks * 16;
        uint32_t bf[16];
        #pragma unroll
        for (int np = 0; np < 4; np++) {
            uint32_t off = (uint32_t)((wn * 64 + np * 16 + nrow) * ROWB + (k0 + bkcol) * 2);
            ldsm4(&bf[np * 4], Bs + off);   // [N][K] k-contig == mma "col" B, non-trans
        }
        #pragma unroll
        for (int mi = 0; mi < 2; mi++) {
            uint32_t off = (uint32_t)((wm * 32 + mi * 16 + mrow) * ROWB + (k0 + akcol) * 2);
            uint32_t af[4];
            ldsm4(af, As + off);
            #pragma unroll
            for (int ni = 0; ni < 8; ni++)
                mma16816(acc + (mi * 8 + ni) * 4, af, &bf[ni * 2]);
        }
    }
}

// OUT: 0 = fp32 C, 1 = fp16 Ch
template<int OUT>
__global__ __launch_bounds__(256, 2)
void hgemm(const __half* __restrict__ A, const __half* __restrict__ B,
           const float* __restrict__ colbias, const float* __restrict__ rowbias, float oscale,
           float* __restrict__ C, __half* __restrict__ Ch,
           int K, long long lda, long long ldb, long long ldc,
           long long sAb, long long sBb, long long sCb)
{
    extern __shared__ char dsm[];
    const int tid = threadIdx.x, wid = tid >> 5, lane = tid & 31;
    const int wm = wid & 3, wn = wid >> 2;   // 4x2 warp grid, tile 32x64

    A += (long long)blockIdx.z * sAb + (long long)blockIdx.y * 128 * lda;
    B += (long long)blockIdx.z * sBb + (long long)blockIdx.x * 128 * ldb;

    float acc[64];
    #pragma unroll
    for (int i = 0; i < 64; i++) acc[i] = 0.0f;

    const uint32_t sbase = smem_u32(dsm);
    const int NC = K >> 5;

    issue_chunk(sbase,          A, B, lda, ldb, 0,  tid); CPCOMMIT();
    issue_chunk(sbase + STAGEB, A, B, lda, ldb, 32, tid); CPCOMMIT();

    for (int i = 0; i < NC; i++) {
        CPWAIT1();               // >= chunk i complete
        __syncthreads();         // all warps past compute(i-1); stage (i+2)%3 free
        if (i + 2 < NC)
            issue_chunk(sbase + ((i + 2) % NSTAGE) * STAGEB, A, B, lda, ldb, (i + 2) * 32, tid);
        CPCOMMIT();              // unconditional: pending-group invariant at tail
        gemm_compute(sbase + (i % NSTAGE) * STAGEB, wm, wn, lane, acc);
    }

    // epilogue: frag c0:(r,c) c1:(r,c+1) c2:(r+8,c) c3:(r+8,c+1)
    const long long wr = (long long)blockIdx.y * 128 + wm * 32;
    const long long wc = (long long)blockIdx.x * 128 + wn * 64;
    #pragma unroll
    for (int mi = 0; mi < 2; mi++) {
        long long r0 = wr + mi * 16 + (lane >> 2);
        float rb0 = rowbias ? rowbias[r0]     : 0.0f;
        float rb1 = rowbias ? rowbias[r0 + 8] : 0.0f;
        #pragma unroll
        for (int ni = 0; ni < 8; ni++) {
            long long c0 = wc + ni * 8 + (lane & 3) * 2;
            float cb0 = 0.0f, cb1 = 0.0f;
            if (colbias) { float2 cb = *(const float2*)(colbias + c0); cb0 = cb.x; cb1 = cb.y; }
            const float* a = acc + (mi * 8 + ni) * 4;
            float v00 = (a[0] + cb0 + rb0) * oscale, v01 = (a[1] + cb1 + rb0) * oscale;
            float v10 = (a[2] + cb0 + rb1) * oscale, v11 = (a[3] + cb1 + rb1) * oscale;
            long long o0 = ((long long)blockIdx.z * sCb) + r0 * ldc + c0;
            if (OUT == 0) {
                *(float2*)(C + o0)           = make_float2(v00, v01);
                *(float2*)(C + o0 + 8 * ldc) = make_float2(v10, v11);
            } else {
                *(uint32_t*)(Ch + o0)           = pack2(__float2half_rn(v00), __float2half_rn(v01));
                *(uint32_t*)(Ch + o0 + 8 * ldc) = pack2(__float2half_rn(v10), __float2half_rn(v11));
            }
        }
    }
}

// ---------------- fused mask+softmax: S -> P fp16 + att (transposed) ----------------
__global__ __launch_bounds__(256)
void smx_att(const float* __restrict__ S, const unsigned char* __restrict__ cmask,
             const unsigned char* __restrict__ words,
             __half* __restrict__ Ph, float* __restrict__ att)
{
    __shared__ float tile[8][521];
    __shared__ unsigned char words_s[512];
    const int b = blockIdx.y, q = blockIdx.x;
    const int tid = threadIdx.x, w = tid >> 5, lane = tid & 31;
    for (int i = tid; i < 512; i += 256) words_s[i] = words[b * 512 + i];
    __syncthreads();

    const long long base8 = ((long long)b * 512 + q) * 8;
    const float* row = S + (base8 + w) * 512;
    const bool cmb = cmask[base8 + w] != 0;

    float v[16];
    float mx = -3.0e38f;
    #pragma unroll
    for (int i = 0; i < 4; i++) {
        float4 x = *(const float4*)(row + i * 128 + lane * 4);
        float t[4] = {x.x, x.y, x.z, x.w};
        #pragma unroll
        for (int j = 0; j < 4; j++) {
            int k = i * 128 + lane * 4 + j;
            float s = t[j];                       // 1/sqrt(512) pre-folded into Qp
            s = (cmb && words_s[k]) ? s : -1e9f;
            v[i * 4 + j] = s;
            mx = fmaxf(mx, s);
        }
    }
    #pragma unroll
    for (int o = 16; o > 0; o >>= 1) mx = fmaxf(mx, __shfl_xor_sync(0xffffffffu, mx, o));
    float sum = 0.0f;
    #pragma unroll
    for (int i = 0; i < 16; i++) { float e = __expf(v[i] - mx); v[i] = e; sum += e; }
    #pragma unroll
    for (int o = 16; o > 0; o >>= 1) sum += __shfl_xor_sync(0xffffffffu, sum, o);
    const float inv = 1.0f / sum;

    #pragma unroll
    for (int i = 0; i < 4; i++) {
        float p0 = v[i*4]*inv, p1 = v[i*4+1]*inv, p2 = v[i*4+2]*inv, p3 = v[i*4+3]*inv;
        long long off = (base8 + w) * 512 + i * 128 + lane * 4;
        *(uint2*)(Ph + off) = make_uint2(
            pack2(__float2half_rn(p0), __float2half_rn(p1)),
            pack2(__float2half_rn(p2), __float2half_rn(p3)));
        int k = i * 128 + lane * 4;
        tile[w][k] = p0; tile[w][k+1] = p1; tile[w][k+2] = p2; tile[w][k+3] = p3;
    }
    if (att) {
        __syncthreads();
        float* obase = att + base8 * 512;
        #pragma unroll
        for (int it = 0; it < 16; it++) {
            int idx = tid + it * 256;
            obase[idx] = tile[idx & 7][idx >> 3];
        }
    }
}

// ---------------- input conversion (fp32 -> fp16) ----------------
__global__ void convert4_kernel(const float* __restrict__ in, __half* __restrict__ h,
                                long long n4) {
    long long i = (long long)blockIdx.x * blockDim.x + threadIdx.x;
    if (i >= n4) return;
    float4 v = ((const float4*)in)[i];
    ((uint2*)h)[i] = make_uint2(
        pack2(__float2half_rn(v.x), __float2half_rn(v.y)),
        pack2(__float2half_rn(v.z), __float2half_rn(v.w)));
}

// all 4 weight transposes in ONE launch: [R][C] fp32 -> [C][R] fp16
__global__ void transpose_cast_all(
    const float* __restrict__ Wq, const float* __restrict__ Wk,
    const float* __restrict__ Wv, const float* __restrict__ Wz,
    __half* __restrict__ wqh, __half* __restrict__ wkh,
    __half* __restrict__ wvh, __half* __restrict__ wzh)
{
    __shared__ float t[32][33];
    const int z = blockIdx.z;
    const float* in; __half* oh; int R;
    if (z == 0)      { in = Wq; oh = wqh; R = DQ; }
    else if (z == 1) { in = Wk; oh = wkh; R = DIN; }
    else if (z == 2) { in = Wv; oh = wvh; R = DIN; }
    else             { in = Wz; oh = wzh; R = DOUT; }
    const int C = 512;
    int c0 = blockIdx.x * 32, r0 = blockIdx.y * 32;
    if (r0 >= R) return;   // uniform per block
    int x = threadIdx.x, y = threadIdx.y;
    #pragma unroll
    for (int j = 0; j < 32; j += 8)
        t[y + j][x] = in[(long long)(r0 + y + j) * C + c0 + x];
    __syncthreads();
    #pragma unroll
    for (int j = 0; j < 32; j += 8)
        oh[(long long)(c0 + y + j) * R + r0 + x] = __float2half_rn(t[x][y + j]);
}

// ---------------- mask handling ----------------
__global__ void detect_mask_kernel(const unsigned int* __restrict__ m) {
    if (blockIdx.x == 0 && threadIdx.x == 0) {
        bool all01 = true, allf = true;
        for (int i = 0; i < 1024; i++) {
            unsigned int v = m[i];
            if (!(v == 0u || v == 1u)) all01 = false;
            if (!(v == 0u || v == 0x3F800000u)) allf = false;
        }
        g_mask_mode = all01 ? 1 : (allf ? 0 : 2);
    }
}
__global__ void normalize_mask_kernel(const void* __restrict__ m,
                                      unsigned char* __restrict__ cmask,
                                      unsigned char* __restrict__ words) {
    int idx = blockIdx.x * blockDim.x + threadIdx.x;
    if (idx >= BB * SS) return;
    int mode = g_mask_mode;
    unsigned char any = 0;
    #pragma unroll
    for (int w = 0; w < WW; w++) {
        int e = idx * WW + w;
        unsigned char v;
        if (mode == 1)      v = (((const int*)m)[e] != 0);
        else if (mode == 0) v = (((const float*)m)[e] != 0.0f);
        else                v = (((const unsigned char*)m)[e] != 0);
        cmask[e] = v;
        any |= v;
    }
    words[idx] = any;
}

// ---------------- launch ----------------
extern "C" void kernel_launch(void* const* d_in, const int* in_sizes, int n_in,
                              void* d_out, int out_size) {
    const float* query = (const float*)d_in[0];
    const float* data  = (const float*)d_in[1];
    const void*  maskr = d_in[2];
    const float* Wq = (const float*)d_in[3];
    const float* bq = (const float*)d_in[4];
    const float* Wk = (const float*)d_in[5];
    const float* bk = (const float*)d_in[6];
    const float* Wv = (const float*)d_in[7];
    const float* bv = (const float*)d_in[8];
    const float* Wz = (const float*)d_in[9];
    const float* bz = (const float*)d_in[10];

    float* out = (float*)d_out;
    const long long zs_elems  = (long long)BB * SS * WW * DOUT;
    const long long att_elems = (long long)BB * SS * SS * WW;
    float* att = ((long long)out_size >= zs_elems + att_elems) ? out + zs_elems : nullptr;

    __half *qh,*dh,*wqh,*wkh,*wvh,*wzh,*Qh,*Kh,*Vh,*Ph,*Zh;
    float *Sp;
    unsigned char *cm, *wm;
    cudaGetSymbolAddress((void**)&qh, g_qh);
    cudaGetSymbolAddress((void**)&dh, g_dh);
    cudaGetSymbolAddress((void**)&wqh, g_wqh);
    cudaGetSymbolAddress((void**)&wkh, g_wkh);
    cudaGetSymbolAddress((void**)&wvh, g_wvh);
    cudaGetSymbolAddress((void**)&wzh, g_wzh);
    cudaGetSymbolAddress((void**)&Qh, g_Qh);
    cudaGetSymbolAddress((void**)&Kh, g_Kh);
    cudaGetSymbolAddress((void**)&Vh, g_Vh);
    cudaGetSymbolAddress((void**)&Ph, g_Ph);
    cudaGetSymbolAddress((void**)&Zh, g_Zh);
    cudaGetSymbolAddress((void**)&Sp, g_S);
    cudaGetSymbolAddress((void**)&cm, g_cmask);
    cudaGetSymbolAddress((void**)&wm, g_words);

    const int SMEM = NSTAGE * STAGEB;   // 61440 -> 2 CTAs/SM
    cudaFuncSetAttribute(hgemm<0>, cudaFuncAttributeMaxDynamicSharedMemorySize, SMEM);
    cudaFuncSetAttribute(hgemm<1>, cudaFuncAttributeMaxDynamicSharedMemorySize, SMEM);

    detect_mask_kernel<<<1, 1>>>((const unsigned int*)maskr);
    normalize_mask_kernel<<<(BB * SS + 255) / 256, 256>>>(maskr, cm, wm);
    {
        long long nq4 = (long long)BB * SS * WW * DQ / 4;
        convert4_kernel<<<(unsigned)((nq4 + 255) / 256), 256>>>(query, qh, nq4);
        long long nd4 = (long long)BB * SS * DIN / 4;
        convert4_kernel<<<(unsigned)((nd4 + 255) / 256), 256>>>(data, dh, nd4);
    }
    transpose_cast_all<<<dim3(16, 16, 4), dim3(32, 8)>>>(
        Wq, Wk, Wv, Wz, wqh, wkh, wvh, wzh);

    const float SCALE = 0.04419417382415922f;  // 1/sqrt(512), folded into Qp

    // Qproj -> Qh (scaled): [65536,512]
    hgemm<1><<<dim3(4, 512, 1), 256, SMEM>>>(qh, wqh, bq, nullptr, SCALE,
        nullptr, Qh, DQ, DQ, DQ, DIN, 0, 0, 0);
    // Kproj -> Kh: [8192,512]
    hgemm<1><<<dim3(4, 64, 1), 256, SMEM>>>(dh, wkh, bk, nullptr, 1.0f,
        nullptr, Kh, DIN, DIN, DIN, DIN, 0, 0, 0);
    // VT[b]: [512z,512s] = wv[z,:] . data_b[s,:] + bv[z]
    hgemm<1><<<dim3(4, 4, BB), 256, SMEM>>>(wvh, dh, nullptr, bv, 1.0f,
        nullptr, Vh, DIN, DIN, DIN, SS, 0, (long long)SS * DIN, (long long)DIN * SS);
    // scores[b] fp32: [4096,512] = Qh_b @ Kh_b^T
    hgemm<0><<<dim3(4, 32, BB), 256, SMEM>>>(Qh, Kh, nullptr, nullptr, 1.0f,
        Sp, nullptr, DIN, DIN, DIN, SS,
        (long long)SS * WW * DIN, (long long)SS * DIN, (long long)SS * WW * SS);
    // softmax + P fp16 + att
    smx_att<<<dim3(SS, BB), 256>>>(Sp, cm, wm, Ph, att);
    // Z1[b] = P_b @ VT_b^T
    hgemm<1><<<dim3(4, 32, BB), 256, SMEM>>>(Ph, Vh, nullptr, nullptr, 1.0f,
        nullptr, Zh, SS, SS, SS, DOUT,
        (long long)SS * WW * SS, (long long)DIN * SS, (long long)SS * WW * DOUT);
    // zs = Z1 @ Wz^T + bz -> d_out fp32
    hgemm<0><<<dim3(4, 512, 1), 256, SMEM>>>(Zh, wzh, bz, nullptr, 1.0f,
        out, nullptr, DOUT, DOUT, DOUT, DOUT, 0, 0, 0);
}

// round 13
// speedup vs baseline: 2.8273x; 1.2349x over previous
#include <cuda_runtime.h>
#include <cuda_fp16.h>
#include <math.h>
#include <stdint.h>

#define BB   16
#define SS   512
#define WW   8
#define DQ   256
#define DIN  512
#define DOUT 512

// ---------------- device scratch: plain fp16 operands ----------------
static __device__ __align__(1024) __half g_qh[(size_t)BB*SS*WW*DQ];
static __device__ __align__(1024) __half g_dh[(size_t)BB*SS*DIN];
static __device__ __align__(1024) __half g_wqh[DIN*DQ];
static __device__ __align__(1024) __half g_wkh[DIN*DIN];
static __device__ __align__(1024) __half g_wvh[DOUT*DIN];
static __device__ __align__(1024) __half g_wzh[DOUT*DOUT];
static __device__ __align__(1024) __half g_Qh[(size_t)BB*SS*WW*DIN];
static __device__ __align__(1024) __half g_Kh[(size_t)BB*SS*DIN];
static __device__ __align__(1024) __half g_Vh[(size_t)BB*SS*DIN];    // V [b,s,d]
static __device__ __align__(1024) __half g_UTh[(size_t)BB*DOUT*SS];  // (V@Wz)^T per batch [z][s]
static __device__ __align__(1024) __half g_Ph[(size_t)BB*SS*WW*SS];
static __device__ __align__(1024) float  g_S[(size_t)BB*SS*WW*SS];   // fp32 scores
static __device__ unsigned char g_cmask[BB*SS*WW];
static __device__ unsigned char g_words[BB*SS];
static __device__ int g_mask_mode;

// ---------------- low-level helpers ----------------
__device__ __forceinline__ uint32_t smem_u32(const void* p) {
    uint32_t a;
    asm("{ .reg .u64 t; cvta.to.shared.u64 t, %1; cvt.u32.u64 %0, t; }" : "=r"(a) : "l"(p));
    return a;
}
__device__ __forceinline__ void ldsm4(uint32_t* r, uint32_t addr) {
    asm volatile("ldmatrix.sync.aligned.m8n8.x4.shared.b16 {%0,%1,%2,%3}, [%4];\n"
        : "=r"(r[0]), "=r"(r[1]), "=r"(r[2]), "=r"(r[3]) : "r"(addr));
}
__device__ __forceinline__ void mma16816(float* c, const uint32_t* a, const uint32_t* b) {
    asm volatile(
        "mma.sync.aligned.m16n8k16.row.col.f32.f16.f16.f32 "
        "{%0,%1,%2,%3}, {%4,%5,%6,%7}, {%8,%9}, {%0,%1,%2,%3};\n"
        : "+f"(c[0]), "+f"(c[1]), "+f"(c[2]), "+f"(c[3])
        : "r"(a[0]), "r"(a[1]), "r"(a[2]), "r"(a[3]), "r"(b[0]), "r"(b[1]));
}
#define CPASYNC16(dst, src) \
    asm volatile("cp.async.cg.shared.global [%0], [%1], 16;\n" :: "r"(dst), "l"(src) : "memory")
#define CPCOMMIT() asm volatile("cp.async.commit_group;\n" ::: "memory")
#define CPWAIT1()  asm volatile("cp.async.wait_group 1;\n" ::: "memory")

__device__ __forceinline__ uint32_t pack2(__half a, __half b) {
    __half2 h = __halves2half2(a, b);
    return *(uint32_t*)&h;
}

// ---------------- fp16 HMMA GEMM: C[M,N] = A[M,K] @ B[N,K]^T ----------------
// BM=128, BN=128, BK=32, 256 thr, 8 warps (4x2), warp tile 32x64, 3-stage, 2 CTAs/SM.
#define ROWB   80
#define PLANE  10240           /* 128 rows x 80B */
#define STAGEB 20480           /* A, B plane slots */
#define NSTAGE 3

__device__ __forceinline__ void issue_chunk(uint32_t sb,
    const __half* A, const __half* B, long long lda, long long ldb, int k0, int tid)
{
    #pragma unroll
    for (int it = 0; it < 2; it++) {              // 128 rows x 4 lines per plane
        int s = tid + it * 256, r = s >> 2, sg = s & 3;
        CPASYNC16(sb + r * ROWB + sg * 16,         A + (long long)r * lda + k0 + sg * 8);
        CPASYNC16(sb + PLANE + r * ROWB + sg * 16, B + (long long)r * ldb + k0 + sg * 8);
    }
}

__device__ __forceinline__ void gemm_compute(uint32_t sb, int wm, int wn, int lane, float* acc) {
    const uint32_t As = sb, Bs = sb + PLANE;
    const int mrow = (lane & 7) + ((lane >> 3) & 1) * 8, akcol = ((lane >> 4) & 1) * 8;
    const int nrow = (lane & 7) + ((lane >> 4) & 1) * 8, bkcol = ((lane >> 3) & 1) * 8;
    #pragma unroll
    for (int ks = 0; ks < 2; ks++) {
        const int k0 = ks * 16;
        uint32_t bf[16];
        #pragma unroll
        for (int np = 0; np < 4; np++) {
            uint32_t off = (uint32_t)((wn * 64 + np * 16 + nrow) * ROWB + (k0 + bkcol) * 2);
            ldsm4(&bf[np * 4], Bs + off);   // [N][K] k-contig == mma "col" B, non-trans
        }
        #pragma unroll
        for (int mi = 0; mi < 2; mi++) {
            uint32_t off = (uint32_t)((wm * 32 + mi * 16 + mrow) * ROWB + (k0 + akcol) * 2);
            uint32_t af[4];
            ldsm4(af, As + off);
            #pragma unroll
            for (int ni = 0; ni < 8; ni++)
                mma16816(acc + (mi * 8 + ni) * 4, af, &bf[ni * 2]);
        }
    }
}

// OUT: 0 = fp32 C, 1 = fp16 Ch
template<int OUT>
__global__ __launch_bounds__(256, 2)
void hgemm(const __half* __restrict__ A, const __half* __restrict__ B,
           const float* __restrict__ colbias, float oscale,
           float* __restrict__ C, __half* __restrict__ Ch,
           int K, long long lda, long long ldb, long long ldc,
           long long sAb, long long sBb, long long sCb)
{
    extern __shared__ char dsm[];
    const int tid = threadIdx.x, wid = tid >> 5, lane = tid & 31;
    const int wm = wid & 3, wn = wid >> 2;   // 4x2 warp grid, tile 32x64

    A += (long long)blockIdx.z * sAb + (long long)blockIdx.y * 128 * lda;
    B += (long long)blockIdx.z * sBb + (long long)blockIdx.x * 128 * ldb;

    float acc[64];
    #pragma unroll
    for (int i = 0; i < 64; i++) acc[i] = 0.0f;

    const uint32_t sbase = smem_u32(dsm);
    const int NC = K >> 5;

    issue_chunk(sbase,          A, B, lda, ldb, 0,  tid); CPCOMMIT();
    issue_chunk(sbase + STAGEB, A, B, lda, ldb, 32, tid); CPCOMMIT();

    for (int i = 0; i < NC; i++) {
        CPWAIT1();               // >= chunk i complete
        __syncthreads();         // all warps past compute(i-1); stage (i+2)%3 free
        if (i + 2 < NC)
            issue_chunk(sbase + ((i + 2) % NSTAGE) * STAGEB, A, B, lda, ldb, (i + 2) * 32, tid);
        CPCOMMIT();              // unconditional: pending-group invariant at tail
        gemm_compute(sbase + (i % NSTAGE) * STAGEB, wm, wn, lane, acc);
    }

    // epilogue: frag c0:(r,c) c1:(r,c+1) c2:(r+8,c) c3:(r+8,c+1)
    const long long wr = (long long)blockIdx.y * 128 + wm * 32;
    const long long wc = (long long)blockIdx.x * 128 + wn * 64;
    #pragma unroll
    for (int mi = 0; mi < 2; mi++) {
        long long r0 = wr + mi * 16 + (lane >> 2);
        #pragma unroll
        for (int ni = 0; ni < 8; ni++) {
            long long c0 = wc + ni * 8 + (lane & 3) * 2;
            float cb0 = 0.0f, cb1 = 0.0f;
            if (colbias) { float2 cb = *(const float2*)(colbias + c0); cb0 = cb.x; cb1 = cb.y; }
            const float* a = acc + (mi * 8 + ni) * 4;
            float v00 = (a[0] + cb0) * oscale, v01 = (a[1] + cb1) * oscale;
            float v10 = (a[2] + cb0) * oscale, v11 = (a[3] + cb1) * oscale;
            long long o0 = ((long long)blockIdx.z * sCb) + r0 * ldc + c0;
            if (OUT == 0) {
                *(float2*)(C + o0)           = make_float2(v00, v01);
                *(float2*)(C + o0 + 8 * ldc) = make_float2(v10, v11);
            } else {
                *(uint32_t*)(Ch + o0)           = pack2(__float2half_rn(v00), __float2half_rn(v01));
                *(uint32_t*)(Ch + o0 + 8 * ldc) = pack2(__float2half_rn(v10), __float2half_rn(v11));
            }
        }
    }
}

// ---------------- fused mask+softmax: S -> P fp16 + att (transposed) ----------------
__global__ __launch_bounds__(256)
void smx_att(const float* __restrict__ S, const unsigned char* __restrict__ cmask,
             const unsigned char* __restrict__ words,
             __half* __restrict__ Ph, float* __restrict__ att)
{
    __shared__ float tile[8][521];
    __shared__ unsigned char words_s[512];
    const int b = blockIdx.y, q = blockIdx.x;
    const int tid = threadIdx.x, w = tid >> 5, lane = tid & 31;
    for (int i = tid; i < 512; i += 256) words_s[i] = words[b * 512 + i];
    __syncthreads();

    const long long base8 = ((long long)b * 512 + q) * 8;
    const float* row = S + (base8 + w) * 512;
    const bool cmb = cmask[base8 + w] != 0;

    float v[16];
    float mx = -3.0e38f;
    #pragma unroll
    for (int i = 0; i < 4; i++) {
        float4 x = *(const float4*)(row + i * 128 + lane * 4);
        float t[4] = {x.x, x.y, x.z, x.w};
        #pragma unroll
        for (int j = 0; j < 4; j++) {
            int k = i * 128 + lane * 4 + j;
            float s = t[j];                       // 1/sqrt(512) pre-folded into Qp
            s = (cmb && words_s[k]) ? s : -1e9f;
            v[i * 4 + j] = s;
            mx = fmaxf(mx, s);
        }
    }
    #pragma unroll
    for (int o = 16; o > 0; o >>= 1) mx = fmaxf(mx, __shfl_xor_sync(0xffffffffu, mx, o));
    float sum = 0.0f;
    #pragma unroll
    for (int i = 0; i < 16; i++) { float e = __expf(v[i] - mx); v[i] = e; sum += e; }
    #pragma unroll
    for (int o = 16; o > 0; o >>= 1) sum += __shfl_xor_sync(0xffffffffu, sum, o);
    const float inv = 1.0f / sum;

    #pragma unroll
    for (int i = 0; i < 4; i++) {
        float p0 = v[i*4]*inv, p1 = v[i*4+1]*inv, p2 = v[i*4+2]*inv, p3 = v[i*4+3]*inv;
        long long off = (base8 + w) * 512 + i * 128 + lane * 4;
        *(uint2*)(Ph + off) = make_uint2(
            pack2(__float2half_rn(p0), __float2half_rn(p1)),
            pack2(__float2half_rn(p2), __float2half_rn(p3)));
        int k = i * 128 + lane * 4;
        tile[w][k] = p0; tile[w][k+1] = p1; tile[w][k+2] = p2; tile[w][k+3] = p3;
    }
    if (att) {
        __syncthreads();
        float* obase = att + base8 * 512;
        #pragma unroll
        for (int it = 0; it < 16; it++) {
            int idx = tid + it * 256;
            obase[idx] = tile[idx & 7][idx >> 3];
        }
    }
}

// ---------------- input conversion (fp32 -> fp16) ----------------
__global__ void convert4_kernel(const float* __restrict__ in, __half* __restrict__ h,
                                long long n4) {
    long long i = (long long)blockIdx.x * blockDim.x + threadIdx.x;
    if (i >= n4) return;
    float4 v = ((const float4*)in)[i];
    ((uint2*)h)[i] = make_uint2(
        pack2(__float2half_rn(v.x), __float2half_rn(v.y)),
        pack2(__float2half_rn(v.z), __float2half_rn(v.w)));
}

// all 4 weight transposes in ONE launch: [R][C] fp32 -> [C][R] fp16
__global__ void transpose_cast_all(
    const float* __restrict__ Wq, const float* __restrict__ Wk,
    const float* __restrict__ Wv, const float* __restrict__ Wz,
    __half* __restrict__ wqh, __half* __restrict__ wkh,
    __half* __restrict__ wvh, __half* __restrict__ wzh)
{
    __shared__ float t[32][33];
    const int z = blockIdx.z;
    const float* in; __half* oh; int R;
    if (z == 0)      { in = Wq; oh = wqh; R = DQ; }
    else if (z == 1) { in = Wk; oh = wkh; R = DIN; }
    else if (z == 2) { in = Wv; oh = wvh; R = DIN; }
    else             { in = Wz; oh = wzh; R = DOUT; }
    const int C = 512;
    int c0 = blockIdx.x * 32, r0 = blockIdx.y * 32;
    if (r0 >= R) return;   // uniform per block
    int x = threadIdx.x, y = threadIdx.y;
    #pragma unroll
    for (int j = 0; j < 32; j += 8)
        t[y + j][x] = in[(long long)(r0 + y + j) * C + c0 + x];
    __syncthreads();
    #pragma unroll
    for (int j = 0; j < 32; j += 8)
        oh[(long long)(c0 + y + j) * R + r0 + x] = __float2half_rn(t[x][y + j]);
}

// ---------------- mask handling ----------------
__global__ void detect_mask_kernel(const unsigned int* __restrict__ m) {
    if (blockIdx.x == 0 && threadIdx.x == 0) {
        bool all01 = true, allf = true;
        for (int i = 0; i < 1024; i++) {
            unsigned int v = m[i];
            if (!(v == 0u || v == 1u)) all01 = false;
            if (!(v == 0u || v == 0x3F800000u)) allf = false;
        }
        g_mask_mode = all01 ? 1 : (allf ? 0 : 2);
    }
}
__global__ void normalize_mask_kernel(const void* __restrict__ m,
                                      unsigned char* __restrict__ cmask,
                                      unsigned char* __restrict__ words) {
    int idx = blockIdx.x * blockDim.x + threadIdx.x;
    if (idx >= BB * SS) return;
    int mode = g_mask_mode;
    unsigned char any = 0;
    #pragma unroll
    for (int w = 0; w < WW; w++) {
        int e = idx * WW + w;
        unsigned char v;
        if (mode == 1)      v = (((const int*)m)[e] != 0);
        else if (mode == 0) v = (((const float*)m)[e] != 0.0f);
        else                v = (((const unsigned char*)m)[e] != 0);
        cmask[e] = v;
        any |= v;
    }
    words[idx] = any;
}

// ---------------- launch ----------------
extern "C" void kernel_launch(void* const* d_in, const int* in_sizes, int n_in,
                              void* d_out, int out_size) {
    const float* query = (const float*)d_in[0];
    const float* data  = (const float*)d_in[1];
    const void*  maskr = d_in[2];
    const float* Wq = (const float*)d_in[3];
    const float* bq = (const float*)d_in[4];
    const float* Wk = (const float*)d_in[5];
    const float* bk = (const float*)d_in[6];
    const float* Wv = (const float*)d_in[7];
    const float* bv = (const float*)d_in[8];
    const float* Wz = (const float*)d_in[9];
    const float* bz = (const float*)d_in[10];

    float* out = (float*)d_out;
    const long long zs_elems  = (long long)BB * SS * WW * DOUT;
    const long long att_elems = (long long)BB * SS * SS * WW;
    float* att = ((long long)out_size >= zs_elems + att_elems) ? out + zs_elems : nullptr;

    __half *qh,*dh,*wqh,*wkh,*wvh,*wzh,*Qh,*Kh,*Vh,*UTh,*Ph;
    float *Sp;
    unsigned char *cm, *wm;
    cudaGetSymbolAddress((void**)&qh, g_qh);
    cudaGetSymbolAddress((void**)&dh, g_dh);
    cudaGetSymbolAddress((void**)&wqh, g_wqh);
    cudaGetSymbolAddress((void**)&wkh, g_wkh);
    cudaGetSymbolAddress((void**)&wvh, g_wvh);
    cudaGetSymbolAddress((void**)&wzh, g_wzh);
    cudaGetSymbolAddress((void**)&Qh, g_Qh);
    cudaGetSymbolAddress((void**)&Kh, g_Kh);
    cudaGetSymbolAddress((void**)&Vh, g_Vh);
    cudaGetSymbolAddress((void**)&UTh, g_UTh);
    cudaGetSymbolAddress((void**)&Ph, g_Ph);
    cudaGetSymbolAddress((void**)&Sp, g_S);
    cudaGetSymbolAddress((void**)&cm, g_cmask);
    cudaGetSymbolAddress((void**)&wm, g_words);

    const int SMEM = NSTAGE * STAGEB;   // 61440 -> 2 CTAs/SM
    cudaFuncSetAttribute(hgemm<0>, cudaFuncAttributeMaxDynamicSharedMemorySize, SMEM);
    cudaFuncSetAttribute(hgemm<1>, cudaFuncAttributeMaxDynamicSharedMemorySize, SMEM);

    detect_mask_kernel<<<1, 1>>>((const unsigned int*)maskr);
    normalize_mask_kernel<<<(BB * SS + 255) / 256, 256>>>(maskr, cm, wm);
    {
        long long nq4 = (long long)BB * SS * WW * DQ / 4;
        convert4_kernel<<<(unsigned)((nq4 + 255) / 256), 256>>>(query, qh, nq4);
        long long nd4 = (long long)BB * SS * DIN / 4;
        convert4_kernel<<<(unsigned)((nd4 + 255) / 256), 256>>>(data, dh, nd4);
    }
    transpose_cast_all<<<dim3(16, 16, 4), dim3(32, 8)>>>(
        Wq, Wk, Wv, Wz, wqh, wkh, wvh, wzh);

    const float SCALE = 0.04419417382415922f;  // 1/sqrt(512), folded into Qp

    // Qproj -> Qh (scaled): [65536,512]
    hgemm<1><<<dim3(4, 512, 1), 256, SMEM>>>(qh, wqh, bq, SCALE,
        nullptr, Qh, DQ, DQ, DQ, DIN, 0, 0, 0);
    // Kproj -> Kh: [8192,512]
    hgemm<1><<<dim3(4, 64, 1), 256, SMEM>>>(dh, wkh, bk, 1.0f,
        nullptr, Kh, DIN, DIN, DIN, DIN, 0, 0, 0);
    // Vproj -> Vh: [8192,512] = data @ Wv^T + bv
    hgemm<1><<<dim3(4, 64, 1), 256, SMEM>>>(dh, wvh, bv, 1.0f,
        nullptr, Vh, DIN, DIN, DIN, DIN, 0, 0, 0);
    // UT[b] = Wz^T @ V_b^T : [512z,512s] per batch  (U = V @ Wz)
    hgemm<1><<<dim3(4, 4, BB), 256, SMEM>>>(wzh, Vh, nullptr, 1.0f,
        nullptr, UTh, DIN, DIN, DIN, SS, 0, (long long)SS * DIN, (long long)DOUT * SS);
    // scores[b] fp32: [4096,512] = Qh_b @ Kh_b^T
    hgemm<0><<<dim3(4, 32, BB), 256, SMEM>>>(Qh, Kh, nullptr, 1.0f,
        Sp, nullptr, DIN, DIN, DIN, SS,
        (long long)SS * WW * DIN, (long long)SS * DIN, (long long)SS * WW * SS);
    // softmax + P fp16 + att
    smx_att<<<dim3(SS, BB), 256>>>(Sp, cm, wm, Ph, att);
    // zs = P @ UT^T + bz -> d_out fp32   (= att @ (V@Wz) + bz)
    hgemm<0><<<dim3(4, 32, BB), 256, SMEM>>>(Ph, UTh, bz, 1.0f,
        out, nullptr, SS, SS, SS, DOUT,
        (long long)SS * WW * SS, (long long)DOUT * SS, (long long)SS * WW * DOUT);
}

// round 14
// speedup vs baseline: 2.9021x; 1.0265x over previous
#include <cuda_runtime.h>
#include <cuda_fp16.h>
#include <math.h>
#include <stdint.h>

#define BB   16
#define SS   512
#define WW   8
#define DQ   256
#define DIN  512
#define DOUT 512

// ---------------- device scratch: plain fp16 operands ----------------
static __device__ __align__(1024) __half g_qh[(size_t)BB*SS*WW*DQ];
static __device__ __align__(1024) __half g_dh[(size_t)BB*SS*DIN];
static __device__ __align__(1024) __half g_wqh[DIN*DQ];
static __device__ __align__(1024) __half g_wkvh[2*DIN*DIN];           // concat [Wk^T; Wv^T] rows
static __device__ __align__(1024) __half g_wzh[DOUT*DOUT];
static __device__ __align__(1024) float  g_bkv[2*DIN];                // concat(bk, bv)
static __device__ __align__(1024) __half g_Qh[(size_t)BB*SS*WW*DIN];
static __device__ __align__(1024) __half g_KV[(size_t)BB*SS*2*DIN];   // [s][K|V] interleaved
static __device__ __align__(1024) __half g_UTh[(size_t)BB*DOUT*SS];   // (V@Wz)^T per batch [z][s]
static __device__ __align__(1024) __half g_Ph[(size_t)BB*SS*WW*SS];
static __device__ __align__(1024) __half g_Sh[(size_t)BB*SS*WW*SS];   // fp16 scores
static __device__ unsigned char g_cmask[BB*SS*WW];
static __device__ unsigned char g_words[BB*SS];
static __device__ int g_mask_mode;

// ---------------- low-level helpers ----------------
__device__ __forceinline__ uint32_t smem_u32(const void* p) {
    uint32_t a;
    asm("{ .reg .u64 t; cvta.to.shared.u64 t, %1; cvt.u32.u64 %0, t; }" : "=r"(a) : "l"(p));
    return a;
}
__device__ __forceinline__ void ldsm4(uint32_t* r, uint32_t addr) {
    asm volatile("ldmatrix.sync.aligned.m8n8.x4.shared.b16 {%0,%1,%2,%3}, [%4];\n"
        : "=r"(r[0]), "=r"(r[1]), "=r"(r[2]), "=r"(r[3]) : "r"(addr));
}
__device__ __forceinline__ void mma16816(float* c, const uint32_t* a, const uint32_t* b) {
    asm volatile(
        "mma.sync.aligned.m16n8k16.row.col.f32.f16.f16.f32 "
        "{%0,%1,%2,%3}, {%4,%5,%6,%7}, {%8,%9}, {%0,%1,%2,%3};\n"
        : "+f"(c[0]), "+f"(c[1]), "+f"(c[2]), "+f"(c[3])
        : "r"(a[0]), "r"(a[1]), "r"(a[2]), "r"(a[3]), "r"(b[0]), "r"(b[1]));
}
#define CPASYNC16(dst, src) \
    asm volatile("cp.async.cg.shared.global [%0], [%1], 16;\n" :: "r"(dst), "l"(src) : "memory")
#define CPCOMMIT() asm volatile("cp.async.commit_group;\n" ::: "memory")
#define CPWAIT1()  asm volatile("cp.async.wait_group 1;\n" ::: "memory")

__device__ __forceinline__ uint32_t pack2(__half a, __half b) {
    __half2 h = __halves2half2(a, b);
    return *(uint32_t*)&h;
}

// ---------------- fp16 HMMA GEMM: C[M,N] = A[M,K] @ B[N,K]^T ----------------
// BM=128, BN=128, BK=32, 256 thr, 8 warps (4x2), warp tile 32x64, 3-stage, 2 CTAs/SM.
#define ROWB   80
#define PLANE  10240           /* 128 rows x 80B */
#define STAGEB 20480           /* A, B plane slots */
#define NSTAGE 3

__device__ __forceinline__ void issue_chunk(uint32_t sb,
    const __half* A, const __half* B, long long lda, long long ldb, int k0, int tid)
{
    #pragma unroll
    for (int it = 0; it < 2; it++) {              // 128 rows x 4 lines per plane
        int s = tid + it * 256, r = s >> 2, sg = s & 3;
        CPASYNC16(sb + r * ROWB + sg * 16,         A + (long long)r * lda + k0 + sg * 8);
        CPASYNC16(sb + PLANE + r * ROWB + sg * 16, B + (long long)r * ldb + k0 + sg * 8);
    }
}

__device__ __forceinline__ void gemm_compute(uint32_t sb, int wm, int wn, int lane, float* acc) {
    const uint32_t As = sb, Bs = sb + PLANE;
    const int mrow = (lane & 7) + ((lane >> 3) & 1) * 8, akcol = ((lane >> 4) & 1) * 8;
    const int nrow = (lane & 7) + ((lane >> 4) & 1) * 8, bkcol = ((lane >> 3) & 1) * 8;
    #pragma unroll
    for (int ks = 0; ks < 2; ks++) {
        const int k0 = ks * 16;
        uint32_t bf[16];
        #pragma unroll
        for (int np = 0; np < 4; np++) {
            uint32_t off = (uint32_t)((wn * 64 + np * 16 + nrow) * ROWB + (k0 + bkcol) * 2);
            ldsm4(&bf[np * 4], Bs + off);   // [N][K] k-contig == mma "col" B, non-trans
        }
        #pragma unroll
        for (int mi = 0; mi < 2; mi++) {
            uint32_t off = (uint32_t)((wm * 32 + mi * 16 + mrow) * ROWB + (k0 + akcol) * 2);
            uint32_t af[4];
            ldsm4(af, As + off);
            #pragma unroll
            for (int ni = 0; ni < 8; ni++)
                mma16816(acc + (mi * 8 + ni) * 4, af, &bf[ni * 2]);
        }
    }
}

// OUT: 0 = fp32 C, 1 = fp16 Ch
template<int OUT>
__global__ __launch_bounds__(256, 2)
void hgemm(const __half* __restrict__ A, const __half* __restrict__ B,
           const float* __restrict__ colbias, float oscale,
           float* __restrict__ C, __half* __restrict__ Ch,
           int K, long long lda, long long ldb, long long ldc,
           long long sAb, long long sBb, long long sCb)
{
    extern __shared__ char dsm[];
    const int tid = threadIdx.x, wid = tid >> 5, lane = tid & 31;
    const int wm = wid & 3, wn = wid >> 2;   // 4x2 warp grid, tile 32x64

    A += (long long)blockIdx.z * sAb + (long long)blockIdx.y * 128 * lda;
    B += (long long)blockIdx.z * sBb + (long long)blockIdx.x * 128 * ldb;

    float acc[64];
    #pragma unroll
    for (int i = 0; i < 64; i++) acc[i] = 0.0f;

    const uint32_t sbase = smem_u32(dsm);
    const int NC = K >> 5;

    issue_chunk(sbase,          A, B, lda, ldb, 0,  tid); CPCOMMIT();
    issue_chunk(sbase + STAGEB, A, B, lda, ldb, 32, tid); CPCOMMIT();

    for (int i = 0; i < NC; i++) {
        CPWAIT1();               // >= chunk i complete
        __syncthreads();         // all warps past compute(i-1); stage (i+2)%3 free
        if (i + 2 < NC)
            issue_chunk(sbase + ((i + 2) % NSTAGE) * STAGEB, A, B, lda, ldb, (i + 2) * 32, tid);
        CPCOMMIT();              // unconditional: pending-group invariant at tail
        gemm_compute(sbase + (i % NSTAGE) * STAGEB, wm, wn, lane, acc);
    }

    // epilogue: frag c0:(r,c) c1:(r,c+1) c2:(r+8,c) c3:(r+8,c+1)
    const long long wr = (long long)blockIdx.y * 128 + wm * 32;
    const long long wc = (long long)blockIdx.x * 128 + wn * 64;
    #pragma unroll
    for (int mi = 0; mi < 2; mi++) {
        long long r0 = wr + mi * 16 + (lane >> 2);
        #pragma unroll
        for (int ni = 0; ni < 8; ni++) {
            long long c0 = wc + ni * 8 + (lane & 3) * 2;
            float cb0 = 0.0f, cb1 = 0.0f;
            if (colbias) { float2 cb = *(const float2*)(colbias + c0); cb0 = cb.x; cb1 = cb.y; }
            const float* a = acc + (mi * 8 + ni) * 4;
            float v00 = (a[0] + cb0) * oscale, v01 = (a[1] + cb1) * oscale;
            float v10 = (a[2] + cb0) * oscale, v11 = (a[3] + cb1) * oscale;
            long long o0 = ((long long)blockIdx.z * sCb) + r0 * ldc + c0;
            if (OUT == 0) {
                *(float2*)(C + o0)           = make_float2(v00, v01);
                *(float2*)(C + o0 + 8 * ldc) = make_float2(v10, v11);
            } else {
                *(uint32_t*)(Ch + o0)           = pack2(__float2half_rn(v00), __float2half_rn(v01));
                *(uint32_t*)(Ch + o0 + 8 * ldc) = pack2(__float2half_rn(v10), __float2half_rn(v11));
            }
        }
    }
}

// ---------------- fused mask+softmax: Sh(fp16) -> P fp16 + att (transposed) ----------------
__global__ __launch_bounds__(256)
void smx_att(const __half* __restrict__ Sh, const unsigned char* __restrict__ cmask,
             const unsigned char* __restrict__ words,
             __half* __restrict__ Ph, float* __restrict__ att)
{
    __shared__ float tile[8][521];
    __shared__ unsigned char words_s[512];
    const int b = blockIdx.y, q = blockIdx.x;
    const int tid = threadIdx.x, w = tid >> 5, lane = tid & 31;
    for (int i = tid; i < 512; i += 256) words_s[i] = words[b * 512 + i];
    __syncthreads();

    const long long base8 = ((long long)b * 512 + q) * 8;
    const __half* row = Sh + (base8 + w) * 512;
    const bool cmb = cmask[base8 + w] != 0;

    float v[16];
    float mx = -3.0e38f;
    #pragma unroll
    for (int i = 0; i < 4; i++) {
        uint2 px = *(const uint2*)(row + i * 128 + lane * 4);
        __half2 h01 = *(__half2*)&px.x, h23 = *(__half2*)&px.y;
        float t[4] = { __low2float(h01), __high2float(h01),
                       __low2float(h23), __high2float(h23) };
        #pragma unroll
        for (int j = 0; j < 4; j++) {
            int k = i * 128 + lane * 4 + j;
            float s = t[j];                       // 1/sqrt(512) pre-folded into Qp
            s = (cmb && words_s[k]) ? s : -1e9f;
            v[i * 4 + j] = s;
            mx = fmaxf(mx, s);
        }
    }
    #pragma unroll
    for (int o = 16; o > 0; o >>= 1) mx = fmaxf(mx, __shfl_xor_sync(0xffffffffu, mx, o));
    float sum = 0.0f;
    #pragma unroll
    for (int i = 0; i < 16; i++) { float e = __expf(v[i] - mx); v[i] = e; sum += e; }
    #pragma unroll
    for (int o = 16; o > 0; o >>= 1) sum += __shfl_xor_sync(0xffffffffu, sum, o);
    const float inv = 1.0f / sum;

    #pragma unroll
    for (int i = 0; i < 4; i++) {
        float p0 = v[i*4]*inv, p1 = v[i*4+1]*inv, p2 = v[i*4+2]*inv, p3 = v[i*4+3]*inv;
        long long off = (base8 + w) * 512 + i * 128 + lane * 4;
        *(uint2*)(Ph + off) = make_uint2(
            pack2(__float2half_rn(p0), __float2half_rn(p1)),
            pack2(__float2half_rn(p2), __float2half_rn(p3)));
        int k = i * 128 + lane * 4;
        tile[w][k] = p0; tile[w][k+1] = p1; tile[w][k+2] = p2; tile[w][k+3] = p3;
    }
    if (att) {
        __syncthreads();
        float* obase = att + base8 * 512;
        #pragma unroll
        for (int it = 0; it < 16; it++) {
            int idx = tid + it * 256;
            obase[idx] = tile[idx & 7][idx >> 3];
        }
    }
}

// ---------------- input conversion (fp32 -> fp16) ----------------
__global__ void convert4_kernel(const float* __restrict__ in, __half* __restrict__ h,
                                long long n4) {
    long long i = (long long)blockIdx.x * blockDim.x + threadIdx.x;
    if (i >= n4) return;
    float4 v = ((const float4*)in)[i];
    ((uint2*)h)[i] = make_uint2(
        pack2(__float2half_rn(v.x), __float2half_rn(v.y)),
        pack2(__float2half_rn(v.z), __float2half_rn(v.w)));
}

// weight transposes in ONE launch: Wq -> wqh; Wk,Wv -> wkvh (concat rows); Wz -> wzh
__global__ void transpose_cast_all(
    const float* __restrict__ Wq, const float* __restrict__ Wk,
    const float* __restrict__ Wv, const float* __restrict__ Wz,
    __half* __restrict__ wqh, __half* __restrict__ wkvh, __half* __restrict__ wzh)
{
    __shared__ float t[32][33];
    const int z = blockIdx.z;
    const float* in; __half* oh; int R;
    if (z == 0)      { in = Wq; oh = wqh;              R = DQ; }
    else if (z == 1) { in = Wk; oh = wkvh;             R = DIN; }
    else if (z == 2) { in = Wv; oh = wkvh + DIN * DIN; R = DIN; }
    else             { in = Wz; oh = wzh;              R = DOUT; }
    const int C = 512;
    int c0 = blockIdx.x * 32, r0 = blockIdx.y * 32;
    if (r0 >= R) return;   // uniform per block
    int x = threadIdx.x, y = threadIdx.y;
    #pragma unroll
    for (int j = 0; j < 32; j += 8)
        t[y + j][x] = in[(long long)(r0 + y + j) * C + c0 + x];
    __syncthreads();
    #pragma unroll
    for (int j = 0; j < 32; j += 8)
        oh[(long long)(c0 + y + j) * R + r0 + x] = __float2half_rn(t[x][y + j]);
}

// concat(bk, bv) -> bkv
__global__ void concat_bias_kernel(const float* __restrict__ bk, const float* __restrict__ bv,
                                   float* __restrict__ bkv) {
    int i = blockIdx.x * blockDim.x + threadIdx.x;
    if (i < DIN) bkv[i] = bk[i];
    else if (i < 2 * DIN) bkv[i] = bv[i - DIN];
}

// ---------------- mask handling ----------------
__global__ void detect_mask_kernel(const unsigned int* __restrict__ m) {
    if (blockIdx.x == 0 && threadIdx.x == 0) {
        bool all01 = true, allf = true;
        for (int i = 0; i < 1024; i++) {
            unsigned int v = m[i];
            if (!(v == 0u || v == 1u)) all01 = false;
            if (!(v == 0u || v == 0x3F800000u)) allf = false;
        }
        g_mask_mode = all01 ? 1 : (allf ? 0 : 2);
    }
}
__global__ void normalize_mask_kernel(const void* __restrict__ m,
                                      unsigned char* __restrict__ cmask,
                                      unsigned char* __restrict__ words) {
    int idx = blockIdx.x * blockDim.x + threadIdx.x;
    if (idx >= BB * SS) return;
    int mode = g_mask_mode;
    unsigned char any = 0;
    #pragma unroll
    for (int w = 0; w < WW; w++) {
        int e = idx * WW + w;
        unsigned char v;
        if (mode == 1)      v = (((const int*)m)[e] != 0);
        else if (mode == 0) v = (((const float*)m)[e] != 0.0f);
        else                v = (((const unsigned char*)m)[e] != 0);
        cmask[e] = v;
        any |= v;
    }
    words[idx] = any;
}

// ---------------- launch ----------------
extern "C" void kernel_launch(void* const* d_in, const int* in_sizes, int n_in,
                              void* d_out, int out_size) {
    const float* query = (const float*)d_in[0];
    const float* data  = (const float*)d_in[1];
    const void*  maskr = d_in[2];
    const float* Wq = (const float*)d_in[3];
    const float* bq = (const float*)d_in[4];
    const float* Wk = (const float*)d_in[5];
    const float* bk = (const float*)d_in[6];
    const float* Wv = (const float*)d_in[7];
    const float* bv = (const float*)d_in[8];
    const float* Wz = (const float*)d_in[9];
    const float* bz = (const float*)d_in[10];

    float* out = (float*)d_out;
    const long long zs_elems  = (long long)BB * SS * WW * DOUT;
    const long long att_elems = (long long)BB * SS * SS * WW;
    float* att = ((long long)out_size >= zs_elems + att_elems) ? out + zs_elems : nullptr;

    __half *qh,*dh,*wqh,*wkvh,*wzh,*Qh,*KV,*UTh,*Ph,*Sh;
    float *bkv;
    unsigned char *cm, *wm;
    cudaGetSymbolAddress((void**)&qh, g_qh);
    cudaGetSymbolAddress((void**)&dh, g_dh);
    cudaGetSymbolAddress((void**)&wqh, g_wqh);
    cudaGetSymbolAddress((void**)&wkvh, g_wkvh);
    cudaGetSymbolAddress((void**)&wzh, g_wzh);
    cudaGetSymbolAddress((void**)&bkv, g_bkv);
    cudaGetSymbolAddress((void**)&Qh, g_Qh);
    cudaGetSymbolAddress((void**)&KV, g_KV);
    cudaGetSymbolAddress((void**)&UTh, g_UTh);
    cudaGetSymbolAddress((void**)&Ph, g_Ph);
    cudaGetSymbolAddress((void**)&Sh, g_Sh);
    cudaGetSymbolAddress((void**)&cm, g_cmask);
    cudaGetSymbolAddress((void**)&wm, g_words);

    const int SMEM = NSTAGE * STAGEB;   // 61440 -> 2 CTAs/SM
    cudaFuncSetAttribute(hgemm<0>, cudaFuncAttributeMaxDynamicSharedMemorySize, SMEM);
    cudaFuncSetAttribute(hgemm<1>, cudaFuncAttributeMaxDynamicSharedMemorySize, SMEM);

    detect_mask_kernel<<<1, 1>>>((const unsigned int*)maskr);
    normalize_mask_kernel<<<(BB * SS + 255) / 256, 256>>>(maskr, cm, wm);
    concat_bias_kernel<<<4, 256>>>(bk, bv, bkv);
    {
        long long nq4 = (long long)BB * SS * WW * DQ / 4;
        convert4_kernel<<<(unsigned)((nq4 + 255) / 256), 256>>>(query, qh, nq4);
        long long nd4 = (long long)BB * SS * DIN / 4;
        convert4_kernel<<<(unsigned)((nd4 + 255) / 256), 256>>>(data, dh, nd4);
    }
    transpose_cast_all<<<dim3(16, 16, 4), dim3(32, 8)>>>(Wq, Wk, Wv, Wz, wqh, wkvh, wzh);

    const float SCALE = 0.04419417382415922f;  // 1/sqrt(512), folded into Qp

    // Qproj -> Qh (scaled): [65536,512]
    hgemm<1><<<dim3(4, 512, 1), 256, SMEM>>>(qh, wqh, bq, SCALE,
        nullptr, Qh, DQ, DQ, DQ, DIN, 0, 0, 0);
    // K+V proj fused -> KV [8192, 1024] (cols 0-511 = K, 512-1023 = V)
    hgemm<1><<<dim3(8, 64, 1), 256, SMEM>>>(dh, wkvh, bkv, 1.0f,
        nullptr, KV, DIN, DIN, DIN, 2 * DIN, 0, 0, 0);
    // UT[b] = Wz^T @ V_b^T : [512z,512s] per batch  (U = V @ Wz); V rows stride 1024
    hgemm<1><<<dim3(4, 4, BB), 256, SMEM>>>(wzh, KV + DIN, nullptr, 1.0f,
        nullptr, UTh, DIN, DIN, 2 * DIN, SS, 0, (long long)SS * 2 * DIN, (long long)DOUT * SS);
    // scores[b] fp16: [4096,512] = Qh_b @ K_b^T ; K rows stride 1024
    hgemm<1><<<dim3(4, 32, BB), 256, SMEM>>>(Qh, KV, nullptr, 1.0f,
        nullptr, Sh, DIN, DIN, 2 * DIN, SS,
        (long long)SS * WW * DIN, (long long)SS * 2 * DIN, (long long)SS * WW * SS);
    // softmax + P fp16 + att
    smx_att<<<dim3(SS, BB), 256>>>(Sh, cm, wm, Ph, att);
    // zs = P @ UT^T + bz -> d_out fp32   (= att @ (V@Wz) + bz)
    hgemm<0><<<dim3(4, 32, BB), 256, SMEM>>>(Ph, UTh, bz, 1.0f,
        out, nullptr, SS, SS, SS, DOUT,
        (long long)SS * WW * SS, (long long)DOUT * SS, (long long)SS * WW * DOUT);
}

// round 15
// speedup vs baseline: 2.9172x; 1.0052x over previous
#include <cuda_runtime.h>
#include <cuda_fp16.h>
#include <math.h>
#include <stdint.h>

#define BB   16
#define SS   512
#define WW   8
#define DQ   256
#define DIN  512
#define DOUT 512

// ---------------- device scratch: plain fp16 operands ----------------
static __device__ __align__(1024) __half g_qh[(size_t)BB*SS*WW*DQ];
static __device__ __align__(1024) __half g_dh[(size_t)BB*SS*DIN];
static __device__ __align__(1024) __half g_wqh[DIN*DQ];
static __device__ __align__(1024) __half g_wkvh[2*DIN*DIN];           // concat [Wk^T; Wv^T] rows
static __device__ __align__(1024) __half g_wzh[DOUT*DOUT];
static __device__ __align__(1024) float  g_bkv[2*DIN];                // concat(bk, bv)
static __device__ __align__(1024) __half g_Qh[(size_t)BB*SS*WW*DIN];
static __device__ __align__(1024) __half g_KV[(size_t)BB*SS*2*DIN];   // [s][K|V] interleaved
static __device__ __align__(1024) __half g_UTh[(size_t)BB*DOUT*SS];   // (V@Wz)^T per batch [z][s]
static __device__ __align__(1024) __half g_Ph[(size_t)BB*SS*WW*SS];
static __device__ __align__(1024) __half g_Sh[(size_t)BB*SS*WW*SS];   // fp16 scores
static __device__ unsigned char g_cmask[BB*SS*WW];
static __device__ unsigned char g_words[BB*SS];
static __device__ int g_mask_mode;

// ---------------- low-level helpers ----------------
__device__ __forceinline__ uint32_t smem_u32(const void* p) {
    uint32_t a;
    asm("{ .reg .u64 t; cvta.to.shared.u64 t, %1; cvt.u32.u64 %0, t; }" : "=r"(a) : "l"(p));
    return a;
}
__device__ __forceinline__ void ldsm4(uint32_t* r, uint32_t addr) {
    asm volatile("ldmatrix.sync.aligned.m8n8.x4.shared.b16 {%0,%1,%2,%3}, [%4];\n"
        : "=r"(r[0]), "=r"(r[1]), "=r"(r[2]), "=r"(r[3]) : "r"(addr));
}
__device__ __forceinline__ void mma16816(float* c, const uint32_t* a, const uint32_t* b) {
    asm volatile(
        "mma.sync.aligned.m16n8k16.row.col.f32.f16.f16.f32 "
        "{%0,%1,%2,%3}, {%4,%5,%6,%7}, {%8,%9}, {%0,%1,%2,%3};\n"
        : "+f"(c[0]), "+f"(c[1]), "+f"(c[2]), "+f"(c[3])
        : "r"(a[0]), "r"(a[1]), "r"(a[2]), "r"(a[3]), "r"(b[0]), "r"(b[1]));
}
#define CPASYNC16(dst, src) \
    asm volatile("cp.async.cg.shared.global [%0], [%1], 16;\n" :: "r"(dst), "l"(src) : "memory")
#define CPCOMMIT() asm volatile("cp.async.commit_group;\n" ::: "memory")
#define CPWAIT1()  asm volatile("cp.async.wait_group 1;\n" ::: "memory")

__device__ __forceinline__ uint32_t pack2(__half a, __half b) {
    __half2 h = __halves2half2(a, b);
    return *(uint32_t*)&h;
}

// ---------------- fp16 HMMA GEMM: C[M,N] = A[M,K] @ B[N,K]^T ----------------
// BM=128, BN=128, BK=64, 256 thr, 8 warps (4x2), warp tile 32x64, 3-stage, 2 CTAs/SM.
// Row = 128B payload (64 halves) + 16B pad = 144B: row-stride mod 128 = 16 ->
// each 8-row ldsm group covers 8 distinct 16B groups (conflict-free).
#define ROWB   144
#define PLANE  18432           /* 128 rows x 144B */
#define STAGEB 36864           /* A, B plane slots */
#define NSTAGE 3

__device__ __forceinline__ void issue_chunk(uint32_t sb,
    const __half* A, const __half* B, long long lda, long long ldb, int k0, int tid)
{
    #pragma unroll
    for (int it = 0; it < 4; it++) {              // 128 rows x 8 lines per plane
        int s = tid + it * 256, r = s >> 3, sg = s & 7;
        CPASYNC16(sb + r * ROWB + sg * 16,         A + (long long)r * lda + k0 + sg * 8);
        CPASYNC16(sb + PLANE + r * ROWB + sg * 16, B + (long long)r * ldb + k0 + sg * 8);
    }
}

__device__ __forceinline__ void gemm_compute(uint32_t sb, int wm, int wn, int lane, float* acc) {
    const uint32_t As = sb, Bs = sb + PLANE;
    const int mrow = (lane & 7) + ((lane >> 3) & 1) * 8, akcol = ((lane >> 4) & 1) * 8;
    const int nrow = (lane & 7) + ((lane >> 4) & 1) * 8, bkcol = ((lane >> 3) & 1) * 8;
    #pragma unroll
    for (int ks = 0; ks < 4; ks++) {
        const int k0 = ks * 16;
        uint32_t bf[16];
        #pragma unroll
        for (int np = 0; np < 4; np++) {
            uint32_t off = (uint32_t)((wn * 64 + np * 16 + nrow) * ROWB + (k0 + bkcol) * 2);
            ldsm4(&bf[np * 4], Bs + off);   // [N][K] k-contig == mma "col" B, non-trans
        }
        #pragma unroll
        for (int mi = 0; mi < 2; mi++) {
            uint32_t off = (uint32_t)((wm * 32 + mi * 16 + mrow) * ROWB + (k0 + akcol) * 2);
            uint32_t af[4];
            ldsm4(af, As + off);
            #pragma unroll
            for (int ni = 0; ni < 8; ni++)
                mma16816(acc + (mi * 8 + ni) * 4, af, &bf[ni * 2]);
        }
    }
}

// OUT: 0 = fp32 C, 1 = fp16 Ch
template<int OUT>
__global__ __launch_bounds__(256, 2)
void hgemm(const __half* __restrict__ A, const __half* __restrict__ B,
           const float* __restrict__ colbias, float oscale,
           float* __restrict__ C, __half* __restrict__ Ch,
           int K, long long lda, long long ldb, long long ldc,
           long long sAb, long long sBb, long long sCb)
{
    extern __shared__ char dsm[];
    const int tid = threadIdx.x, wid = tid >> 5, lane = tid & 31;
    const int wm = wid & 3, wn = wid >> 2;   // 4x2 warp grid, tile 32x64

    A += (long long)blockIdx.z * sAb + (long long)blockIdx.y * 128 * lda;
    B += (long long)blockIdx.z * sBb + (long long)blockIdx.x * 128 * ldb;

    float acc[64];
    #pragma unroll
    for (int i = 0; i < 64; i++) acc[i] = 0.0f;

    const uint32_t sbase = smem_u32(dsm);
    const int NC = K >> 6;

    issue_chunk(sbase,          A, B, lda, ldb, 0,  tid); CPCOMMIT();
    issue_chunk(sbase + STAGEB, A, B, lda, ldb, 64, tid); CPCOMMIT();

    for (int i = 0; i < NC; i++) {
        CPWAIT1();               // >= chunk i complete
        __syncthreads();         // all warps past compute(i-1); stage (i+2)%3 free
        if (i + 2 < NC)
            issue_chunk(sbase + ((i + 2) % NSTAGE) * STAGEB, A, B, lda, ldb, (i + 2) * 64, tid);
        CPCOMMIT();              // unconditional: pending-group invariant at tail
        gemm_compute(sbase + (i % NSTAGE) * STAGEB, wm, wn, lane, acc);
    }

    // epilogue: frag c0:(r,c) c1:(r,c+1) c2:(r+8,c) c3:(r+8,c+1)
    const long long wr = (long long)blockIdx.y * 128 + wm * 32;
    const long long wc = (long long)blockIdx.x * 128 + wn * 64;
    #pragma unroll
    for (int mi = 0; mi < 2; mi++) {
        long long r0 = wr + mi * 16 + (lane >> 2);
        #pragma unroll
        for (int ni = 0; ni < 8; ni++) {
            long long c0 = wc + ni * 8 + (lane & 3) * 2;
            float cb0 = 0.0f, cb1 = 0.0f;
            if (colbias) { float2 cb = *(const float2*)(colbias + c0); cb0 = cb.x; cb1 = cb.y; }
            const float* a = acc + (mi * 8 + ni) * 4;
            float v00 = (a[0] + cb0) * oscale, v01 = (a[1] + cb1) * oscale;
            float v10 = (a[2] + cb0) * oscale, v11 = (a[3] + cb1) * oscale;
            long long o0 = ((long long)blockIdx.z * sCb) + r0 * ldc + c0;
            if (OUT == 0) {
                *(float2*)(C + o0)           = make_float2(v00, v01);
                *(float2*)(C + o0 + 8 * ldc) = make_float2(v10, v11);
            } else {
                *(uint32_t*)(Ch + o0)           = pack2(__float2half_rn(v00), __float2half_rn(v01));
                *(uint32_t*)(Ch + o0 + 8 * ldc) = pack2(__float2half_rn(v10), __float2half_rn(v11));
            }
        }
    }
}

// ---------------- fused mask+softmax: Sh(fp16) -> P fp16 + att (transposed) ----------------
__global__ __launch_bounds__(256)
void smx_att(const __half* __restrict__ Sh, const unsigned char* __restrict__ cmask,
             const unsigned char* __restrict__ words,
             __half* __restrict__ Ph, float* __restrict__ att)
{
    __shared__ float tile[8][521];
    __shared__ unsigned char words_s[512];
    const int b = blockIdx.y, q = blockIdx.x;
    const int tid = threadIdx.x, w = tid >> 5, lane = tid & 31;
    for (int i = tid; i < 512; i += 256) words_s[i] = words[b * 512 + i];
    __syncthreads();

    const long long base8 = ((long long)b * 512 + q) * 8;
    const __half* row = Sh + (base8 + w) * 512;
    const bool cmb = cmask[base8 + w] != 0;

    float v[16];
    float mx = -3.0e38f;
    #pragma unroll
    for (int i = 0; i < 4; i++) {
        uint2 px = *(const uint2*)(row + i * 128 + lane * 4);
        __half2 h01 = *(__half2*)&px.x, h23 = *(__half2*)&px.y;
        float t[4] = { __low2float(h01), __high2float(h01),
                       __low2float(h23), __high2float(h23) };
        #pragma unroll
        for (int j = 0; j < 4; j++) {
            int k = i * 128 + lane * 4 + j;
            float s = t[j];                       // 1/sqrt(512) pre-folded into Qp
            s = (cmb && words_s[k]) ? s : -1e9f;
            v[i * 4 + j] = s;
            mx = fmaxf(mx, s);
        }
    }
    #pragma unroll
    for (int o = 16; o > 0; o >>= 1) mx = fmaxf(mx, __shfl_xor_sync(0xffffffffu, mx, o));
    float sum = 0.0f;
    #pragma unroll
    for (int i = 0; i < 16; i++) { float e = __expf(v[i] - mx); v[i] = e; sum += e; }
    #pragma unroll
    for (int o = 16; o > 0; o >>= 1) sum += __shfl_xor_sync(0xffffffffu, sum, o);
    const float inv = 1.0f / sum;

    #pragma unroll
    for (int i = 0; i < 4; i++) {
        float p0 = v[i*4]*inv, p1 = v[i*4+1]*inv, p2 = v[i*4+2]*inv, p3 = v[i*4+3]*inv;
        long long off = (base8 + w) * 512 + i * 128 + lane * 4;
        *(uint2*)(Ph + off) = make_uint2(
            pack2(__float2half_rn(p0), __float2half_rn(p1)),
            pack2(__float2half_rn(p2), __float2half_rn(p3)));
        int k = i * 128 + lane * 4;
        tile[w][k] = p0; tile[w][k+1] = p1; tile[w][k+2] = p2; tile[w][k+3] = p3;
    }
    if (att) {
        __syncthreads();
        float* obase = att + base8 * 512;
        #pragma unroll
        for (int it = 0; it < 16; it++) {
            int idx = tid + it * 256;
            obase[idx] = tile[idx & 7][idx >> 3];
        }
    }
}

// ---------------- input conversion (fp32 -> fp16), both tensors in ONE launch ----------------
__global__ void convert_both_kernel(const float* __restrict__ q, __half* __restrict__ qh,
                                    long long nq4,
                                    const float* __restrict__ d, __half* __restrict__ dh,
                                    long long nd4) {
    long long i = (long long)blockIdx.x * blockDim.x + threadIdx.x;
    const float* in; __half* oh; long long idx;
    if (i < nq4) { in = q; oh = qh; idx = i; }
    else if (i < nq4 + nd4) { in = d; oh = dh; idx = i - nq4; }
    else return;
    float4 v = ((const float4*)in)[idx];
    ((uint2*)oh)[idx] = make_uint2(
        pack2(__float2half_rn(v.x), __float2half_rn(v.y)),
        pack2(__float2half_rn(v.z), __float2half_rn(v.w)));
}

// weight transposes in ONE launch: Wq -> wqh; Wk,Wv -> wkvh (concat rows); Wz -> wzh
__global__ void transpose_cast_all(
    const float* __restrict__ Wq, const float* __restrict__ Wk,
    const float* __restrict__ Wv, const float* __restrict__ Wz,
    __half* __restrict__ wqh, __half* __restrict__ wkvh, __half* __restrict__ wzh)
{
    __shared__ float t[32][33];
    const int z = blockIdx.z;
    const float* in; __half* oh; int R;
    if (z == 0)      { in = Wq; oh = wqh;              R = DQ; }
    else if (z == 1) { in = Wk; oh = wkvh;             R = DIN; }
    else if (z == 2) { in = Wv; oh = wkvh + DIN * DIN; R = DIN; }
    else             { in = Wz; oh = wzh;              R = DOUT; }
    const int C = 512;
    int c0 = blockIdx.x * 32, r0 = blockIdx.y * 32;
    if (r0 >= R) return;   // uniform per block
    int x = threadIdx.x, y = threadIdx.y;
    #pragma unroll
    for (int j = 0; j < 32; j += 8)
        t[y + j][x] = in[(long long)(r0 + y + j) * C + c0 + x];
    __syncthreads();
    #pragma unroll
    for (int j = 0; j < 32; j += 8)
        oh[(long long)(c0 + y + j) * R + r0 + x] = __float2half_rn(t[x][y + j]);
}

// concat(bk, bv) -> bkv
__global__ void concat_bias_kernel(const float* __restrict__ bk, const float* __restrict__ bv,
                                   float* __restrict__ bkv) {
    int i = blockIdx.x * blockDim.x + threadIdx.x;
    if (i < DIN) bkv[i] = bk[i];
    else if (i < 2 * DIN) bkv[i] = bv[i - DIN];
}

// ---------------- mask handling ----------------
__global__ void detect_mask_kernel(const unsigned int* __restrict__ m) {
    if (blockIdx.x == 0 && threadIdx.x == 0) {
        bool all01 = true, allf = true;
        for (int i = 0; i < 1024; i++) {
            unsigned int v = m[i];
            if (!(v == 0u || v == 1u)) all01 = false;
            if (!(v == 0u || v == 0x3F800000u)) allf = false;
        }
        g_mask_mode = all01 ? 1 : (allf ? 0 : 2);
    }
}
__global__ void normalize_mask_kernel(const void* __restrict__ m,
                                      unsigned char* __restrict__ cmask,
                                      unsigned char* __restrict__ words) {
    int idx = blockIdx.x * blockDim.x + threadIdx.x;
    if (idx >= BB * SS) return;
    int mode = g_mask_mode;
    unsigned char any = 0;
    #pragma unroll
    for (int w = 0; w < WW; w++) {
        int e = idx * WW + w;
        unsigned char v;
        if (mode == 1)      v = (((const int*)m)[e] != 0);
        else if (mode == 0) v = (((const float*)m)[e] != 0.0f);
        else                v = (((const unsigned char*)m)[e] != 0);
        cmask[e] = v;
        any |= v;
    }
    words[idx] = any;
}

// ---------------- launch ----------------
extern "C" void kernel_launch(void* const* d_in, const int* in_sizes, int n_in,
                              void* d_out, int out_size) {
    const float* query = (const float*)d_in[0];
    const float* data  = (const float*)d_in[1];
    const void*  maskr = d_in[2];
    const float* Wq = (const float*)d_in[3];
    const float* bq = (const float*)d_in[4];
    const float* Wk = (const float*)d_in[5];
    const float* bk = (const float*)d_in[6];
    const float* Wv = (const float*)d_in[7];
    const float* bv = (const float*)d_in[8];
    const float* Wz = (const float*)d_in[9];
    const float* bz = (const float*)d_in[10];

    float* out = (float*)d_out;
    const long long zs_elems  = (long long)BB * SS * WW * DOUT;
    const long long att_elems = (long long)BB * SS * SS * WW;
    float* att = ((long long)out_size >= zs_elems + att_elems) ? out + zs_elems : nullptr;

    __half *qh,*dh,*wqh,*wkvh,*wzh,*Qh,*KV,*UTh,*Ph,*Sh;
    float *bkv;
    unsigned char *cm, *wm;
    cudaGetSymbolAddress((void**)&qh, g_qh);
    cudaGetSymbolAddress((void**)&dh, g_dh);
    cudaGetSymbolAddress((void**)&wqh, g_wqh);
    cudaGetSymbolAddress((void**)&wkvh, g_wkvh);
    cudaGetSymbolAddress((void**)&wzh, g_wzh);
    cudaGetSymbolAddress((void**)&bkv, g_bkv);
    cudaGetSymbolAddress((void**)&Qh, g_Qh);
    cudaGetSymbolAddress((void**)&KV, g_KV);
    cudaGetSymbolAddress((void**)&UTh, g_UTh);
    cudaGetSymbolAddress((void**)&Ph, g_Ph);
    cudaGetSymbolAddress((void**)&Sh, g_Sh);
    cudaGetSymbolAddress((void**)&cm, g_cmask);
    cudaGetSymbolAddress((void**)&wm, g_words);

    const int SMEM = NSTAGE * STAGEB;   // 110592 -> 2 CTAs/SM (216 KB < 228 KB)
    cudaFuncSetAttribute(hgemm<0>, cudaFuncAttributeMaxDynamicSharedMemorySize, SMEM);
    cudaFuncSetAttribute(hgemm<1>, cudaFuncAttributeMaxDynamicSharedMemorySize, SMEM);

    detect_mask_kernel<<<1, 1>>>((const unsigned int*)maskr);
    normalize_mask_kernel<<<(BB * SS + 255) / 256, 256>>>(maskr, cm, wm);
    concat_bias_kernel<<<4, 256>>>(bk, bv, bkv);
    {
        long long nq4 = (long long)BB * SS * WW * DQ / 4;
        long long nd4 = (long long)BB * SS * DIN / 4;
        convert_both_kernel<<<(unsigned)((nq4 + nd4 + 255) / 256), 256>>>(
            query, qh, nq4, data, dh, nd4);
    }
    transpose_cast_all<<<dim3(16, 16, 4), dim3(32, 8)>>>(Wq, Wk, Wv, Wz, wqh, wkvh, wzh);

    const float SCALE = 0.04419417382415922f;  // 1/sqrt(512), folded into Qp

    // Qproj -> Qh (scaled): [65536,512]
    hgemm<1><<<dim3(4, 512, 1), 256, SMEM>>>(qh, wqh, bq, SCALE,
        nullptr, Qh, DQ, DQ, DQ, DIN, 0, 0, 0);
    // K+V proj fused -> KV [8192, 1024] (cols 0-511 = K, 512-1023 = V)
    hgemm<1><<<dim3(8, 64, 1), 256, SMEM>>>(dh, wkvh, bkv, 1.0f,
        nullptr, KV, DIN, DIN, DIN, 2 * DIN, 0, 0, 0);
    // UT[b] = Wz^T @ V_b^T : [512z,512s] per batch  (U = V @ Wz); V rows stride 1024
    hgemm<1><<<dim3(4, 4, BB), 256, SMEM>>>(wzh, KV + DIN, nullptr, 1.0f,
        nullptr, UTh, DIN, DIN, 2 * DIN, SS, 0, (long long)SS * 2 * DIN, (long long)DOUT * SS);
    // scores[b] fp16: [4096,512] = Qh_b @ K_b^T ; K rows stride 1024
    hgemm<1><<<dim3(4, 32, BB), 256, SMEM>>>(Qh, KV, nullptr, 1.0f,
        nullptr, Sh, DIN, DIN, 2 * DIN, SS,
        (long long)SS * WW * DIN, (long long)SS * 2 * DIN, (long long)SS * WW * SS);
    // softmax + P fp16 + att
    smx_att<<<dim3(SS, BB), 256>>>(Sh, cm, wm, Ph, att);
    // zs = P @ UT^T + bz -> d_out fp32   (= att @ (V@Wz) + bz)
    hgemm<0><<<dim3(4, 32, BB), 256, SMEM>>>(Ph, UTh, bz, 1.0f,
        out, nullptr, SS, SS, SS, DOUT,
        (long long)SS * WW * SS, (long long)DOUT * SS, (long long)SS * WW * DOUT);
}

// round 17
// speedup vs baseline: 2.9546x; 1.0128x over previous
#include <cuda_runtime.h>
#include <cuda_fp16.h>
#include <math.h>
#include <stdint.h>

#define BB   16
#define SS   512
#define WW   8
#define DQ   256
#define DIN  512
#define DOUT 512

// ---------------- device scratch: plain fp16 operands ----------------
static __device__ __align__(1024) __half g_qh[(size_t)BB*SS*WW*DQ];
static __device__ __align__(1024) __half g_dh[(size_t)BB*SS*DIN];
static __device__ __align__(1024) __half g_wqh[DIN*DQ];
static __device__ __align__(1024) __half g_wkvh[2*DIN*DIN];           // concat [Wk^T; Wv^T] rows
static __device__ __align__(1024) __half g_wzh[DOUT*DOUT];
static __device__ __align__(1024) float  g_bkv[2*DIN];                // concat(bk, bv)
static __device__ __align__(1024) __half g_Qh[(size_t)BB*SS*WW*DIN];
static __device__ __align__(1024) __half g_KV[(size_t)BB*SS*2*DIN];   // [s][K|V] interleaved
static __device__ __align__(1024) __half g_UTh[(size_t)BB*DOUT*SS];   // (V@Wz)^T per batch [z][s]
static __device__ __align__(1024) __half g_Eh[(size_t)BB*SS*WW*SS];   // unnormalized exp(scores)
static __device__ __align__(1024) float  g_inv[(size_t)BB*SS*WW];     // 1/rowsum
static __device__ unsigned char g_cmask[BB*SS*WW];
static __device__ unsigned char g_words[BB*SS];
static __device__ int g_mask_mode;

// ---------------- low-level helpers ----------------
__device__ __forceinline__ uint32_t smem_u32(const void* p) {
    uint32_t a;
    asm("{ .reg .u64 t; cvta.to.shared.u64 t, %1; cvt.u32.u64 %0, t; }" : "=r"(a) : "l"(p));
    return a;
}
__device__ __forceinline__ void ldsm4(uint32_t* r, uint32_t addr) {
    asm volatile("ldmatrix.sync.aligned.m8n8.x4.shared.b16 {%0,%1,%2,%3}, [%4];\n"
        : "=r"(r[0]), "=r"(r[1]), "=r"(r[2]), "=r"(r[3]) : "r"(addr));
}
__device__ __forceinline__ void mma16816(float* c, const uint32_t* a, const uint32_t* b) {
    asm volatile(
        "mma.sync.aligned.m16n8k16.row.col.f32.f16.f16.f32 "
        "{%0,%1,%2,%3}, {%4,%5,%6,%7}, {%8,%9}, {%0,%1,%2,%3};\n"
        : "+f"(c[0]), "+f"(c[1]), "+f"(c[2]), "+f"(c[3])
        : "r"(a[0]), "r"(a[1]), "r"(a[2]), "r"(a[3]), "r"(b[0]), "r"(b[1]));
}
#define CPASYNC16(dst, src) \
    asm volatile("cp.async.cg.shared.global [%0], [%1], 16;\n" :: "r"(dst), "l"(src) : "memory")
#define CPCOMMIT() asm volatile("cp.async.commit_group;\n" ::: "memory")
#define CPWAIT1()  asm volatile("cp.async.wait_group 1;\n" ::: "memory")

__device__ __forceinline__ uint32_t pack2(__half a, __half b) {
    __half2 h = __halves2half2(a, b);
    return *(uint32_t*)&h;
}

// ---------------- fp16 HMMA GEMM: C[M,N] = A[M,K] @ B[N,K]^T ----------------
// BM=128, BN=128, BK=64, 256 thr, 8 warps (4x2), warp tile 32x64, 3-stage, 2 CTAs/SM.
// SMEM row = 128B payload + 16B pad = 144B (conflict-free ldsm).
#define ROWB   144
#define PLANE  18432
#define STAGEB 36864
#define NSTAGE 3

__device__ __forceinline__ void issue_chunk(uint32_t sb,
    const __half* A, const __half* B, long long lda, long long ldb, int k0, int tid)
{
    #pragma unroll
    for (int it = 0; it < 4; it++) {
        int s = tid + it * 256, r = s >> 3, sg = s & 7;
        CPASYNC16(sb + r * ROWB + sg * 16,         A + (long long)r * lda + k0 + sg * 8);
        CPASYNC16(sb + PLANE + r * ROWB + sg * 16, B + (long long)r * ldb + k0 + sg * 8);
    }
}

__device__ __forceinline__ void gemm_compute(uint32_t sb, int wm, int wn, int lane, float* acc) {
    const uint32_t As = sb, Bs = sb + PLANE;
    const int mrow = (lane & 7) + ((lane >> 3) & 1) * 8, akcol = ((lane >> 4) & 1) * 8;
    const int nrow = (lane & 7) + ((lane >> 4) & 1) * 8, bkcol = ((lane >> 3) & 1) * 8;
    #pragma unroll
    for (int ks = 0; ks < 4; ks++) {
        const int k0 = ks * 16;
        uint32_t bf[16];
        #pragma unroll
        for (int np = 0; np < 4; np++) {
            uint32_t off = (uint32_t)((wn * 64 + np * 16 + nrow) * ROWB + (k0 + bkcol) * 2);
            ldsm4(&bf[np * 4], Bs + off);   // [N][K] k-contig == mma "col" B, non-trans
        }
        #pragma unroll
        for (int mi = 0; mi < 2; mi++) {
            uint32_t off = (uint32_t)((wm * 32 + mi * 16 + mrow) * ROWB + (k0 + akcol) * 2);
            uint32_t af[4];
            ldsm4(af, As + off);
            #pragma unroll
            for (int ni = 0; ni < 8; ni++)
                mma16816(acc + (mi * 8 + ni) * 4, af, &bf[ni * 2]);
        }
    }
}

// OUT: 0 = fp32 C = acc*rowscale + colbias   (rowscale may be null -> 1)
//      1 = fp16 Ch = acc*oscale + colbias
//      2 = fp16 Ch = exp(masked acc)  [cmask rows, words cols; masked row -> 1.0]
template<int OUT>
__global__ __launch_bounds__(256, 2)
void hgemm(const __half* __restrict__ A, const __half* __restrict__ B,
           const float* __restrict__ colbias, float oscale,
           float* __restrict__ C, __half* __restrict__ Ch,
           const unsigned char* __restrict__ cmask, const unsigned char* __restrict__ words_g,
           const float* __restrict__ rowscale,
           int K, long long lda, long long ldb, long long ldc,
           long long sAb, long long sBb, long long sCb)
{
    extern __shared__ char dsm[];
    __shared__ unsigned char ws[128];
    const int tid = threadIdx.x, wid = tid >> 5, lane = tid & 31;
    const int wm = wid & 3, wn = wid >> 2;   // 4x2 warp grid, tile 32x64

    if (OUT == 2 && tid < 128)
        ws[tid] = words_g[(long long)blockIdx.z * 512 + blockIdx.x * 128 + tid];

    A += (long long)blockIdx.z * sAb + (long long)blockIdx.y * 128 * lda;
    B += (long long)blockIdx.z * sBb + (long long)blockIdx.x * 128 * ldb;

    float acc[64];
    #pragma unroll
    for (int i = 0; i < 64; i++) acc[i] = 0.0f;

    const uint32_t sbase = smem_u32(dsm);
    const int NC = K >> 6;

    issue_chunk(sbase,          A, B, lda, ldb, 0,  tid); CPCOMMIT();
    issue_chunk(sbase + STAGEB, A, B, lda, ldb, 64, tid); CPCOMMIT();

    for (int i = 0; i < NC; i++) {
        CPWAIT1();
        __syncthreads();
        if (i + 2 < NC)
            issue_chunk(sbase + ((i + 2) % NSTAGE) * STAGEB, A, B, lda, ldb, (i + 2) * 64, tid);
        CPCOMMIT();
        gemm_compute(sbase + (i % NSTAGE) * STAGEB, wm, wn, lane, acc);
    }

    // epilogue: frag c0:(r,c) c1:(r,c+1) c2:(r+8,c) c3:(r+8,c+1)
    const long long wr = (long long)blockIdx.y * 128 + wm * 32;
    const long long wc = (long long)blockIdx.x * 128 + wn * 64;
    #pragma unroll
    for (int mi = 0; mi < 2; mi++) {
        long long r0 = wr + mi * 16 + (lane >> 2);
        bool cm0 = true, cm8 = true;
        float rs0 = 1.0f, rs8 = 1.0f;
        if (OUT == 2) {
            cm0 = cmask[(long long)blockIdx.z * 4096 + r0] != 0;
            cm8 = cmask[(long long)blockIdx.z * 4096 + r0 + 8] != 0;
        }
        if (OUT == 0 && rowscale) {
            rs0 = rowscale[(long long)blockIdx.z * 4096 + r0];
            rs8 = rowscale[(long long)blockIdx.z * 4096 + r0 + 8];
        }
        #pragma unroll
        for (int ni = 0; ni < 8; ni++) {
            long long c0 = wc + ni * 8 + (lane & 3) * 2;
            float cb0 = 0.0f, cb1 = 0.0f;
            if (colbias) { float2 cb = *(const float2*)(colbias + c0); cb0 = cb.x; cb1 = cb.y; }
            const float* a = acc + (mi * 8 + ni) * 4;
            long long o0 = ((long long)blockIdx.z * sCb) + r0 * ldc + c0;
            if (OUT == 0) {
                // acc * rowscale + colbias  (bias AFTER the row scale)
                *(float2*)(C + o0)           = make_float2(a[0]*rs0 + cb0, a[1]*rs0 + cb1);
                *(float2*)(C + o0 + 8 * ldc) = make_float2(a[2]*rs8 + cb0, a[3]*rs8 + cb1);
            } else if (OUT == 1) {
                float v00 = a[0]*oscale + cb0*oscale, v01 = a[1]*oscale + cb1*oscale;
                float v10 = a[2]*oscale + cb0*oscale, v11 = a[3]*oscale + cb1*oscale;
                *(uint32_t*)(Ch + o0)           = pack2(__float2half_rn(v00), __float2half_rn(v01));
                *(uint32_t*)(Ch + o0 + 8 * ldc) = pack2(__float2half_rn(v10), __float2half_rn(v11));
            } else {
                int ci = wn * 64 + ni * 8 + (lane & 3) * 2;
                bool w0 = ws[ci] != 0, w1 = ws[ci + 1] != 0;
                // masked key -> 0; fully-masked row -> 1.0 (uniform softmax, matches ref)
                float e00 = cm0 ? (w0 ? __expf(a[0]) : 0.0f) : 1.0f;
                float e01 = cm0 ? (w1 ? __expf(a[1]) : 0.0f) : 1.0f;
                float e10 = cm8 ? (w0 ? __expf(a[2]) : 0.0f) : 1.0f;
                float e11 = cm8 ? (w1 ? __expf(a[3]) : 0.0f) : 1.0f;
                *(uint32_t*)(Ch + o0)           = pack2(__float2half_rn(e00), __float2half_rn(e01));
                *(uint32_t*)(Ch + o0 + 8 * ldc) = pack2(__float2half_rn(e10), __float2half_rn(e11));
            }
        }
    }
}

// ---------------- att kernel: Eh -> inv (1/rowsum) + normalized transposed att ----------------
__global__ __launch_bounds__(256)
void att_kernel(const __half* __restrict__ Eh, float* __restrict__ inv,
                float* __restrict__ att)
{
    __shared__ float tile[8][521];
    const int b = blockIdx.y, q = blockIdx.x;
    const int tid = threadIdx.x, w = tid >> 5, lane = tid & 31;

    const long long base8 = ((long long)b * 512 + q) * 8;
    const __half* row = Eh + (base8 + w) * 512;

    float v[16];
    float sum = 0.0f;
    #pragma unroll
    for (int i = 0; i < 4; i++) {
        uint2 px = *(const uint2*)(row + i * 128 + lane * 4);
        __half2 h01 = *(__half2*)&px.x, h23 = *(__half2*)&px.y;
        v[i*4+0] = __low2float(h01);  v[i*4+1] = __high2float(h01);
        v[i*4+2] = __low2float(h23);  v[i*4+3] = __high2float(h23);
        sum += v[i*4+0] + v[i*4+1] + v[i*4+2] + v[i*4+3];
    }
    #pragma unroll
    for (int o = 16; o > 0; o >>= 1) sum += __shfl_xor_sync(0xffffffffu, sum, o);
    const float iv = 1.0f / sum;
    if (lane == 0) inv[base8 + w] = iv;

    #pragma unroll
    for (int i = 0; i < 4; i++) {
        int k = i * 128 + lane * 4;
        tile[w][k]   = v[i*4+0] * iv;
        tile[w][k+1] = v[i*4+1] * iv;
        tile[w][k+2] = v[i*4+2] * iv;
        tile[w][k+3] = v[i*4+3] * iv;
    }
    if (att) {
        __syncthreads();
        float* obase = att + base8 * 512;
        #pragma unroll
        for (int it = 0; it < 16; it++) {
            int idx = tid + it * 256;
            obase[idx] = tile[idx & 7][idx >> 3];
        }
    }
}

// ---------------- input conversion (fp32 -> fp16), both tensors in ONE launch ----------------
__global__ void convert_both_kernel(const float* __restrict__ q, __half* __restrict__ qh,
                                    long long nq4,
                                    const float* __restrict__ d, __half* __restrict__ dh,
                                    long long nd4) {
    long long i = (long long)blockIdx.x * blockDim.x + threadIdx.x;
    const float* in; __half* oh; long long idx;
    if (i < nq4) { in = q; oh = qh; idx = i; }
    else if (i < nq4 + nd4) { in = d; oh = dh; idx = i - nq4; }
    else return;
    float4 v = ((const float4*)in)[idx];
    ((uint2*)oh)[idx] = make_uint2(
        pack2(__float2half_rn(v.x), __float2half_rn(v.y)),
        pack2(__float2half_rn(v.z), __float2half_rn(v.w)));
}

// weight transposes in ONE launch: Wq -> wqh; Wk,Wv -> wkvh (concat rows); Wz -> wzh
__global__ void transpose_cast_all(
    const float* __restrict__ Wq, const float* __restrict__ Wk,
    const float* __restrict__ Wv, const float* __restrict__ Wz,
    __half* __restrict__ wqh, __half* __restrict__ wkvh, __half* __restrict__ wzh)
{
    __shared__ float t[32][33];
    const int z = blockIdx.z;
    const float* in; __half* oh; int R;
    if (z == 0)      { in = Wq; oh = wqh;              R = DQ; }
    else if (z == 1) { in = Wk; oh = wkvh;             R = DIN; }
    else if (z == 2) { in = Wv; oh = wkvh + DIN * DIN; R = DIN; }
    else             { in = Wz; oh = wzh;              R = DOUT; }
    const int C = 512;
    int c0 = blockIdx.x * 32, r0 = blockIdx.y * 32;
    if (r0 >= R) return;
    int x = threadIdx.x, y = threadIdx.y;
    #pragma unroll
    for (int j = 0; j < 32; j += 8)
        t[y + j][x] = in[(long long)(r0 + y + j) * C + c0 + x];
    __syncthreads();
    #pragma unroll
    for (int j = 0; j < 32; j += 8)
        oh[(long long)(c0 + y + j) * R + r0 + x] = __float2half_rn(t[x][y + j]);
}

// concat(bk, bv) -> bkv
__global__ void concat_bias_kernel(const float* __restrict__ bk, const float* __restrict__ bv,
                                   float* __restrict__ bkv) {
    int i = blockIdx.x * blockDim.x + threadIdx.x;
    if (i < DIN) bkv[i] = bk[i];
    else if (i < 2 * DIN) bkv[i] = bv[i - DIN];
}

// ---------------- mask handling ----------------
__global__ void detect_mask_kernel(const unsigned int* __restrict__ m) {
    if (blockIdx.x == 0 && threadIdx.x == 0) {
        bool all01 = true, allf = true;
        for (int i = 0; i < 1024; i++) {
            unsigned int v = m[i];
            if (!(v == 0u || v == 1u)) all01 = false;
            if (!(v == 0u || v == 0x3F800000u)) allf = false;
        }
        g_mask_mode = all01 ? 1 : (allf ? 0 : 2);
    }
}
__global__ void normalize_mask_kernel(const void* __restrict__ m,
                                      unsigned char* __restrict__ cmask,
                                      unsigned char* __restrict__ words) {
    int idx = blockIdx.x * blockDim.x + threadIdx.x;
    if (idx >= BB * SS) return;
    int mode = g_mask_mode;
    unsigned char any = 0;
    #pragma unroll
    for (int w = 0; w < WW; w++) {
        int e = idx * WW + w;
        unsigned char v;
        if (mode == 1)      v = (((const int*)m)[e] != 0);
        else if (mode == 0) v = (((const float*)m)[e] != 0.0f);
        else                v = (((const unsigned char*)m)[e] != 0);
        cmask[e] = v;
        any |= v;
    }
    words[idx] = any;
}

// ---------------- launch ----------------
extern "C" void kernel_launch(void* const* d_in, const int* in_sizes, int n_in,
                              void* d_out, int out_size) {
    const float* query = (const float*)d_in[0];
    const float* data  = (const float*)d_in[1];
    const void*  maskr = d_in[2];
    const float* Wq = (const float*)d_in[3];
    const float* bq = (const float*)d_in[4];
    const float* Wk = (const float*)d_in[5];
    const float* bk = (const float*)d_in[6];
    const float* Wv = (const float*)d_in[7];
    const float* bv = (const float*)d_in[8];
    const float* Wz = (const float*)d_in[9];
    const float* bz = (const float*)d_in[10];

    float* out = (float*)d_out;
    const long long zs_elems  = (long long)BB * SS * WW * DOUT;
    const long long att_elems = (long long)BB * SS * SS * WW;
    float* att = ((long long)out_size >= zs_elems + att_elems) ? out + zs_elems : nullptr;

    __half *qh,*dh,*wqh,*wkvh,*wzh,*Qh,*KV,*UTh,*Eh;
    float *bkv, *ivp;
    unsigned char *cm, *wm;
    cudaGetSymbolAddress((void**)&qh, g_qh);
    cudaGetSymbolAddress((void**)&dh, g_dh);
    cudaGetSymbolAddress((void**)&wqh, g_wqh);
    cudaGetSymbolAddress((void**)&wkvh, g_wkvh);
    cudaGetSymbolAddress((void**)&wzh, g_wzh);
    cudaGetSymbolAddress((void**)&bkv, g_bkv);
    cudaGetSymbolAddress((void**)&Qh, g_Qh);
    cudaGetSymbolAddress((void**)&KV, g_KV);
    cudaGetSymbolAddress((void**)&UTh, g_UTh);
    cudaGetSymbolAddress((void**)&Eh, g_Eh);
    cudaGetSymbolAddress((void**)&ivp, g_inv);
    cudaGetSymbolAddress((void**)&cm, g_cmask);
    cudaGetSymbolAddress((void**)&wm, g_words);

    const int SMEM = NSTAGE * STAGEB;   // 110592 -> 2 CTAs/SM
    cudaFuncSetAttribute(hgemm<0>, cudaFuncAttributeMaxDynamicSharedMemorySize, SMEM);
    cudaFuncSetAttribute(hgemm<1>, cudaFuncAttributeMaxDynamicSharedMemorySize, SMEM);
    cudaFuncSetAttribute(hgemm<2>, cudaFuncAttributeMaxDynamicSharedMemorySize, SMEM);

    detect_mask_kernel<<<1, 1>>>((const unsigned int*)maskr);
    normalize_mask_kernel<<<(BB * SS + 255) / 256, 256>>>(maskr, cm, wm);
    concat_bias_kernel<<<4, 256>>>(bk, bv, bkv);
    {
        long long nq4 = (long long)BB * SS * WW * DQ / 4;
        long long nd4 = (long long)BB * SS * DIN / 4;
        convert_both_kernel<<<(unsigned)((nq4 + nd4 + 255) / 256), 256>>>(
            query, qh, nq4, data, dh, nd4);
    }
    transpose_cast_all<<<dim3(16, 16, 4), dim3(32, 8)>>>(Wq, Wk, Wv, Wz, wqh, wkvh, wzh);

    const float SCALE = 0.04419417382415922f;  // 1/sqrt(512), folded into Qp

    // Qproj -> Qh (scaled): [65536,512]
    hgemm<1><<<dim3(4, 512, 1), 256, SMEM>>>(qh, wqh, bq, SCALE,
        nullptr, Qh, nullptr, nullptr, nullptr, DQ, DQ, DQ, DIN, 0, 0, 0);
    // K+V proj fused -> KV [8192, 1024] (cols 0-511 = K, 512-1023 = V)
    hgemm<1><<<dim3(8, 64, 1), 256, SMEM>>>(dh, wkvh, bkv, 1.0f,
        nullptr, KV, nullptr, nullptr, nullptr, DIN, DIN, DIN, 2 * DIN, 0, 0, 0);
    // UT[b] = Wz^T @ V_b^T : [512z,512s]; V rows stride 1024
    hgemm<1><<<dim3(4, 4, BB), 256, SMEM>>>(wzh, KV + DIN, nullptr, 1.0f,
        nullptr, UTh, nullptr, nullptr, nullptr, DIN, DIN, 2 * DIN, SS,
        0, (long long)SS * 2 * DIN, (long long)DOUT * SS);
    // scores -> Eh = exp(masked logits) fp16; K rows stride 1024
    hgemm<2><<<dim3(4, 32, BB), 256, SMEM>>>(Qh, KV, nullptr, 1.0f,
        nullptr, Eh, cm, wm, nullptr, DIN, DIN, 2 * DIN, SS,
        (long long)SS * WW * DIN, (long long)SS * 2 * DIN, (long long)SS * WW * SS);
    // rowsums (inv) + normalized transposed att
    att_kernel<<<dim3(SS, BB), 256>>>(Eh, ivp, att);
    // zs = (Eh @ UT^T) * inv + bz -> d_out fp32
    hgemm<0><<<dim3(4, 32, BB), 256, SMEM>>>(Eh, UTh, bz, 1.0f,
        out, nullptr, nullptr, nullptr, ivp, SS, SS, SS, DOUT,
        (long long)SS * WW * SS, (long long)DOUT * SS, (long long)SS * WW * DOUT);
}